// round 1
// baseline (speedup 1.0000x reference)
#include <cuda_runtime.h>
#include <math.h>

#define V_   50257
#define D_   768
#define S_   2048
#define B_   2
#define HID_ 2048
#define NH_  12
#define HD_  64
#define T_   (B_*S_)   // 4096 tokens

// ---------------- scratch (device globals; no allocation allowed) ----------
__device__ float g_x  [T_*D_];
__device__ float g_q  [T_*D_];
__device__ float g_k  [T_*D_];
__device__ float g_v  [T_*D_];
__device__ float g_ctx[T_*D_];
__device__ float g_ao [T_*D_];
__device__ float g_h1 [T_*HID_];
__device__ float g_h2 [T_*D_];
__device__ float g_hn [T_*D_];
__device__ float g_rowloss[T_];

// ---------------- embedding + sinusoidal positional encoding ---------------
__global__ void embed_kernel(const int* __restrict__ inputs,
                             const float* __restrict__ wte,
                             float* __restrict__ x)
{
    int idx = blockIdx.x * blockDim.x + threadIdx.x;   // over T_*D_
    if (idx >= T_*D_) return;
    int t = idx / D_;
    int d = idx - t * D_;
    int s = t & (S_-1);           // position within sequence (S_ = 2048 pow2)
    int tok = inputs[t];
    int i2 = (d >> 1) * 2;        // even index 0,2,4,...
    float div = expf((float)(-i2) * (logf(10000.0f) / (float)D_));
    float ang = (float)s * div;
    float pe = (d & 1) ? cosf(ang) : sinf(ang);
    x[idx] = wte[(size_t)tok * D_ + d] + pe;
}

// ---------------- classic SGEMM: C = A[M,K] @ W[K,N] + bias, opt ReLU ------
// BM=BN=128, BK=8, 256 threads, 8x8 per thread. K must be a multiple of 8
// and of 4 (holds: 768, 2048). N bounds guarded (V=50257).
__global__ __launch_bounds__(256)
void sgemm_kernel(const float* __restrict__ A, const float* __restrict__ W,
                  const float* __restrict__ bias, float* __restrict__ C,
                  int M, int N, int K, int relu)
{
    __shared__ float As[8][128];
    __shared__ float Ws[8][128];

    int tid = threadIdx.x;
    int m0 = blockIdx.y * 128;
    int n0 = blockIdx.x * 128;

    int cRow = tid >> 4;          // 0..15
    int cCol = tid & 15;          // 0..15
    int tr = cRow * 8;
    int tc = cCol * 8;

    int aRow = tid >> 1;          // 0..127
    int aCol = (tid & 1) * 4;     // 0 / 4
    int wRow = tid >> 5;          // 0..7
    int wCol = (tid & 31) * 4;    // 0..124

    float acc[8][8];
#pragma unroll
    for (int i = 0; i < 8; i++)
#pragma unroll
        for (int j = 0; j < 8; j++) acc[i][j] = 0.f;

    const bool nvec = ((N & 3) == 0);

    for (int k0 = 0; k0 < K; k0 += 8) {
        // A tile (transposed into smem)
        float4 av = *(const float4*)(A + (size_t)(m0 + aRow) * K + k0 + aCol);
        As[aCol+0][aRow] = av.x;
        As[aCol+1][aRow] = av.y;
        As[aCol+2][aRow] = av.z;
        As[aCol+3][aRow] = av.w;
        // W tile
        if (nvec && (n0 + wCol + 3) < N) {
            float4 wv = *(const float4*)(W + (size_t)(k0 + wRow) * N + n0 + wCol);
            Ws[wRow][wCol+0] = wv.x;
            Ws[wRow][wCol+1] = wv.y;
            Ws[wRow][wCol+2] = wv.z;
            Ws[wRow][wCol+3] = wv.w;
        } else {
#pragma unroll
            for (int t = 0; t < 4; t++) {
                int n = n0 + wCol + t;
                Ws[wRow][wCol+t] = (n < N) ? W[(size_t)(k0 + wRow) * N + n] : 0.f;
            }
        }
        __syncthreads();

#pragma unroll
        for (int kk = 0; kk < 8; kk++) {
            float4 a0 = *(const float4*)&As[kk][tr];
            float4 a1 = *(const float4*)&As[kk][tr+4];
            float4 w0 = *(const float4*)&Ws[kk][tc];
            float4 w1 = *(const float4*)&Ws[kk][tc+4];
            float a[8] = {a0.x,a0.y,a0.z,a0.w,a1.x,a1.y,a1.z,a1.w};
            float w[8] = {w0.x,w0.y,w0.z,w0.w,w1.x,w1.y,w1.z,w1.w};
#pragma unroll
            for (int i = 0; i < 8; i++)
#pragma unroll
                for (int j = 0; j < 8; j++)
                    acc[i][j] = fmaf(a[i], w[j], acc[i][j]);
        }
        __syncthreads();
    }

#pragma unroll
    for (int i = 0; i < 8; i++) {
        size_t crow = (size_t)(m0 + tr + i) * N;
#pragma unroll
        for (int j = 0; j < 8; j++) {
            int n = n0 + tc + j;
            if (n < N) {
                float v = acc[i][j] + bias[n];
                if (relu) v = fmaxf(v, 0.f);
                C[crow + n] = v;
            }
        }
    }
}

// ---------------- flash attention (online softmax), 64q x 64k tiles --------
// Q,K,V laid out [B,S,NH,HD] (i.e. row t, col h*64+d of the [T,D] matrices).
#define HDP 65   // padded row stride in smem (bank-conflict free)

__global__ __launch_bounds__(256)
void attn_kernel(const float* __restrict__ Q, const float* __restrict__ K,
                 const float* __restrict__ V, float* __restrict__ O)
{
    extern __shared__ float sm[];
    float* Qs = sm;               // 64 x HDP
    float* Ks = Qs + 64*HDP;
    float* Vs = Ks + 64*HDP;
    float* Ps = Vs + 64*HDP;

    int qt = blockIdx.x;                 // query tile (0..31)
    int bh = blockIdx.y;                 // b*NH + h
    int b  = bh / NH_;
    int h  = bh - b * NH_;

    int tid = threadIdx.x;
    int ty = tid >> 4;        // 0..15 (row group)
    int tx = tid & 15;        // 0..15 (col group)
    int r0 = ty * 4;
    int c0 = tx * 4;

    const size_t headoff = (size_t)h * HD_;
    const float* Qg = Q + ((size_t)(b*S_ + qt*64)) * D_ + headoff;

    // load Q tile
    for (int idx = tid; idx < 64*16; idx += 256) {
        int r = idx >> 4;
        int c = (idx & 15) * 4;
        float4 v = *(const float4*)(Qg + (size_t)r * D_ + c);
        Qs[r*HDP + c+0] = v.x;
        Qs[r*HDP + c+1] = v.y;
        Qs[r*HDP + c+2] = v.z;
        Qs[r*HDP + c+3] = v.w;
    }

    float m_i[4], l_i[4], accO[4][4];
#pragma unroll
    for (int i = 0; i < 4; i++) {
        m_i[i] = -INFINITY; l_i[i] = 0.f;
#pragma unroll
        for (int j = 0; j < 4; j++) accO[i][j] = 0.f;
    }

    const float scale = 0.125f;   // 1/sqrt(64)

    for (int kt = 0; kt <= qt; kt++) {
        __syncthreads();
        const float* Kg = K + ((size_t)(b*S_ + kt*64)) * D_ + headoff;
        const float* Vg = V + ((size_t)(b*S_ + kt*64)) * D_ + headoff;
        for (int idx = tid; idx < 64*16; idx += 256) {
            int r = idx >> 4;
            int c = (idx & 15) * 4;
            float4 kv = *(const float4*)(Kg + (size_t)r * D_ + c);
            Ks[r*HDP + c+0] = kv.x; Ks[r*HDP + c+1] = kv.y;
            Ks[r*HDP + c+2] = kv.z; Ks[r*HDP + c+3] = kv.w;
            float4 vv = *(const float4*)(Vg + (size_t)r * D_ + c);
            Vs[r*HDP + c+0] = vv.x; Vs[r*HDP + c+1] = vv.y;
            Vs[r*HDP + c+2] = vv.z; Vs[r*HDP + c+3] = vv.w;
        }
        __syncthreads();

        // scores s[i][j] = q_row(r0+i) . k_row(c0+j)
        float s[4][4];
#pragma unroll
        for (int i = 0; i < 4; i++)
#pragma unroll
            for (int j = 0; j < 4; j++) s[i][j] = 0.f;

        for (int d = 0; d < HD_; d++) {
            float qv[4], kv[4];
#pragma unroll
            for (int i = 0; i < 4; i++) qv[i] = Qs[(r0+i)*HDP + d];
#pragma unroll
            for (int j = 0; j < 4; j++) kv[j] = Ks[(c0+j)*HDP + d];
#pragma unroll
            for (int i = 0; i < 4; i++)
#pragma unroll
                for (int j = 0; j < 4; j++)
                    s[i][j] = fmaf(qv[i], kv[j], s[i][j]);
        }

        // mask + scale + online softmax per row
#pragma unroll
        for (int i = 0; i < 4; i++) {
            int qpos = qt*64 + r0 + i;
            float rowmax = -INFINITY;
#pragma unroll
            for (int j = 0; j < 4; j++) {
                int kpos = kt*64 + c0 + j;
                s[i][j] = (kpos <= qpos) ? s[i][j]*scale : -INFINITY;
                rowmax = fmaxf(rowmax, s[i][j]);
            }
#pragma unroll
            for (int off = 8; off; off >>= 1)
                rowmax = fmaxf(rowmax, __shfl_xor_sync(0xffffffffu, rowmax, off, 16));
            float mnew = fmaxf(m_i[i], rowmax);
            float rsum = 0.f;
            float p[4];
#pragma unroll
            for (int j = 0; j < 4; j++) { p[j] = __expf(s[i][j] - mnew); rsum += p[j]; }
#pragma unroll
            for (int off = 8; off; off >>= 1)
                rsum += __shfl_xor_sync(0xffffffffu, rsum, off, 16);
            float corr = __expf(m_i[i] - mnew);
            l_i[i] = l_i[i]*corr + rsum;
#pragma unroll
            for (int j = 0; j < 4; j++) accO[i][j] *= corr;
            m_i[i] = mnew;
#pragma unroll
            for (int j = 0; j < 4; j++) Ps[(r0+i)*HDP + c0 + j] = p[j];
        }
        __syncthreads();

        // accO[i][cc] += sum_j Ps[r0+i][j] * Vs[j][c0+cc]
        for (int j = 0; j < 64; j++) {
            float pr[4], vv[4];
#pragma unroll
            for (int i = 0; i < 4; i++) pr[i] = Ps[(r0+i)*HDP + j];
#pragma unroll
            for (int cc = 0; cc < 4; cc++) vv[cc] = Vs[j*HDP + c0 + cc];
#pragma unroll
            for (int i = 0; i < 4; i++)
#pragma unroll
                for (int cc = 0; cc < 4; cc++)
                    accO[i][cc] = fmaf(pr[i], vv[cc], accO[i][cc]);
        }
    }

    // write out ctx [b, s, h, d]
#pragma unroll
    for (int i = 0; i < 4; i++) {
        float inv = 1.f / l_i[i];
        size_t row = ((size_t)(b*S_ + qt*64 + r0 + i)) * D_ + headoff;
#pragma unroll
        for (int cc = 0; cc < 4; cc++)
            O[row + c0 + cc] = accO[i][cc] * inv;
    }
}

// ---------------- LayerNorm over D -----------------------------------------
__global__ void ln_kernel(const float* __restrict__ H,
                          const float* __restrict__ g,
                          const float* __restrict__ bb,
                          float* __restrict__ out)
{
    int row = blockIdx.x;
    const float* h = H + (size_t)row * D_;
    __shared__ float red[256];
    int tid = threadIdx.x;

    float s = 0.f;
    for (int i = tid; i < D_; i += 256) s += h[i];
    red[tid] = s; __syncthreads();
    for (int o = 128; o; o >>= 1) { if (tid < o) red[tid] += red[tid+o]; __syncthreads(); }
    float mu = red[0] / (float)D_;
    __syncthreads();

    float v = 0.f;
    for (int i = tid; i < D_; i += 256) { float d = h[i] - mu; v += d*d; }
    red[tid] = v; __syncthreads();
    for (int o = 128; o; o >>= 1) { if (tid < o) red[tid] += red[tid+o]; __syncthreads(); }
    float rstd = rsqrtf(red[0] / (float)D_ + 1e-5f);

    float* o2 = out + (size_t)row * D_;
    for (int i = tid; i < D_; i += 256)
        o2[i] = (h[i] - mu) * rstd * g[i] + bb[i];
}

// ---------------- per-row cross-entropy -------------------------------------
__global__ void loss_rows_kernel(const float* __restrict__ logits,
                                 const int* __restrict__ targets,
                                 float* __restrict__ rowloss)
{
    int row = blockIdx.x;
    const float* l = logits + (size_t)row * V_;
    __shared__ float red[256];
    int tid = threadIdx.x;

    float mx = -INFINITY;
    for (int i = tid; i < V_; i += 256) mx = fmaxf(mx, l[i]);
    red[tid] = mx; __syncthreads();
    for (int o = 128; o; o >>= 1) { if (tid < o) red[tid] = fmaxf(red[tid], red[tid+o]); __syncthreads(); }
    mx = red[0]; __syncthreads();

    float sum = 0.f;
    for (int i = tid; i < V_; i += 256) sum += expf(l[i] - mx);
    red[tid] = sum; __syncthreads();
    for (int o = 128; o; o >>= 1) { if (tid < o) red[tid] += red[tid+o]; __syncthreads(); }

    if (tid == 0)
        rowloss[row] = -(l[targets[row]] - mx - logf(red[0]));
}

__global__ void loss_reduce_kernel(const float* __restrict__ rowloss,
                                   float* __restrict__ out)
{
    __shared__ float red[256];
    int tid = threadIdx.x;
    float s = 0.f;
    for (int i = tid; i < T_; i += 256) s += rowloss[i];
    red[tid] = s; __syncthreads();
    for (int o = 128; o; o >>= 1) { if (tid < o) red[tid] += red[tid+o]; __syncthreads(); }
    if (tid == 0) out[0] = red[0] / (float)T_;
}

// ---------------- launcher ---------------------------------------------------
extern "C" void kernel_launch(void* const* d_in, const int* in_sizes, int n_in,
                              void* d_out, int out_size)
{
    const int*   inputs  = (const int*)  d_in[0];
    const int*   targets = (const int*)  d_in[1];
    const float* wte     = (const float*)d_in[2];
    const float* wq      = (const float*)d_in[3];
    const float* bq      = (const float*)d_in[4];
    const float* wk      = (const float*)d_in[5];
    const float* bk      = (const float*)d_in[6];
    const float* wv      = (const float*)d_in[7];
    const float* bv      = (const float*)d_in[8];
    const float* wo      = (const float*)d_in[9];
    const float* bo      = (const float*)d_in[10];
    const float* w1      = (const float*)d_in[11];
    const float* b1      = (const float*)d_in[12];
    const float* w2      = (const float*)d_in[13];
    const float* b2      = (const float*)d_in[14];
    const float* ln_g    = (const float*)d_in[15];
    const float* ln_b    = (const float*)d_in[16];
    const float* w_out   = (const float*)d_in[17];
    const float* b_out   = (const float*)d_in[18];
    float* out = (float*)d_out;

    float *x,*q,*k,*v,*ctx,*ao,*h1,*h2,*hn,*rowloss;
    cudaGetSymbolAddress((void**)&x,   g_x);
    cudaGetSymbolAddress((void**)&q,   g_q);
    cudaGetSymbolAddress((void**)&k,   g_k);
    cudaGetSymbolAddress((void**)&v,   g_v);
    cudaGetSymbolAddress((void**)&ctx, g_ctx);
    cudaGetSymbolAddress((void**)&ao,  g_ao);
    cudaGetSymbolAddress((void**)&h1,  g_h1);
    cudaGetSymbolAddress((void**)&h2,  g_h2);
    cudaGetSymbolAddress((void**)&hn,  g_hn);
    cudaGetSymbolAddress((void**)&rowloss, g_rowloss);

    const int SMEM_ATTN = 4 * 64 * HDP * (int)sizeof(float);   // 66560 B
    cudaFuncSetAttribute(attn_kernel, cudaFuncAttributeMaxDynamicSharedMemorySize, SMEM_ATTN);

    // 1. embedding + positional encoding
    embed_kernel<<<(T_*D_)/256, 256>>>(inputs, wte, x);

    // 2. Q,K,V projections
    dim3 gDD(D_/128, T_/128);
    sgemm_kernel<<<gDD, 256>>>(x, wq, bq, q, T_, D_, D_, 0);
    sgemm_kernel<<<gDD, 256>>>(x, wk, bk, k, T_, D_, D_, 0);
    sgemm_kernel<<<gDD, 256>>>(x, wv, bv, v, T_, D_, D_, 0);

    // 3. causal multi-head attention
    attn_kernel<<<dim3(S_/64, B_*NH_), 256, SMEM_ATTN>>>(q, k, v, ctx);

    // 4. output projection
    sgemm_kernel<<<gDD, 256>>>(ctx, wo, bo, ao, T_, D_, D_, 0);

    // 5. FFN
    sgemm_kernel<<<dim3(HID_/128, T_/128), 256>>>(ao, w1, b1, h1, T_, HID_, D_, 1);
    sgemm_kernel<<<gDD, 256>>>(h1, w2, b2, h2, T_, D_, HID_, 0);

    // 6. LayerNorm
    ln_kernel<<<T_, 256>>>(h2, ln_g, ln_b, hn);

    // 7. vocab projection -> logits (written straight to d_out)
    sgemm_kernel<<<dim3((V_+127)/128, T_/128), 256>>>(hn, w_out, b_out, out, T_, V_, D_, 0);

    // 8. cross-entropy loss
    loss_rows_kernel<<<T_, 256>>>(out, targets, rowloss);
    if (out_size > T_ * V_)
        loss_reduce_kernel<<<1, 256>>>(rowloss, out + (size_t)T_ * V_);
}

// round 2
// speedup vs baseline: 1.0001x; 1.0001x over previous
#include <cuda_runtime.h>
#include <math.h>

#define V_   50257
#define D_   768
#define S_   2048
#define B_   2
#define HID_ 2048
#define NH_  12
#define HD_  64
#define T_   (B_*S_)   // 4096 tokens

// ---------------- scratch (device globals; no allocation allowed) ----------
__device__ float g_x  [T_*D_];
__device__ float g_q  [T_*D_];
__device__ float g_k  [T_*D_];
__device__ float g_v  [T_*D_];
__device__ float g_ctx[T_*D_];
__device__ float g_ao [T_*D_];
__device__ float g_h1 [T_*HID_];
__device__ float g_h2 [T_*D_];
__device__ float g_hn [T_*D_];
__device__ float g_rowloss[T_];

// ---------------- embedding + sinusoidal positional encoding ---------------
__global__ void embed_kernel(const int* __restrict__ inputs,
                             const float* __restrict__ wte,
                             float* __restrict__ x)
{
    int idx = blockIdx.x * blockDim.x + threadIdx.x;   // over T_*D_
    if (idx >= T_*D_) return;
    int t = idx / D_;
    int d = idx - t * D_;
    int s = t & (S_-1);           // position within sequence (S_ = 2048 pow2)
    int tok = inputs[t];
    int i2 = (d >> 1) * 2;        // even index 0,2,4,...
    float div = expf((float)(-i2) * (logf(10000.0f) / (float)D_));
    float ang = (float)s * div;
    float pe = (d & 1) ? cosf(ang) : sinf(ang);
    x[idx] = wte[(size_t)tok * D_ + d] + pe;
}

// ---------------- classic SGEMM: C = A[M,K] @ W[K,N] + bias, opt ReLU ------
// BM=BN=128, BK=8, 256 threads, 8x8 per thread. K must be a multiple of 8
// and of 4 (holds: 768, 2048). N bounds guarded (V=50257).
__global__ __launch_bounds__(256)
void sgemm_kernel(const float* __restrict__ A, const float* __restrict__ W,
                  const float* __restrict__ bias, float* __restrict__ C,
                  int M, int N, int K, int relu)
{
    __shared__ float As[8][128];
    __shared__ float Ws[8][128];

    int tid = threadIdx.x;
    int m0 = blockIdx.y * 128;
    int n0 = blockIdx.x * 128;

    int cRow = tid >> 4;          // 0..15
    int cCol = tid & 15;          // 0..15
    int tr = cRow * 8;
    int tc = cCol * 8;

    int aRow = tid >> 1;          // 0..127
    int aCol = (tid & 1) * 4;     // 0 / 4
    int wRow = tid >> 5;          // 0..7
    int wCol = (tid & 31) * 4;    // 0..124

    float acc[8][8];
#pragma unroll
    for (int i = 0; i < 8; i++)
#pragma unroll
        for (int j = 0; j < 8; j++) acc[i][j] = 0.f;

    const bool nvec = ((N & 3) == 0);

    for (int k0 = 0; k0 < K; k0 += 8) {
        // A tile (transposed into smem)
        float4 av = *(const float4*)(A + (size_t)(m0 + aRow) * K + k0 + aCol);
        As[aCol+0][aRow] = av.x;
        As[aCol+1][aRow] = av.y;
        As[aCol+2][aRow] = av.z;
        As[aCol+3][aRow] = av.w;
        // W tile
        if (nvec && (n0 + wCol + 3) < N) {
            float4 wv = *(const float4*)(W + (size_t)(k0 + wRow) * N + n0 + wCol);
            Ws[wRow][wCol+0] = wv.x;
            Ws[wRow][wCol+1] = wv.y;
            Ws[wRow][wCol+2] = wv.z;
            Ws[wRow][wCol+3] = wv.w;
        } else {
#pragma unroll
            for (int t = 0; t < 4; t++) {
                int n = n0 + wCol + t;
                Ws[wRow][wCol+t] = (n < N) ? W[(size_t)(k0 + wRow) * N + n] : 0.f;
            }
        }
        __syncthreads();

#pragma unroll
        for (int kk = 0; kk < 8; kk++) {
            float4 a0 = *(const float4*)&As[kk][tr];
            float4 a1 = *(const float4*)&As[kk][tr+4];
            float4 w0 = *(const float4*)&Ws[kk][tc];
            float4 w1 = *(const float4*)&Ws[kk][tc+4];
            float a[8] = {a0.x,a0.y,a0.z,a0.w,a1.x,a1.y,a1.z,a1.w};
            float w[8] = {w0.x,w0.y,w0.z,w0.w,w1.x,w1.y,w1.z,w1.w};
#pragma unroll
            for (int i = 0; i < 8; i++)
#pragma unroll
                for (int j = 0; j < 8; j++)
                    acc[i][j] = fmaf(a[i], w[j], acc[i][j]);
        }
        __syncthreads();
    }

#pragma unroll
    for (int i = 0; i < 8; i++) {
        size_t crow = (size_t)(m0 + tr + i) * N;
#pragma unroll
        for (int j = 0; j < 8; j++) {
            int n = n0 + tc + j;
            if (n < N) {
                float v = acc[i][j] + bias[n];
                if (relu) v = fmaxf(v, 0.f);
                C[crow + n] = v;
            }
        }
    }
}

// ---------------- flash attention (online softmax), 64q x 64k tiles --------
// Q,K,V laid out [B,S,NH,HD] (i.e. row t, col h*64+d of the [T,D] matrices).
#define HDP 65   // padded row stride in smem (bank-conflict free)

__global__ __launch_bounds__(256)
void attn_kernel(const float* __restrict__ Q, const float* __restrict__ K,
                 const float* __restrict__ V, float* __restrict__ O)
{
    extern __shared__ float sm[];
    float* Qs = sm;               // 64 x HDP
    float* Ks = Qs + 64*HDP;
    float* Vs = Ks + 64*HDP;
    float* Ps = Vs + 64*HDP;

    int qt = blockIdx.x;                 // query tile (0..31)
    int bh = blockIdx.y;                 // b*NH + h
    int b  = bh / NH_;
    int h  = bh - b * NH_;

    int tid = threadIdx.x;
    int ty = tid >> 4;        // 0..15 (row group)
    int tx = tid & 15;        // 0..15 (col group)
    int r0 = ty * 4;
    int c0 = tx * 4;

    const size_t headoff = (size_t)h * HD_;
    const float* Qg = Q + ((size_t)(b*S_ + qt*64)) * D_ + headoff;

    // load Q tile
    for (int idx = tid; idx < 64*16; idx += 256) {
        int r = idx >> 4;
        int c = (idx & 15) * 4;
        float4 v = *(const float4*)(Qg + (size_t)r * D_ + c);
        Qs[r*HDP + c+0] = v.x;
        Qs[r*HDP + c+1] = v.y;
        Qs[r*HDP + c+2] = v.z;
        Qs[r*HDP + c+3] = v.w;
    }

    float m_i[4], l_i[4], accO[4][4];
#pragma unroll
    for (int i = 0; i < 4; i++) {
        m_i[i] = -INFINITY; l_i[i] = 0.f;
#pragma unroll
        for (int j = 0; j < 4; j++) accO[i][j] = 0.f;
    }

    const float scale = 0.125f;   // 1/sqrt(64)

    for (int kt = 0; kt <= qt; kt++) {
        __syncthreads();
        const float* Kg = K + ((size_t)(b*S_ + kt*64)) * D_ + headoff;
        const float* Vg = V + ((size_t)(b*S_ + kt*64)) * D_ + headoff;
        for (int idx = tid; idx < 64*16; idx += 256) {
            int r = idx >> 4;
            int c = (idx & 15) * 4;
            float4 kv = *(const float4*)(Kg + (size_t)r * D_ + c);
            Ks[r*HDP + c+0] = kv.x; Ks[r*HDP + c+1] = kv.y;
            Ks[r*HDP + c+2] = kv.z; Ks[r*HDP + c+3] = kv.w;
            float4 vv = *(const float4*)(Vg + (size_t)r * D_ + c);
            Vs[r*HDP + c+0] = vv.x; Vs[r*HDP + c+1] = vv.y;
            Vs[r*HDP + c+2] = vv.z; Vs[r*HDP + c+3] = vv.w;
        }
        __syncthreads();

        // scores s[i][j] = q_row(r0+i) . k_row(c0+j)
        float s[4][4];
#pragma unroll
        for (int i = 0; i < 4; i++)
#pragma unroll
            for (int j = 0; j < 4; j++) s[i][j] = 0.f;

        for (int d = 0; d < HD_; d++) {
            float qv[4], kv[4];
#pragma unroll
            for (int i = 0; i < 4; i++) qv[i] = Qs[(r0+i)*HDP + d];
#pragma unroll
            for (int j = 0; j < 4; j++) kv[j] = Ks[(c0+j)*HDP + d];
#pragma unroll
            for (int i = 0; i < 4; i++)
#pragma unroll
                for (int j = 0; j < 4; j++)
                    s[i][j] = fmaf(qv[i], kv[j], s[i][j]);
        }

        // mask + scale + online softmax per row
#pragma unroll
        for (int i = 0; i < 4; i++) {
            int qpos = qt*64 + r0 + i;
            float rowmax = -INFINITY;
#pragma unroll
            for (int j = 0; j < 4; j++) {
                int kpos = kt*64 + c0 + j;
                s[i][j] = (kpos <= qpos) ? s[i][j]*scale : -INFINITY;
                rowmax = fmaxf(rowmax, s[i][j]);
            }
#pragma unroll
            for (int off = 8; off; off >>= 1)
                rowmax = fmaxf(rowmax, __shfl_xor_sync(0xffffffffu, rowmax, off, 16));
            float mnew = fmaxf(m_i[i], rowmax);
            float rsum = 0.f;
            float p[4];
#pragma unroll
            for (int j = 0; j < 4; j++) { p[j] = __expf(s[i][j] - mnew); rsum += p[j]; }
#pragma unroll
            for (int off = 8; off; off >>= 1)
                rsum += __shfl_xor_sync(0xffffffffu, rsum, off, 16);
            float corr = __expf(m_i[i] - mnew);
            l_i[i] = l_i[i]*corr + rsum;
#pragma unroll
            for (int j = 0; j < 4; j++) accO[i][j] *= corr;
            m_i[i] = mnew;
#pragma unroll
            for (int j = 0; j < 4; j++) Ps[(r0+i)*HDP + c0 + j] = p[j];
        }
        __syncthreads();

        // accO[i][cc] += sum_j Ps[r0+i][j] * Vs[j][c0+cc]
        for (int j = 0; j < 64; j++) {
            float pr[4], vv[4];
#pragma unroll
            for (int i = 0; i < 4; i++) pr[i] = Ps[(r0+i)*HDP + j];
#pragma unroll
            for (int cc = 0; cc < 4; cc++) vv[cc] = Vs[j*HDP + c0 + cc];
#pragma unroll
            for (int i = 0; i < 4; i++)
#pragma unroll
                for (int cc = 0; cc < 4; cc++)
                    accO[i][cc] = fmaf(pr[i], vv[cc], accO[i][cc]);
        }
    }

    // write out ctx [b, s, h, d]
#pragma unroll
    for (int i = 0; i < 4; i++) {
        float inv = 1.f / l_i[i];
        size_t row = ((size_t)(b*S_ + qt*64 + r0 + i)) * D_ + headoff;
#pragma unroll
        for (int cc = 0; cc < 4; cc++)
            O[row + c0 + cc] = accO[i][cc] * inv;
    }
}

// ---------------- LayerNorm over D -----------------------------------------
__global__ void ln_kernel(const float* __restrict__ H,
                          const float* __restrict__ g,
                          const float* __restrict__ bb,
                          float* __restrict__ out)
{
    int row = blockIdx.x;
    const float* h = H + (size_t)row * D_;
    __shared__ float red[256];
    int tid = threadIdx.x;

    float s = 0.f;
    for (int i = tid; i < D_; i += 256) s += h[i];
    red[tid] = s; __syncthreads();
    for (int o = 128; o; o >>= 1) { if (tid < o) red[tid] += red[tid+o]; __syncthreads(); }
    float mu = red[0] / (float)D_;
    __syncthreads();

    float v = 0.f;
    for (int i = tid; i < D_; i += 256) { float d = h[i] - mu; v += d*d; }
    red[tid] = v; __syncthreads();
    for (int o = 128; o; o >>= 1) { if (tid < o) red[tid] += red[tid+o]; __syncthreads(); }
    float rstd = rsqrtf(red[0] / (float)D_ + 1e-5f);

    float* o2 = out + (size_t)row * D_;
    for (int i = tid; i < D_; i += 256)
        o2[i] = (h[i] - mu) * rstd * g[i] + bb[i];
}

// ---------------- per-row cross-entropy -------------------------------------
__global__ void loss_rows_kernel(const float* __restrict__ logits,
                                 const int* __restrict__ targets,
                                 float* __restrict__ rowloss)
{
    int row = blockIdx.x;
    const float* l = logits + (size_t)row * V_;
    __shared__ float red[256];
    int tid = threadIdx.x;

    float mx = -INFINITY;
    for (int i = tid; i < V_; i += 256) mx = fmaxf(mx, l[i]);
    red[tid] = mx; __syncthreads();
    for (int o = 128; o; o >>= 1) { if (tid < o) red[tid] = fmaxf(red[tid], red[tid+o]); __syncthreads(); }
    mx = red[0]; __syncthreads();

    float sum = 0.f;
    for (int i = tid; i < V_; i += 256) sum += expf(l[i] - mx);
    red[tid] = sum; __syncthreads();
    for (int o = 128; o; o >>= 1) { if (tid < o) red[tid] += red[tid+o]; __syncthreads(); }

    if (tid == 0)
        rowloss[row] = -(l[targets[row]] - mx - logf(red[0]));
}

__global__ void loss_reduce_kernel(const float* __restrict__ rowloss,
                                   float* __restrict__ out)
{
    __shared__ float red[256];
    int tid = threadIdx.x;
    float s = 0.f;
    for (int i = tid; i < T_; i += 256) s += rowloss[i];
    red[tid] = s; __syncthreads();
    for (int o = 128; o; o >>= 1) { if (tid < o) red[tid] += red[tid+o]; __syncthreads(); }
    if (tid == 0) out[0] = red[0] / (float)T_;
}

// ---------------- launcher ---------------------------------------------------
extern "C" void kernel_launch(void* const* d_in, const int* in_sizes, int n_in,
                              void* d_out, int out_size)
{
    const int*   inputs  = (const int*)  d_in[0];
    const int*   targets = (const int*)  d_in[1];
    const float* wte     = (const float*)d_in[2];
    const float* wq      = (const float*)d_in[3];
    const float* bq      = (const float*)d_in[4];
    const float* wk      = (const float*)d_in[5];
    const float* bk      = (const float*)d_in[6];
    const float* wv      = (const float*)d_in[7];
    const float* bv      = (const float*)d_in[8];
    const float* wo      = (const float*)d_in[9];
    const float* bo      = (const float*)d_in[10];
    const float* w1      = (const float*)d_in[11];
    const float* b1      = (const float*)d_in[12];
    const float* w2      = (const float*)d_in[13];
    const float* b2      = (const float*)d_in[14];
    const float* ln_g    = (const float*)d_in[15];
    const float* ln_b    = (const float*)d_in[16];
    const float* w_out   = (const float*)d_in[17];
    const float* b_out   = (const float*)d_in[18];
    float* out = (float*)d_out;

    float *x,*q,*k,*v,*ctx,*ao,*h1,*h2,*hn,*rowloss;
    cudaGetSymbolAddress((void**)&x,   g_x);
    cudaGetSymbolAddress((void**)&q,   g_q);
    cudaGetSymbolAddress((void**)&k,   g_k);
    cudaGetSymbolAddress((void**)&v,   g_v);
    cudaGetSymbolAddress((void**)&ctx, g_ctx);
    cudaGetSymbolAddress((void**)&ao,  g_ao);
    cudaGetSymbolAddress((void**)&h1,  g_h1);
    cudaGetSymbolAddress((void**)&h2,  g_h2);
    cudaGetSymbolAddress((void**)&hn,  g_hn);
    cudaGetSymbolAddress((void**)&rowloss, g_rowloss);

    const int SMEM_ATTN = 4 * 64 * HDP * (int)sizeof(float);   // 66560 B
    cudaFuncSetAttribute(attn_kernel, cudaFuncAttributeMaxDynamicSharedMemorySize, SMEM_ATTN);

    // 1. embedding + positional encoding
    embed_kernel<<<(T_*D_)/256, 256>>>(inputs, wte, x);

    // 2. Q,K,V projections
    dim3 gDD(D_/128, T_/128);
    sgemm_kernel<<<gDD, 256>>>(x, wq, bq, q, T_, D_, D_, 0);
    sgemm_kernel<<<gDD, 256>>>(x, wk, bk, k, T_, D_, D_, 0);
    sgemm_kernel<<<gDD, 256>>>(x, wv, bv, v, T_, D_, D_, 0);

    // 3. causal multi-head attention
    attn_kernel<<<dim3(S_/64, B_*NH_), 256, SMEM_ATTN>>>(q, k, v, ctx);

    // 4. output projection
    sgemm_kernel<<<gDD, 256>>>(ctx, wo, bo, ao, T_, D_, D_, 0);

    // 5. FFN
    sgemm_kernel<<<dim3(HID_/128, T_/128), 256>>>(ao, w1, b1, h1, T_, HID_, D_, 1);
    sgemm_kernel<<<gDD, 256>>>(h1, w2, b2, h2, T_, D_, HID_, 0);

    // 6. LayerNorm
    ln_kernel<<<T_, 256>>>(h2, ln_g, ln_b, hn);

    // 7. vocab projection -> logits (written straight to d_out)
    sgemm_kernel<<<dim3((V_+127)/128, T_/128), 256>>>(hn, w_out, b_out, out, T_, V_, D_, 0);

    // 8. cross-entropy loss
    loss_rows_kernel<<<T_, 256>>>(out, targets, rowloss);
    if (out_size > T_ * V_)
        loss_reduce_kernel<<<1, 256>>>(rowloss, out + (size_t)T_ * V_);
}

// round 3
// speedup vs baseline: 3.0030x; 3.0027x over previous
#include <cuda_runtime.h>
#include <math.h>

#define V_   50257
#define D_   768
#define S_   2048
#define B_   2
#define HID_ 2048
#define NH_  12
#define HD_  64
#define T_   (B_*S_)   // 4096 tokens

// ---------------- scratch (device globals; no allocation allowed) ----------
__device__ float g_x  [T_*D_];
__device__ float g_q  [T_*D_];
__device__ float g_k  [T_*D_];
__device__ float g_v  [T_*D_];
__device__ float g_ctx[T_*D_];
__device__ float g_ao [T_*D_];
__device__ float g_h1 [T_*HID_];
__device__ float g_h2 [T_*D_];
__device__ float g_hn [T_*D_];
__device__ float g_rowloss[T_];

// ---------------- embedding + sinusoidal positional encoding ---------------
__global__ void embed_kernel(const int* __restrict__ inputs,
                             const float* __restrict__ wte,
                             float* __restrict__ x)
{
    int idx = blockIdx.x * blockDim.x + threadIdx.x;   // over T_*D_
    if (idx >= T_*D_) return;
    int t = idx / D_;
    int d = idx - t * D_;
    int s = t & (S_-1);
    int tok = inputs[t];
    int i2 = (d >> 1) * 2;
    float div = expf((float)(-i2) * (logf(10000.0f) / (float)D_));
    float ang = (float)s * div;
    float pe = (d & 1) ? cosf(ang) : sinf(ang);
    x[idx] = wte[(size_t)tok * D_ + d] + pe;
}

// ---------------- tf32 tensor-core GEMM -------------------------------------
// C[M,N] = A[M,K] @ W[K,N] + bias, optional ReLU.
// BM=BN=128, BK=16, 256 threads = 8 warps (2x4), warp tile 64x32,
// mma.sync.m16n8k8.tf32 with RN conversion on smem store.
__device__ __forceinline__ unsigned f2tf32(float f) {
    unsigned u;
    asm volatile("cvt.rna.tf32.f32 %0, %1;" : "=r"(u) : "f"(f));
    return u;
}

__global__ __launch_bounds__(256, 2)
void mma_gemm_kernel(const float* __restrict__ A, const float* __restrict__ W,
                     const float* __restrict__ bias, float* __restrict__ C,
                     int M, int N, int K, int relu)
{
    __shared__ unsigned As[128][20];   // pad: stride 20 -> conflict-free frag loads
    __shared__ unsigned Bs[16][136];   // pad: stride 136 -> conflict-free frag loads

    const int tid  = threadIdx.x;
    const int warp = tid >> 5;
    const int lane = tid & 31;
    const int gid  = lane >> 2;      // 0..7
    const int tig  = lane & 3;       // 0..3
    const int wm   = warp >> 2;      // 0..1
    const int wn   = warp & 3;       // 0..3

    const int m0 = blockIdx.y * 128;
    const int n0 = blockIdx.x * 128;

    float acc[4][4][4];
#pragma unroll
    for (int i = 0; i < 4; i++)
#pragma unroll
        for (int j = 0; j < 4; j++)
#pragma unroll
            for (int c = 0; c < 4; c++) acc[i][j][c] = 0.f;

    const bool nvec = ((N & 3) == 0);

    // register staging (prefetch)
    float a_st[2][4], b_st[2][4];

    // slot maps: A slot -> r=slot>>2 (0..127), c=(slot&3)*4
    //            B slot -> r=slot>>5 (0..15),  c=(slot&31)*4
    {
        const int k0 = 0;
#pragma unroll
        for (int i = 0; i < 2; i++) {
            int slot = tid + i * 256;
            int r = slot >> 2, c = (slot & 3) * 4;
            float4 v = *(const float4*)(A + (size_t)(m0 + r) * K + k0 + c);
            a_st[i][0] = v.x; a_st[i][1] = v.y; a_st[i][2] = v.z; a_st[i][3] = v.w;
        }
#pragma unroll
        for (int i = 0; i < 2; i++) {
            int slot = tid + i * 256;
            int r = slot >> 5, c = (slot & 31) * 4;
            if (nvec && (n0 + c + 3) < N) {
                float4 v = *(const float4*)(W + (size_t)(k0 + r) * N + n0 + c);
                b_st[i][0] = v.x; b_st[i][1] = v.y; b_st[i][2] = v.z; b_st[i][3] = v.w;
            } else {
#pragma unroll
                for (int j = 0; j < 4; j++) {
                    int n = n0 + c + j;
                    b_st[i][j] = (n < N) ? W[(size_t)(k0 + r) * N + n] : 0.f;
                }
            }
        }
    }

    for (int k0 = 0; k0 < K; k0 += 16) {
        // stage -> smem (convert to tf32 bits with RN)
#pragma unroll
        for (int i = 0; i < 2; i++) {
            int slot = tid + i * 256;
            int r = slot >> 2, c = (slot & 3) * 4;
#pragma unroll
            for (int j = 0; j < 4; j++) As[r][c + j] = f2tf32(a_st[i][j]);
        }
#pragma unroll
        for (int i = 0; i < 2; i++) {
            int slot = tid + i * 256;
            int r = slot >> 5, c = (slot & 31) * 4;
#pragma unroll
            for (int j = 0; j < 4; j++) Bs[r][c + j] = f2tf32(b_st[i][j]);
        }
        __syncthreads();

        // prefetch next tile while computing this one
        if (k0 + 16 < K) {
            const int kn = k0 + 16;
#pragma unroll
            for (int i = 0; i < 2; i++) {
                int slot = tid + i * 256;
                int r = slot >> 2, c = (slot & 3) * 4;
                float4 v = *(const float4*)(A + (size_t)(m0 + r) * K + kn + c);
                a_st[i][0] = v.x; a_st[i][1] = v.y; a_st[i][2] = v.z; a_st[i][3] = v.w;
            }
#pragma unroll
            for (int i = 0; i < 2; i++) {
                int slot = tid + i * 256;
                int r = slot >> 5, c = (slot & 31) * 4;
                if (nvec && (n0 + c + 3) < N) {
                    float4 v = *(const float4*)(W + (size_t)(kn + r) * N + n0 + c);
                    b_st[i][0] = v.x; b_st[i][1] = v.y; b_st[i][2] = v.z; b_st[i][3] = v.w;
                } else {
#pragma unroll
                    for (int j = 0; j < 4; j++) {
                        int n = n0 + c + j;
                        b_st[i][j] = (n < N) ? W[(size_t)(kn + r) * N + n] : 0.f;
                    }
                }
            }
        }

        // compute: 2 k-steps of 8
#pragma unroll
        for (int kk = 0; kk < 16; kk += 8) {
            unsigned af[4][4], bf[4][2];
#pragma unroll
            for (int mi = 0; mi < 4; mi++) {
                int r = wm * 64 + mi * 16 + gid;
                af[mi][0] = As[r    ][kk + tig    ];
                af[mi][1] = As[r + 8][kk + tig    ];
                af[mi][2] = As[r    ][kk + tig + 4];
                af[mi][3] = As[r + 8][kk + tig + 4];
            }
#pragma unroll
            for (int ni = 0; ni < 4; ni++) {
                int c = wn * 32 + ni * 8 + gid;
                bf[ni][0] = Bs[kk + tig    ][c];
                bf[ni][1] = Bs[kk + tig + 4][c];
            }
#pragma unroll
            for (int mi = 0; mi < 4; mi++)
#pragma unroll
                for (int ni = 0; ni < 4; ni++) {
                    asm volatile(
                        "mma.sync.aligned.m16n8k8.row.col.f32.tf32.tf32.f32 "
                        "{%0,%1,%2,%3},{%4,%5,%6,%7},{%8,%9},{%0,%1,%2,%3};"
                        : "+f"(acc[mi][ni][0]), "+f"(acc[mi][ni][1]),
                          "+f"(acc[mi][ni][2]), "+f"(acc[mi][ni][3])
                        : "r"(af[mi][0]), "r"(af[mi][1]), "r"(af[mi][2]), "r"(af[mi][3]),
                          "r"(bf[ni][0]), "r"(bf[ni][1]));
                }
        }
        __syncthreads();
    }

    // epilogue: bias (+ optional relu), N-guarded stores
#pragma unroll
    for (int mi = 0; mi < 4; mi++) {
        int r = m0 + wm * 64 + mi * 16 + gid;
#pragma unroll
        for (int ni = 0; ni < 4; ni++) {
            int c = n0 + wn * 32 + ni * 8 + tig * 2;
            if (c < N) {
                float v0 = acc[mi][ni][0] + bias[c];
                if (relu) v0 = fmaxf(v0, 0.f);
                C[(size_t)r * N + c] = v0;
                float v2 = acc[mi][ni][2] + bias[c];
                if (relu) v2 = fmaxf(v2, 0.f);
                C[(size_t)(r + 8) * N + c] = v2;
            }
            if (c + 1 < N) {
                float v1 = acc[mi][ni][1] + bias[c + 1];
                if (relu) v1 = fmaxf(v1, 0.f);
                C[(size_t)r * N + c + 1] = v1;
                float v3 = acc[mi][ni][3] + bias[c + 1];
                if (relu) v3 = fmaxf(v3, 0.f);
                C[(size_t)(r + 8) * N + c + 1] = v3;
            }
        }
    }
}

// ---------------- flash attention (online softmax), 64q x 64k tiles --------
#define HDP 65

__global__ __launch_bounds__(256)
void attn_kernel(const float* __restrict__ Q, const float* __restrict__ K,
                 const float* __restrict__ V, float* __restrict__ O)
{
    extern __shared__ float sm[];
    float* Qs = sm;
    float* Ks = Qs + 64*HDP;
    float* Vs = Ks + 64*HDP;
    float* Ps = Vs + 64*HDP;

    int qt = blockIdx.x;
    int bh = blockIdx.y;
    int b  = bh / NH_;
    int h  = bh - b * NH_;

    int tid = threadIdx.x;
    int ty = tid >> 4;
    int tx = tid & 15;
    int r0 = ty * 4;
    int c0 = tx * 4;

    const size_t headoff = (size_t)h * HD_;
    const float* Qg = Q + ((size_t)(b*S_ + qt*64)) * D_ + headoff;

    for (int idx = tid; idx < 64*16; idx += 256) {
        int r = idx >> 4;
        int c = (idx & 15) * 4;
        float4 v = *(const float4*)(Qg + (size_t)r * D_ + c);
        Qs[r*HDP + c+0] = v.x; Qs[r*HDP + c+1] = v.y;
        Qs[r*HDP + c+2] = v.z; Qs[r*HDP + c+3] = v.w;
    }

    float m_i[4], l_i[4], accO[4][4];
#pragma unroll
    for (int i = 0; i < 4; i++) {
        m_i[i] = -INFINITY; l_i[i] = 0.f;
#pragma unroll
        for (int j = 0; j < 4; j++) accO[i][j] = 0.f;
    }

    const float scale = 0.125f;

    for (int kt = 0; kt <= qt; kt++) {
        __syncthreads();
        const float* Kg = K + ((size_t)(b*S_ + kt*64)) * D_ + headoff;
        const float* Vg = V + ((size_t)(b*S_ + kt*64)) * D_ + headoff;
        for (int idx = tid; idx < 64*16; idx += 256) {
            int r = idx >> 4;
            int c = (idx & 15) * 4;
            float4 kv = *(const float4*)(Kg + (size_t)r * D_ + c);
            Ks[r*HDP + c+0] = kv.x; Ks[r*HDP + c+1] = kv.y;
            Ks[r*HDP + c+2] = kv.z; Ks[r*HDP + c+3] = kv.w;
            float4 vv = *(const float4*)(Vg + (size_t)r * D_ + c);
            Vs[r*HDP + c+0] = vv.x; Vs[r*HDP + c+1] = vv.y;
            Vs[r*HDP + c+2] = vv.z; Vs[r*HDP + c+3] = vv.w;
        }
        __syncthreads();

        float s[4][4];
#pragma unroll
        for (int i = 0; i < 4; i++)
#pragma unroll
            for (int j = 0; j < 4; j++) s[i][j] = 0.f;

        for (int d = 0; d < HD_; d++) {
            float qv[4], kv[4];
#pragma unroll
            for (int i = 0; i < 4; i++) qv[i] = Qs[(r0+i)*HDP + d];
#pragma unroll
            for (int j = 0; j < 4; j++) kv[j] = Ks[(c0+j)*HDP + d];
#pragma unroll
            for (int i = 0; i < 4; i++)
#pragma unroll
                for (int j = 0; j < 4; j++)
                    s[i][j] = fmaf(qv[i], kv[j], s[i][j]);
        }

#pragma unroll
        for (int i = 0; i < 4; i++) {
            int qpos = qt*64 + r0 + i;
            float rowmax = -INFINITY;
#pragma unroll
            for (int j = 0; j < 4; j++) {
                int kpos = kt*64 + c0 + j;
                s[i][j] = (kpos <= qpos) ? s[i][j]*scale : -INFINITY;
                rowmax = fmaxf(rowmax, s[i][j]);
            }
#pragma unroll
            for (int off = 8; off; off >>= 1)
                rowmax = fmaxf(rowmax, __shfl_xor_sync(0xffffffffu, rowmax, off, 16));
            float mnew = fmaxf(m_i[i], rowmax);
            float rsum = 0.f;
            float p[4];
#pragma unroll
            for (int j = 0; j < 4; j++) { p[j] = __expf(s[i][j] - mnew); rsum += p[j]; }
#pragma unroll
            for (int off = 8; off; off >>= 1)
                rsum += __shfl_xor_sync(0xffffffffu, rsum, off, 16);
            float corr = __expf(m_i[i] - mnew);
            l_i[i] = l_i[i]*corr + rsum;
#pragma unroll
            for (int j = 0; j < 4; j++) accO[i][j] *= corr;
            m_i[i] = mnew;
#pragma unroll
            for (int j = 0; j < 4; j++) Ps[(r0+i)*HDP + c0 + j] = p[j];
        }
        __syncthreads();

        for (int j = 0; j < 64; j++) {
            float pr[4], vv[4];
#pragma unroll
            for (int i = 0; i < 4; i++) pr[i] = Ps[(r0+i)*HDP + j];
#pragma unroll
            for (int cc = 0; cc < 4; cc++) vv[cc] = Vs[j*HDP + c0 + cc];
#pragma unroll
            for (int i = 0; i < 4; i++)
#pragma unroll
                for (int cc = 0; cc < 4; cc++)
                    accO[i][cc] = fmaf(pr[i], vv[cc], accO[i][cc]);
        }
    }

#pragma unroll
    for (int i = 0; i < 4; i++) {
        float inv = 1.f / l_i[i];
        size_t row = ((size_t)(b*S_ + qt*64 + r0 + i)) * D_ + headoff;
#pragma unroll
        for (int cc = 0; cc < 4; cc++)
            O[row + c0 + cc] = accO[i][cc] * inv;
    }
}

// ---------------- LayerNorm over D -----------------------------------------
__global__ void ln_kernel(const float* __restrict__ H,
                          const float* __restrict__ g,
                          const float* __restrict__ bb,
                          float* __restrict__ out)
{
    int row = blockIdx.x;
    const float* h = H + (size_t)row * D_;
    __shared__ float red[256];
    int tid = threadIdx.x;

    float s = 0.f;
    for (int i = tid; i < D_; i += 256) s += h[i];
    red[tid] = s; __syncthreads();
    for (int o = 128; o; o >>= 1) { if (tid < o) red[tid] += red[tid+o]; __syncthreads(); }
    float mu = red[0] / (float)D_;
    __syncthreads();

    float v = 0.f;
    for (int i = tid; i < D_; i += 256) { float d = h[i] - mu; v += d*d; }
    red[tid] = v; __syncthreads();
    for (int o = 128; o; o >>= 1) { if (tid < o) red[tid] += red[tid+o]; __syncthreads(); }
    float rstd = rsqrtf(red[0] / (float)D_ + 1e-5f);

    float* o2 = out + (size_t)row * D_;
    for (int i = tid; i < D_; i += 256)
        o2[i] = (h[i] - mu) * rstd * g[i] + bb[i];
}

// ---------------- per-row cross-entropy (single-pass online softmax) --------
__global__ void loss_rows_kernel(const float* __restrict__ logits,
                                 const int* __restrict__ targets,
                                 float* __restrict__ rowloss)
{
    int row = blockIdx.x;
    const float* l = logits + (size_t)row * V_;
    __shared__ float redm[256];
    __shared__ float reds[256];
    int tid = threadIdx.x;

    float m = -INFINITY, s = 0.f;
    for (int i = tid; i < V_; i += 256) {
        float x = l[i];
        if (x > m) { s = s * __expf(m - x) + 1.f; m = x; }
        else       { s += __expf(x - m); }
    }
    redm[tid] = m; reds[tid] = s; __syncthreads();
    for (int o = 128; o; o >>= 1) {
        if (tid < o) {
            float m2 = redm[tid+o], s2 = reds[tid+o];
            float m1 = redm[tid],   s1 = reds[tid];
            float mm = fmaxf(m1, m2);
            redm[tid] = mm;
            reds[tid] = s1 * __expf(m1 - mm) + s2 * __expf(m2 - mm);
        }
        __syncthreads();
    }
    if (tid == 0)
        rowloss[row] = -(l[targets[row]] - redm[0] - logf(reds[0]));
}

__global__ void loss_reduce_kernel(const float* __restrict__ rowloss,
                                   float* __restrict__ out)
{
    __shared__ float red[256];
    int tid = threadIdx.x;
    float s = 0.f;
    for (int i = tid; i < T_; i += 256) s += rowloss[i];
    red[tid] = s; __syncthreads();
    for (int o = 128; o; o >>= 1) { if (tid < o) red[tid] += red[tid+o]; __syncthreads(); }
    if (tid == 0) out[0] = red[0] / (float)T_;
}

// ---------------- launcher ---------------------------------------------------
extern "C" void kernel_launch(void* const* d_in, const int* in_sizes, int n_in,
                              void* d_out, int out_size)
{
    const int*   inputs  = (const int*)  d_in[0];
    const int*   targets = (const int*)  d_in[1];
    const float* wte     = (const float*)d_in[2];
    const float* wq      = (const float*)d_in[3];
    const float* bq      = (const float*)d_in[4];
    const float* wk      = (const float*)d_in[5];
    const float* bk      = (const float*)d_in[6];
    const float* wv      = (const float*)d_in[7];
    const float* bv      = (const float*)d_in[8];
    const float* wo      = (const float*)d_in[9];
    const float* bo      = (const float*)d_in[10];
    const float* w1      = (const float*)d_in[11];
    const float* b1      = (const float*)d_in[12];
    const float* w2      = (const float*)d_in[13];
    const float* b2      = (const float*)d_in[14];
    const float* ln_g    = (const float*)d_in[15];
    const float* ln_b    = (const float*)d_in[16];
    const float* w_out   = (const float*)d_in[17];
    const float* b_out   = (const float*)d_in[18];
    float* out = (float*)d_out;

    float *x,*q,*k,*v,*ctx,*ao,*h1,*h2,*hn,*rowloss;
    cudaGetSymbolAddress((void**)&x,   g_x);
    cudaGetSymbolAddress((void**)&q,   g_q);
    cudaGetSymbolAddress((void**)&k,   g_k);
    cudaGetSymbolAddress((void**)&v,   g_v);
    cudaGetSymbolAddress((void**)&ctx, g_ctx);
    cudaGetSymbolAddress((void**)&ao,  g_ao);
    cudaGetSymbolAddress((void**)&h1,  g_h1);
    cudaGetSymbolAddress((void**)&h2,  g_h2);
    cudaGetSymbolAddress((void**)&hn,  g_hn);
    cudaGetSymbolAddress((void**)&rowloss, g_rowloss);

    const int SMEM_ATTN = 4 * 64 * HDP * (int)sizeof(float);
    cudaFuncSetAttribute(attn_kernel, cudaFuncAttributeMaxDynamicSharedMemorySize, SMEM_ATTN);

    // 1. embedding + positional encoding
    embed_kernel<<<(T_*D_)/256, 256>>>(inputs, wte, x);

    // 2. Q,K,V projections (tf32 tensor cores)
    dim3 gDD(D_/128, T_/128);
    mma_gemm_kernel<<<gDD, 256>>>(x, wq, bq, q, T_, D_, D_, 0);
    mma_gemm_kernel<<<gDD, 256>>>(x, wk, bk, k, T_, D_, D_, 0);
    mma_gemm_kernel<<<gDD, 256>>>(x, wv, bv, v, T_, D_, D_, 0);

    // 3. causal multi-head attention
    attn_kernel<<<dim3(S_/64, B_*NH_), 256, SMEM_ATTN>>>(q, k, v, ctx);

    // 4. output projection
    mma_gemm_kernel<<<gDD, 256>>>(ctx, wo, bo, ao, T_, D_, D_, 0);

    // 5. FFN
    mma_gemm_kernel<<<dim3(HID_/128, T_/128), 256>>>(ao, w1, b1, h1, T_, HID_, D_, 1);
    mma_gemm_kernel<<<gDD, 256>>>(h1, w2, b2, h2, T_, D_, HID_, 0);

    // 6. LayerNorm
    ln_kernel<<<T_, 256>>>(h2, ln_g, ln_b, hn);

    // 7. vocab projection -> logits (written straight to d_out)
    mma_gemm_kernel<<<dim3((V_+127)/128, T_/128), 256>>>(hn, w_out, b_out, out, T_, V_, D_, 0);

    // 8. cross-entropy loss
    loss_rows_kernel<<<T_, 256>>>(out, targets, rowloss);
    if (out_size > T_ * V_)
        loss_reduce_kernel<<<1, 256>>>(rowloss, out + (size_t)T_ * V_);
}

// round 4
// speedup vs baseline: 3.5166x; 1.1710x over previous
#include <cuda_runtime.h>
#include <math.h>

#define V_   50257
#define VP_  50260            // padded row stride for w_out scratch (16B-aligned rows)
#define D_   768
#define S_   2048
#define B_   2
#define HID_ 2048
#define NH_  12
#define HD_  64
#define T_   (B_*S_)   // 4096 tokens

// ---------------- scratch (device globals; no allocation allowed) ----------
__device__ float g_x  [T_*D_];
__device__ float g_q  [T_*D_];
__device__ float g_k  [T_*D_];
__device__ float g_v  [T_*D_];
__device__ float g_ctx[T_*D_];
__device__ float g_ao [T_*D_];
__device__ float g_h1 [T_*HID_];
__device__ float g_h2 [T_*D_];
__device__ float g_hn [T_*D_];
__device__ float g_rowloss[T_];
// tf32-rounded weight scratch: wq wk wv wo | w1 | w2 | w_out(padded)
#define OFF_WQ  0
#define OFF_WK  (OFF_WQ + D_*D_)
#define OFF_WV  (OFF_WK + D_*D_)
#define OFF_WO  (OFF_WV + D_*D_)
#define OFF_W1  (OFF_WO + D_*D_)
#define OFF_W2  (OFF_W1 + D_*HID_)
#define OFF_WOUT (OFF_W2 + HID_*D_)
#define W_TOTAL (OFF_WOUT + D_*VP_ + 256)
__device__ float g_w[W_TOTAL];

__device__ __forceinline__ unsigned f2tf32(float f) {
    unsigned u;
    asm volatile("cvt.rna.tf32.f32 %0, %1;" : "=r"(u) : "f"(f));
    return u;
}
__device__ __forceinline__ float roundtf32(float f) {
    return __uint_as_float(f2tf32(f));
}

// ---------------- weight conversion (to tf32 grid) ---------------------------
__global__ void convert_w_kernel(const float* __restrict__ in,
                                 float* __restrict__ out, int n4)
{
    int i = blockIdx.x * blockDim.x + threadIdx.x;
    if (i >= n4) return;
    float4 v = ((const float4*)in)[i];
    v.x = roundtf32(v.x); v.y = roundtf32(v.y);
    v.z = roundtf32(v.z); v.w = roundtf32(v.w);
    ((float4*)out)[i] = v;
}

// w_out: [D_, V_] -> padded [D_, VP_], tf32-rounded, zero pad
__global__ void convert_wout_kernel(const float* __restrict__ in,
                                    float* __restrict__ out)
{
    int i = blockIdx.x * blockDim.x + threadIdx.x;   // over D_*VP_
    if (i >= D_*VP_) return;
    int r = i / VP_;
    int c = i - r * VP_;
    out[i] = (c < V_) ? roundtf32(in[(size_t)r * V_ + c]) : 0.f;
}

// ---------------- embedding + sinusoidal positional encoding ---------------
__global__ void embed_kernel(const int* __restrict__ inputs,
                             const float* __restrict__ wte,
                             float* __restrict__ x)
{
    int idx = blockIdx.x * blockDim.x + threadIdx.x;
    if (idx >= T_*D_) return;
    int t = idx / D_;
    int d = idx - t * D_;
    int s = t & (S_-1);
    int tok = inputs[t];
    int i2 = (d >> 1) * 2;
    float div = expf((float)(-i2) * (logf(10000.0f) / (float)D_));
    float ang = (float)s * div;
    float pe = (d & 1) ? cosf(ang) : sinf(ang);
    // round to tf32 grid: x feeds GEMMs only
    x[idx] = roundtf32(wte[(size_t)tok * D_ + d] + pe);
}

// ---------------- tf32 tensor-core GEMM, cp.async 3-stage pipeline ----------
// C[M,N] = A[M,K] @ W[K,N] + bias. A and W must be pre-rounded to tf32 grid.
// BM=BN=128, BK=16, 256 threads = 8 warps (2x4), warp tile 64x32.
#define GA_STRIDE 20        // A smem row stride (floats)
#define GB_STRIDE 132       // B smem row stride (floats)
#define GSTAGE    (128*GA_STRIDE + 16*GB_STRIDE)   // floats per stage = 4672

__global__ __launch_bounds__(256, 2)
void mma_gemm_kernel(const float* __restrict__ A, const float* __restrict__ W,
                     const float* __restrict__ bias, float* __restrict__ C,
                     int M, int N, int K, int ldW, int relu, int round_out)
{
    extern __shared__ float sm[];

    const int tid  = threadIdx.x;
    const int warp = tid >> 5;
    const int lane = tid & 31;
    const int gid  = lane >> 2;
    const int tig  = lane & 3;
    const int wm   = warp >> 2;
    const int wn   = warp & 3;

    const int m0 = blockIdx.y * 128;
    const int n0 = blockIdx.x * 128;

    // per-thread load coordinates
    const int ar0 = (tid + 0)   >> 2, ac0 = ((tid + 0)   & 3) * 4;
    const int ar1 = (tid + 256) >> 2, ac1 = ((tid + 256) & 3) * 4;
    const int br0 = (tid + 0)   >> 5, bc0 = ((tid + 0)   & 31) * 4;
    const int br1 = (tid + 256) >> 5, bc1 = ((tid + 256) & 31) * 4;

    // B tail handling (vocab GEMM): bytes to fetch per 16B chunk
    int bb0 = (N - (n0 + bc0)) * 4; bb0 = bb0 > 16 ? 16 : (bb0 < 0 ? 0 : bb0);
    int bb1 = (N - (n0 + bc1)) * 4; bb1 = bb1 > 16 ? 16 : (bb1 < 0 ? 0 : bb1);

    float acc[4][4][4];
#pragma unroll
    for (int i = 0; i < 4; i++)
#pragma unroll
        for (int j = 0; j < 4; j++)
#pragma unroll
            for (int c = 0; c < 4; c++) acc[i][j][c] = 0.f;

    const int nk = K >> 4;

    // stage loader
    auto load_stage = [&](int buf, int k0) {
        float* As = sm + buf * GSTAGE;
        float* Bs = As + 128 * GA_STRIDE;
        unsigned da0 = (unsigned)__cvta_generic_to_shared(&As[ar0 * GA_STRIDE + ac0]);
        unsigned da1 = (unsigned)__cvta_generic_to_shared(&As[ar1 * GA_STRIDE + ac1]);
        const float* sa0 = A + (size_t)(m0 + ar0) * K + k0 + ac0;
        const float* sa1 = A + (size_t)(m0 + ar1) * K + k0 + ac1;
        asm volatile("cp.async.cg.shared.global [%0], [%1], 16;\n" :: "r"(da0), "l"(sa0));
        asm volatile("cp.async.cg.shared.global [%0], [%1], 16;\n" :: "r"(da1), "l"(sa1));
        unsigned db0 = (unsigned)__cvta_generic_to_shared(&Bs[br0 * GB_STRIDE + bc0]);
        unsigned db1 = (unsigned)__cvta_generic_to_shared(&Bs[br1 * GB_STRIDE + bc1]);
        const float* sb0 = W + (size_t)(k0 + br0) * ldW + (bb0 ? n0 + bc0 : 0);
        const float* sb1 = W + (size_t)(k0 + br1) * ldW + (bb1 ? n0 + bc1 : 0);
        asm volatile("cp.async.cg.shared.global [%0], [%1], 16, %2;\n" :: "r"(db0), "l"(sb0), "r"(bb0));
        asm volatile("cp.async.cg.shared.global [%0], [%1], 16, %2;\n" :: "r"(db1), "l"(sb1), "r"(bb1));
    };

    // prologue: prefetch tiles 0 and 1
    load_stage(0, 0);
    asm volatile("cp.async.commit_group;\n");
    load_stage(1, 16);
    asm volatile("cp.async.commit_group;\n");

    for (int i = 0; i < nk; i++) {
        asm volatile("cp.async.wait_group 1;\n");
        __syncthreads();

        const int buf = i % 3;
        const float* As = sm + buf * GSTAGE;
        const float* Bs = As + 128 * GA_STRIDE;

        // prefetch tile i+2
        if (i + 2 < nk) load_stage((i + 2) % 3, (i + 2) * 16);
        asm volatile("cp.async.commit_group;\n");

#pragma unroll
        for (int kk = 0; kk < 16; kk += 8) {
            unsigned af[4][4], bf[4][2];
#pragma unroll
            for (int mi = 0; mi < 4; mi++) {
                int r = wm * 64 + mi * 16 + gid;
                af[mi][0] = __float_as_uint(As[(r    ) * GA_STRIDE + kk + tig    ]);
                af[mi][1] = __float_as_uint(As[(r + 8) * GA_STRIDE + kk + tig    ]);
                af[mi][2] = __float_as_uint(As[(r    ) * GA_STRIDE + kk + tig + 4]);
                af[mi][3] = __float_as_uint(As[(r + 8) * GA_STRIDE + kk + tig + 4]);
            }
#pragma unroll
            for (int ni = 0; ni < 4; ni++) {
                int c = wn * 32 + ni * 8 + gid;
                bf[ni][0] = __float_as_uint(Bs[(kk + tig    ) * GB_STRIDE + c]);
                bf[ni][1] = __float_as_uint(Bs[(kk + tig + 4) * GB_STRIDE + c]);
            }
#pragma unroll
            for (int mi = 0; mi < 4; mi++)
#pragma unroll
                for (int ni = 0; ni < 4; ni++) {
                    asm volatile(
                        "mma.sync.aligned.m16n8k8.row.col.f32.tf32.tf32.f32 "
                        "{%0,%1,%2,%3},{%4,%5,%6,%7},{%8,%9},{%0,%1,%2,%3};"
                        : "+f"(acc[mi][ni][0]), "+f"(acc[mi][ni][1]),
                          "+f"(acc[mi][ni][2]), "+f"(acc[mi][ni][3])
                        : "r"(af[mi][0]), "r"(af[mi][1]), "r"(af[mi][2]), "r"(af[mi][3]),
                          "r"(bf[ni][0]), "r"(bf[ni][1]));
                }
        }
        __syncthreads();
    }

    // epilogue
#pragma unroll
    for (int mi = 0; mi < 4; mi++) {
        int r = m0 + wm * 64 + mi * 16 + gid;
#pragma unroll
        for (int ni = 0; ni < 4; ni++) {
            int c = n0 + wn * 32 + ni * 8 + tig * 2;
#pragma unroll
            for (int half = 0; half < 2; half++) {
                int cc = c + half;
                if (cc < N) {
                    float v0 = acc[mi][ni][0 + half] + bias[cc];
                    float v2 = acc[mi][ni][2 + half] + bias[cc];
                    if (relu) { v0 = fmaxf(v0, 0.f); v2 = fmaxf(v2, 0.f); }
                    if (round_out) { v0 = roundtf32(v0); v2 = roundtf32(v2); }
                    C[(size_t)r * N + cc]       = v0;
                    C[(size_t)(r + 8) * N + cc] = v2;
                }
            }
        }
    }
}

// ---------------- flash attention (online softmax), 64q x 64k tiles --------
#define HDP 65

__global__ __launch_bounds__(256)
void attn_kernel(const float* __restrict__ Q, const float* __restrict__ K,
                 const float* __restrict__ V, float* __restrict__ O)
{
    extern __shared__ float sm[];
    float* Qs = sm;
    float* Ks = Qs + 64*HDP;
    float* Vs = Ks + 64*HDP;
    float* Ps = Vs + 64*HDP;

    int qt = blockIdx.x;
    int bh = blockIdx.y;
    int b  = bh / NH_;
    int h  = bh - b * NH_;

    int tid = threadIdx.x;
    int ty = tid >> 4;
    int tx = tid & 15;
    int r0 = ty * 4;
    int c0 = tx * 4;

    const size_t headoff = (size_t)h * HD_;
    const float* Qg = Q + ((size_t)(b*S_ + qt*64)) * D_ + headoff;

    for (int idx = tid; idx < 64*16; idx += 256) {
        int r = idx >> 4;
        int c = (idx & 15) * 4;
        float4 v = *(const float4*)(Qg + (size_t)r * D_ + c);
        Qs[r*HDP + c+0] = v.x; Qs[r*HDP + c+1] = v.y;
        Qs[r*HDP + c+2] = v.z; Qs[r*HDP + c+3] = v.w;
    }

    float m_i[4], l_i[4], accO[4][4];
#pragma unroll
    for (int i = 0; i < 4; i++) {
        m_i[i] = -INFINITY; l_i[i] = 0.f;
#pragma unroll
        for (int j = 0; j < 4; j++) accO[i][j] = 0.f;
    }

    const float scale = 0.125f;

    for (int kt = 0; kt <= qt; kt++) {
        __syncthreads();
        const float* Kg = K + ((size_t)(b*S_ + kt*64)) * D_ + headoff;
        const float* Vg = V + ((size_t)(b*S_ + kt*64)) * D_ + headoff;
        for (int idx = tid; idx < 64*16; idx += 256) {
            int r = idx >> 4;
            int c = (idx & 15) * 4;
            float4 kv = *(const float4*)(Kg + (size_t)r * D_ + c);
            Ks[r*HDP + c+0] = kv.x; Ks[r*HDP + c+1] = kv.y;
            Ks[r*HDP + c+2] = kv.z; Ks[r*HDP + c+3] = kv.w;
            float4 vv = *(const float4*)(Vg + (size_t)r * D_ + c);
            Vs[r*HDP + c+0] = vv.x; Vs[r*HDP + c+1] = vv.y;
            Vs[r*HDP + c+2] = vv.z; Vs[r*HDP + c+3] = vv.w;
        }
        __syncthreads();

        float s[4][4];
#pragma unroll
        for (int i = 0; i < 4; i++)
#pragma unroll
            for (int j = 0; j < 4; j++) s[i][j] = 0.f;

        for (int d = 0; d < HD_; d++) {
            float qv[4], kv[4];
#pragma unroll
            for (int i = 0; i < 4; i++) qv[i] = Qs[(r0+i)*HDP + d];
#pragma unroll
            for (int j = 0; j < 4; j++) kv[j] = Ks[(c0+j)*HDP + d];
#pragma unroll
            for (int i = 0; i < 4; i++)
#pragma unroll
                for (int j = 0; j < 4; j++)
                    s[i][j] = fmaf(qv[i], kv[j], s[i][j]);
        }

#pragma unroll
        for (int i = 0; i < 4; i++) {
            int qpos = qt*64 + r0 + i;
            float rowmax = -INFINITY;
#pragma unroll
            for (int j = 0; j < 4; j++) {
                int kpos = kt*64 + c0 + j;
                s[i][j] = (kpos <= qpos) ? s[i][j]*scale : -INFINITY;
                rowmax = fmaxf(rowmax, s[i][j]);
            }
#pragma unroll
            for (int off = 8; off; off >>= 1)
                rowmax = fmaxf(rowmax, __shfl_xor_sync(0xffffffffu, rowmax, off, 16));
            float mnew = fmaxf(m_i[i], rowmax);
            float rsum = 0.f;
            float p[4];
#pragma unroll
            for (int j = 0; j < 4; j++) { p[j] = __expf(s[i][j] - mnew); rsum += p[j]; }
#pragma unroll
            for (int off = 8; off; off >>= 1)
                rsum += __shfl_xor_sync(0xffffffffu, rsum, off, 16);
            float corr = __expf(m_i[i] - mnew);
            l_i[i] = l_i[i]*corr + rsum;
#pragma unroll
            for (int j = 0; j < 4; j++) accO[i][j] *= corr;
            m_i[i] = mnew;
#pragma unroll
            for (int j = 0; j < 4; j++) Ps[(r0+i)*HDP + c0 + j] = p[j];
        }
        __syncthreads();

        for (int j = 0; j < 64; j++) {
            float pr[4], vv[4];
#pragma unroll
            for (int i = 0; i < 4; i++) pr[i] = Ps[(r0+i)*HDP + j];
#pragma unroll
            for (int cc = 0; cc < 4; cc++) vv[cc] = Vs[j*HDP + c0 + cc];
#pragma unroll
            for (int i = 0; i < 4; i++)
#pragma unroll
                for (int cc = 0; cc < 4; cc++)
                    accO[i][cc] = fmaf(pr[i], vv[cc], accO[i][cc]);
        }
    }

    // ctx feeds the wo GEMM -> round to tf32 grid on store
#pragma unroll
    for (int i = 0; i < 4; i++) {
        float inv = 1.f / l_i[i];
        size_t row = ((size_t)(b*S_ + qt*64 + r0 + i)) * D_ + headoff;
#pragma unroll
        for (int cc = 0; cc < 4; cc++)
            O[row + c0 + cc] = roundtf32(accO[i][cc] * inv);
    }
}

// ---------------- LayerNorm over D -----------------------------------------
__global__ void ln_kernel(const float* __restrict__ H,
                          const float* __restrict__ g,
                          const float* __restrict__ bb,
                          float* __restrict__ out)
{
    int row = blockIdx.x;
    const float* h = H + (size_t)row * D_;
    __shared__ float red[256];
    int tid = threadIdx.x;

    float s = 0.f;
    for (int i = tid; i < D_; i += 256) s += h[i];
    red[tid] = s; __syncthreads();
    for (int o = 128; o; o >>= 1) { if (tid < o) red[tid] += red[tid+o]; __syncthreads(); }
    float mu = red[0] / (float)D_;
    __syncthreads();

    float v = 0.f;
    for (int i = tid; i < D_; i += 256) { float d = h[i] - mu; v += d*d; }
    red[tid] = v; __syncthreads();
    for (int o = 128; o; o >>= 1) { if (tid < o) red[tid] += red[tid+o]; __syncthreads(); }
    float rstd = rsqrtf(red[0] / (float)D_ + 1e-5f);

    // hn feeds the vocab GEMM -> round to tf32 grid
    float* o2 = out + (size_t)row * D_;
    for (int i = tid; i < D_; i += 256)
        o2[i] = roundtf32((h[i] - mu) * rstd * g[i] + bb[i]);
}

// ---------------- per-row cross-entropy (single-pass online softmax) --------
__global__ void loss_rows_kernel(const float* __restrict__ logits,
                                 const int* __restrict__ targets,
                                 float* __restrict__ rowloss)
{
    int row = blockIdx.x;
    const float* l = logits + (size_t)row * V_;
    __shared__ float redm[256];
    __shared__ float reds[256];
    int tid = threadIdx.x;

    float m = -INFINITY, s = 0.f;
    for (int i = tid; i < V_; i += 256) {
        float x = l[i];
        if (x > m) { s = s * __expf(m - x) + 1.f; m = x; }
        else       { s += __expf(x - m); }
    }
    redm[tid] = m; reds[tid] = s; __syncthreads();
    for (int o = 128; o; o >>= 1) {
        if (tid < o) {
            float m2 = redm[tid+o], s2 = reds[tid+o];
            float m1 = redm[tid],   s1 = reds[tid];
            float mm = fmaxf(m1, m2);
            redm[tid] = mm;
            reds[tid] = s1 * __expf(m1 - mm) + s2 * __expf(m2 - mm);
        }
        __syncthreads();
    }
    if (tid == 0)
        rowloss[row] = -(l[targets[row]] - redm[0] - logf(reds[0]));
}

__global__ void loss_reduce_kernel(const float* __restrict__ rowloss,
                                   float* __restrict__ out)
{
    __shared__ float red[256];
    int tid = threadIdx.x;
    float s = 0.f;
    for (int i = tid; i < T_; i += 256) s += rowloss[i];
    red[tid] = s; __syncthreads();
    for (int o = 128; o; o >>= 1) { if (tid < o) red[tid] += red[tid+o]; __syncthreads(); }
    if (tid == 0) out[0] = red[0] / (float)T_;
}

// ---------------- launcher ---------------------------------------------------
extern "C" void kernel_launch(void* const* d_in, const int* in_sizes, int n_in,
                              void* d_out, int out_size)
{
    const int*   inputs  = (const int*)  d_in[0];
    const int*   targets = (const int*)  d_in[1];
    const float* wte     = (const float*)d_in[2];
    const float* wq      = (const float*)d_in[3];
    const float* bq      = (const float*)d_in[4];
    const float* wk      = (const float*)d_in[5];
    const float* bk      = (const float*)d_in[6];
    const float* wv      = (const float*)d_in[7];
    const float* bv      = (const float*)d_in[8];
    const float* wo      = (const float*)d_in[9];
    const float* bo      = (const float*)d_in[10];
    const float* w1      = (const float*)d_in[11];
    const float* b1      = (const float*)d_in[12];
    const float* w2      = (const float*)d_in[13];
    const float* b2      = (const float*)d_in[14];
    const float* ln_g    = (const float*)d_in[15];
    const float* ln_b    = (const float*)d_in[16];
    const float* w_out   = (const float*)d_in[17];
    const float* b_out   = (const float*)d_in[18];
    float* out = (float*)d_out;

    float *x,*q,*k,*v,*ctx,*ao,*h1,*h2,*hn,*rowloss,*w;
    cudaGetSymbolAddress((void**)&x,   g_x);
    cudaGetSymbolAddress((void**)&q,   g_q);
    cudaGetSymbolAddress((void**)&k,   g_k);
    cudaGetSymbolAddress((void**)&v,   g_v);
    cudaGetSymbolAddress((void**)&ctx, g_ctx);
    cudaGetSymbolAddress((void**)&ao,  g_ao);
    cudaGetSymbolAddress((void**)&h1,  g_h1);
    cudaGetSymbolAddress((void**)&h2,  g_h2);
    cudaGetSymbolAddress((void**)&hn,  g_hn);
    cudaGetSymbolAddress((void**)&rowloss, g_rowloss);
    cudaGetSymbolAddress((void**)&w,   g_w);

    const int SMEM_ATTN = 4 * 64 * HDP * (int)sizeof(float);
    cudaFuncSetAttribute(attn_kernel, cudaFuncAttributeMaxDynamicSharedMemorySize, SMEM_ATTN);
    const int SMEM_GEMM = 3 * GSTAGE * (int)sizeof(float);   // 56064
    cudaFuncSetAttribute(mma_gemm_kernel, cudaFuncAttributeMaxDynamicSharedMemorySize, SMEM_GEMM);

    // 0. weight conversion to tf32 grid (scratch)
    convert_w_kernel<<<(D_*D_/4+255)/256, 256>>>(wq, w+OFF_WQ, D_*D_/4);
    convert_w_kernel<<<(D_*D_/4+255)/256, 256>>>(wk, w+OFF_WK, D_*D_/4);
    convert_w_kernel<<<(D_*D_/4+255)/256, 256>>>(wv, w+OFF_WV, D_*D_/4);
    convert_w_kernel<<<(D_*D_/4+255)/256, 256>>>(wo, w+OFF_WO, D_*D_/4);
    convert_w_kernel<<<(D_*HID_/4+255)/256, 256>>>(w1, w+OFF_W1, D_*HID_/4);
    convert_w_kernel<<<(HID_*D_/4+255)/256, 256>>>(w2, w+OFF_W2, HID_*D_/4);
    convert_wout_kernel<<<(D_*VP_+255)/256, 256>>>(w_out, w+OFF_WOUT);

    // 1. embedding + positional encoding (rounded)
    embed_kernel<<<(T_*D_)/256, 256>>>(inputs, wte, x);

    // 2. Q,K,V projections
    dim3 gDD(D_/128, T_/128);
    mma_gemm_kernel<<<gDD, 256, SMEM_GEMM>>>(x, w+OFF_WQ, bq, q, T_, D_, D_, D_, 0, 0);
    mma_gemm_kernel<<<gDD, 256, SMEM_GEMM>>>(x, w+OFF_WK, bk, k, T_, D_, D_, D_, 0, 0);
    mma_gemm_kernel<<<gDD, 256, SMEM_GEMM>>>(x, w+OFF_WV, bv, v, T_, D_, D_, D_, 0, 0);

    // 3. causal multi-head attention (ctx rounded in-kernel)
    attn_kernel<<<dim3(S_/64, B_*NH_), 256, SMEM_ATTN>>>(q, k, v, ctx);

    // 4. output projection (ao feeds FFN1 -> round)
    mma_gemm_kernel<<<gDD, 256, SMEM_GEMM>>>(ctx, w+OFF_WO, bo, ao, T_, D_, D_, D_, 0, 1);

    // 5. FFN (h1 feeds FFN2 -> round; h2 feeds LN -> no round)
    mma_gemm_kernel<<<dim3(HID_/128, T_/128), 256, SMEM_GEMM>>>(ao, w+OFF_W1, b1, h1, T_, HID_, D_, HID_, 1, 1);
    mma_gemm_kernel<<<gDD, 256, SMEM_GEMM>>>(h1, w+OFF_W2, b2, h2, T_, D_, HID_, D_, 0, 0);

    // 6. LayerNorm (hn rounded in-kernel)
    ln_kernel<<<T_, 256>>>(h2, ln_g, ln_b, hn);

    // 7. vocab projection -> logits (no rounding of final output)
    mma_gemm_kernel<<<dim3((V_+127)/128, T_/128), 256, SMEM_GEMM>>>(hn, w+OFF_WOUT, b_out, out, T_, V_, D_, VP_, 0, 0);

    // 8. cross-entropy loss
    loss_rows_kernel<<<T_, 256>>>(out, targets, rowloss);
    if (out_size > T_ * V_)
        loss_reduce_kernel<<<1, 256>>>(rowloss, out + (size_t)T_ * V_);
}

// round 5
// speedup vs baseline: 3.5199x; 1.0009x over previous
#include <cuda_runtime.h>
#include <math.h>

#define V_   50257
#define VP_  50260            // padded row stride for w_out scratch (16B-aligned rows)
#define D_   768
#define S_   2048
#define B_   2
#define HID_ 2048
#define NH_  12
#define HD_  64
#define T_   (B_*S_)   // 4096 tokens

// ---------------- scratch (device globals; no allocation allowed) ----------
__device__ float g_x  [T_*D_];
__device__ float g_q  [T_*D_];
__device__ float g_k  [T_*D_];
__device__ float g_v  [T_*D_];
__device__ float g_ctx[T_*D_];
__device__ float g_ao [T_*D_];
__device__ float g_h1 [T_*HID_];
__device__ float g_h2 [T_*D_];
__device__ float g_hn [T_*D_];
__device__ float g_rowloss[T_];
// tf32-rounded weight scratch: wq wk wv wo | w1 | w2 | w_out(padded)
#define OFF_WQ  0
#define OFF_WK  (OFF_WQ + D_*D_)
#define OFF_WV  (OFF_WK + D_*D_)
#define OFF_WO  (OFF_WV + D_*D_)
#define OFF_W1  (OFF_WO + D_*D_)
#define OFF_W2  (OFF_W1 + D_*HID_)
#define OFF_WOUT (OFF_W2 + HID_*D_)
#define W_TOTAL (OFF_WOUT + D_*VP_ + 256)
__device__ float g_w[W_TOTAL];

__device__ __forceinline__ unsigned f2tf32(float f) {
    unsigned u;
    asm volatile("cvt.rna.tf32.f32 %0, %1;" : "=r"(u) : "f"(f));
    return u;
}
__device__ __forceinline__ float roundtf32(float f) {
    return __uint_as_float(f2tf32(f));
}

// ---------------- weight conversion (to tf32 grid) ---------------------------
__global__ void convert_w_kernel(const float* __restrict__ in,
                                 float* __restrict__ out, int n4)
{
    int i = blockIdx.x * blockDim.x + threadIdx.x;
    if (i >= n4) return;
    float4 v = ((const float4*)in)[i];
    v.x = roundtf32(v.x); v.y = roundtf32(v.y);
    v.z = roundtf32(v.z); v.w = roundtf32(v.w);
    ((float4*)out)[i] = v;
}

// w_out: [D_, V_] -> padded [D_, VP_], tf32-rounded, zero pad.
// Vectorized: one float4 store per thread; coalesced scalar loads
// (input rows are not 16B-aligned since V_ % 4 == 1).
__global__ void convert_wout_kernel(const float* __restrict__ in,
                                    float* __restrict__ out)
{
    const int row4 = VP_ / 4;                     // 12565 float4 per output row
    int j = blockIdx.x * blockDim.x + threadIdx.x;
    if (j >= D_ * row4) return;
    int r  = j / row4;
    int jc = j - r * row4;
    int c  = jc * 4;
    const float* src = in + (size_t)r * V_ + c;
    float4 v;
    v.x = (c     < V_) ? roundtf32(__ldg(src + 0)) : 0.f;
    v.y = (c + 1 < V_) ? roundtf32(__ldg(src + 1)) : 0.f;
    v.z = (c + 2 < V_) ? roundtf32(__ldg(src + 2)) : 0.f;
    v.w = (c + 3 < V_) ? roundtf32(__ldg(src + 3)) : 0.f;
    ((float4*)out)[j] = v;
}

// ---------------- embedding + sinusoidal positional encoding ---------------
__global__ void embed_kernel(const int* __restrict__ inputs,
                             const float* __restrict__ wte,
                             float* __restrict__ x)
{
    int idx = blockIdx.x * blockDim.x + threadIdx.x;
    if (idx >= T_*D_) return;
    int t = idx / D_;
    int d = idx - t * D_;
    int s = t & (S_-1);
    int tok = inputs[t];
    int i2 = (d >> 1) * 2;
    float div = expf((float)(-i2) * (logf(10000.0f) / (float)D_));
    float ang = (float)s * div;
    float pe = (d & 1) ? cosf(ang) : sinf(ang);
    x[idx] = roundtf32(wte[(size_t)tok * D_ + d] + pe);
}

// ---------------- tf32 tensor-core GEMM, cp.async 3-stage pipeline ----------
// C[M,N] = A[M,K] @ W[K,N] + bias. A and W must be pre-rounded to tf32 grid.
// BM=BN=128, BK=16, 256 threads = 8 warps (2x4), warp tile 64x32.
// Grid mapping: blockIdx.x = M-tile (few), blockIdx.y = N-tile (many), so each
// wave holds all M-tiles of a few N-stripes -> B stripe read once from DRAM.
#define GA_STRIDE 20        // A smem row stride (floats)
#define GB_STRIDE 132       // B smem row stride (floats)
#define GSTAGE    (128*GA_STRIDE + 16*GB_STRIDE)   // floats per stage = 4672

__global__ __launch_bounds__(256, 2)
void mma_gemm_kernel(const float* __restrict__ A, const float* __restrict__ W,
                     const float* __restrict__ bias, float* __restrict__ C,
                     int M, int N, int K, int ldW, int relu, int round_out)
{
    extern __shared__ float sm[];

    const int tid  = threadIdx.x;
    const int warp = tid >> 5;
    const int lane = tid & 31;
    const int gid  = lane >> 2;
    const int tig  = lane & 3;
    const int wm   = warp >> 2;
    const int wn   = warp & 3;

    const int m0 = blockIdx.x * 128;   // M-tile (swapped: x = M)
    const int n0 = blockIdx.y * 128;   // N-tile

    // per-thread load coordinates
    const int ar0 = (tid + 0)   >> 2, ac0 = ((tid + 0)   & 3) * 4;
    const int ar1 = (tid + 256) >> 2, ac1 = ((tid + 256) & 3) * 4;
    const int br0 = (tid + 0)   >> 5, bc0 = ((tid + 0)   & 31) * 4;
    const int br1 = (tid + 256) >> 5, bc1 = ((tid + 256) & 31) * 4;

    // B tail handling (vocab GEMM): bytes to fetch per 16B chunk
    int bb0 = (N - (n0 + bc0)) * 4; bb0 = bb0 > 16 ? 16 : (bb0 < 0 ? 0 : bb0);
    int bb1 = (N - (n0 + bc1)) * 4; bb1 = bb1 > 16 ? 16 : (bb1 < 0 ? 0 : bb1);

    float acc[4][4][4];
#pragma unroll
    for (int i = 0; i < 4; i++)
#pragma unroll
        for (int j = 0; j < 4; j++)
#pragma unroll
            for (int c = 0; c < 4; c++) acc[i][j][c] = 0.f;

    const int nk = K >> 4;

    auto load_stage = [&](int buf, int k0) {
        float* As = sm + buf * GSTAGE;
        float* Bs = As + 128 * GA_STRIDE;
        unsigned da0 = (unsigned)__cvta_generic_to_shared(&As[ar0 * GA_STRIDE + ac0]);
        unsigned da1 = (unsigned)__cvta_generic_to_shared(&As[ar1 * GA_STRIDE + ac1]);
        const float* sa0 = A + (size_t)(m0 + ar0) * K + k0 + ac0;
        const float* sa1 = A + (size_t)(m0 + ar1) * K + k0 + ac1;
        asm volatile("cp.async.cg.shared.global [%0], [%1], 16;\n" :: "r"(da0), "l"(sa0));
        asm volatile("cp.async.cg.shared.global [%0], [%1], 16;\n" :: "r"(da1), "l"(sa1));
        unsigned db0 = (unsigned)__cvta_generic_to_shared(&Bs[br0 * GB_STRIDE + bc0]);
        unsigned db1 = (unsigned)__cvta_generic_to_shared(&Bs[br1 * GB_STRIDE + bc1]);
        const float* sb0 = W + (size_t)(k0 + br0) * ldW + (bb0 ? n0 + bc0 : 0);
        const float* sb1 = W + (size_t)(k0 + br1) * ldW + (bb1 ? n0 + bc1 : 0);
        asm volatile("cp.async.cg.shared.global [%0], [%1], 16, %2;\n" :: "r"(db0), "l"(sb0), "r"(bb0));
        asm volatile("cp.async.cg.shared.global [%0], [%1], 16, %2;\n" :: "r"(db1), "l"(sb1), "r"(bb1));
    };

    load_stage(0, 0);
    asm volatile("cp.async.commit_group;\n");
    load_stage(1, 16);
    asm volatile("cp.async.commit_group;\n");

    for (int i = 0; i < nk; i++) {
        asm volatile("cp.async.wait_group 1;\n");
        __syncthreads();

        const int buf = i % 3;
        const float* As = sm + buf * GSTAGE;
        const float* Bs = As + 128 * GA_STRIDE;

        if (i + 2 < nk) load_stage((i + 2) % 3, (i + 2) * 16);
        asm volatile("cp.async.commit_group;\n");

#pragma unroll
        for (int kk = 0; kk < 16; kk += 8) {
            unsigned af[4][4], bf[4][2];
#pragma unroll
            for (int mi = 0; mi < 4; mi++) {
                int r = wm * 64 + mi * 16 + gid;
                af[mi][0] = __float_as_uint(As[(r    ) * GA_STRIDE + kk + tig    ]);
                af[mi][1] = __float_as_uint(As[(r + 8) * GA_STRIDE + kk + tig    ]);
                af[mi][2] = __float_as_uint(As[(r    ) * GA_STRIDE + kk + tig + 4]);
                af[mi][3] = __float_as_uint(As[(r + 8) * GA_STRIDE + kk + tig + 4]);
            }
#pragma unroll
            for (int ni = 0; ni < 4; ni++) {
                int c = wn * 32 + ni * 8 + gid;
                bf[ni][0] = __float_as_uint(Bs[(kk + tig    ) * GB_STRIDE + c]);
                bf[ni][1] = __float_as_uint(Bs[(kk + tig + 4) * GB_STRIDE + c]);
            }
#pragma unroll
            for (int mi = 0; mi < 4; mi++)
#pragma unroll
                for (int ni = 0; ni < 4; ni++) {
                    asm volatile(
                        "mma.sync.aligned.m16n8k8.row.col.f32.tf32.tf32.f32 "
                        "{%0,%1,%2,%3},{%4,%5,%6,%7},{%8,%9},{%0,%1,%2,%3};"
                        : "+f"(acc[mi][ni][0]), "+f"(acc[mi][ni][1]),
                          "+f"(acc[mi][ni][2]), "+f"(acc[mi][ni][3])
                        : "r"(af[mi][0]), "r"(af[mi][1]), "r"(af[mi][2]), "r"(af[mi][3]),
                          "r"(bf[ni][0]), "r"(bf[ni][1]));
                }
        }
        __syncthreads();
    }

    // epilogue
#pragma unroll
    for (int mi = 0; mi < 4; mi++) {
        int r = m0 + wm * 64 + mi * 16 + gid;
#pragma unroll
        for (int ni = 0; ni < 4; ni++) {
            int c = n0 + wn * 32 + ni * 8 + tig * 2;
#pragma unroll
            for (int half = 0; half < 2; half++) {
                int cc = c + half;
                if (cc < N) {
                    float v0 = acc[mi][ni][0 + half] + bias[cc];
                    float v2 = acc[mi][ni][2 + half] + bias[cc];
                    if (relu) { v0 = fmaxf(v0, 0.f); v2 = fmaxf(v2, 0.f); }
                    if (round_out) { v0 = roundtf32(v0); v2 = roundtf32(v2); }
                    C[(size_t)r * N + cc]       = v0;
                    C[(size_t)(r + 8) * N + cc] = v2;
                }
            }
        }
    }
}

// ---------------- flash attention (online softmax), 64q x 64k tiles --------
#define HDP 65

__global__ __launch_bounds__(256)
void attn_kernel(const float* __restrict__ Q, const float* __restrict__ K,
                 const float* __restrict__ V, float* __restrict__ O)
{
    extern __shared__ float sm[];
    float* Qs = sm;
    float* Ks = Qs + 64*HDP;
    float* Vs = Ks + 64*HDP;
    float* Ps = Vs + 64*HDP;

    int qt = blockIdx.x;
    int bh = blockIdx.y;
    int b  = bh / NH_;
    int h  = bh - b * NH_;

    int tid = threadIdx.x;
    int ty = tid >> 4;
    int tx = tid & 15;
    int r0 = ty * 4;
    int c0 = tx * 4;

    const size_t headoff = (size_t)h * HD_;
    const float* Qg = Q + ((size_t)(b*S_ + qt*64)) * D_ + headoff;

    for (int idx = tid; idx < 64*16; idx += 256) {
        int r = idx >> 4;
        int c = (idx & 15) * 4;
        float4 v = *(const float4*)(Qg + (size_t)r * D_ + c);
        Qs[r*HDP + c+0] = v.x; Qs[r*HDP + c+1] = v.y;
        Qs[r*HDP + c+2] = v.z; Qs[r*HDP + c+3] = v.w;
    }

    float m_i[4], l_i[4], accO[4][4];
#pragma unroll
    for (int i = 0; i < 4; i++) {
        m_i[i] = -INFINITY; l_i[i] = 0.f;
#pragma unroll
        for (int j = 0; j < 4; j++) accO[i][j] = 0.f;
    }

    const float scale = 0.125f;

    for (int kt = 0; kt <= qt; kt++) {
        __syncthreads();
        const float* Kg = K + ((size_t)(b*S_ + kt*64)) * D_ + headoff;
        const float* Vg = V + ((size_t)(b*S_ + kt*64)) * D_ + headoff;
        for (int idx = tid; idx < 64*16; idx += 256) {
            int r = idx >> 4;
            int c = (idx & 15) * 4;
            float4 kv = *(const float4*)(Kg + (size_t)r * D_ + c);
            Ks[r*HDP + c+0] = kv.x; Ks[r*HDP + c+1] = kv.y;
            Ks[r*HDP + c+2] = kv.z; Ks[r*HDP + c+3] = kv.w;
            float4 vv = *(const float4*)(Vg + (size_t)r * D_ + c);
            Vs[r*HDP + c+0] = vv.x; Vs[r*HDP + c+1] = vv.y;
            Vs[r*HDP + c+2] = vv.z; Vs[r*HDP + c+3] = vv.w;
        }
        __syncthreads();

        float s[4][4];
#pragma unroll
        for (int i = 0; i < 4; i++)
#pragma unroll
            for (int j = 0; j < 4; j++) s[i][j] = 0.f;

        for (int d = 0; d < HD_; d++) {
            float qv[4], kv[4];
#pragma unroll
            for (int i = 0; i < 4; i++) qv[i] = Qs[(r0+i)*HDP + d];
#pragma unroll
            for (int j = 0; j < 4; j++) kv[j] = Ks[(c0+j)*HDP + d];
#pragma unroll
            for (int i = 0; i < 4; i++)
#pragma unroll
                for (int j = 0; j < 4; j++)
                    s[i][j] = fmaf(qv[i], kv[j], s[i][j]);
        }

#pragma unroll
        for (int i = 0; i < 4; i++) {
            int qpos = qt*64 + r0 + i;
            float rowmax = -INFINITY;
#pragma unroll
            for (int j = 0; j < 4; j++) {
                int kpos = kt*64 + c0 + j;
                s[i][j] = (kpos <= qpos) ? s[i][j]*scale : -INFINITY;
                rowmax = fmaxf(rowmax, s[i][j]);
            }
#pragma unroll
            for (int off = 8; off; off >>= 1)
                rowmax = fmaxf(rowmax, __shfl_xor_sync(0xffffffffu, rowmax, off, 16));
            float mnew = fmaxf(m_i[i], rowmax);
            float rsum = 0.f;
            float p[4];
#pragma unroll
            for (int j = 0; j < 4; j++) { p[j] = __expf(s[i][j] - mnew); rsum += p[j]; }
#pragma unroll
            for (int off = 8; off; off >>= 1)
                rsum += __shfl_xor_sync(0xffffffffu, rsum, off, 16);
            float corr = __expf(m_i[i] - mnew);
            l_i[i] = l_i[i]*corr + rsum;
#pragma unroll
            for (int j = 0; j < 4; j++) accO[i][j] *= corr;
            m_i[i] = mnew;
#pragma unroll
            for (int j = 0; j < 4; j++) Ps[(r0+i)*HDP + c0 + j] = p[j];
        }
        __syncthreads();

        for (int j = 0; j < 64; j++) {
            float pr[4], vv[4];
#pragma unroll
            for (int i = 0; i < 4; i++) pr[i] = Ps[(r0+i)*HDP + j];
#pragma unroll
            for (int cc = 0; cc < 4; cc++) vv[cc] = Vs[j*HDP + c0 + cc];
#pragma unroll
            for (int i = 0; i < 4; i++)
#pragma unroll
                for (int cc = 0; cc < 4; cc++)
                    accO[i][cc] = fmaf(pr[i], vv[cc], accO[i][cc]);
        }
    }

#pragma unroll
    for (int i = 0; i < 4; i++) {
        float inv = 1.f / l_i[i];
        size_t row = ((size_t)(b*S_ + qt*64 + r0 + i)) * D_ + headoff;
#pragma unroll
        for (int cc = 0; cc < 4; cc++)
            O[row + c0 + cc] = roundtf32(accO[i][cc] * inv);
    }
}

// ---------------- LayerNorm over D -----------------------------------------
__global__ void ln_kernel(const float* __restrict__ H,
                          const float* __restrict__ g,
                          const float* __restrict__ bb,
                          float* __restrict__ out)
{
    int row = blockIdx.x;
    const float* h = H + (size_t)row * D_;
    __shared__ float red[256];
    int tid = threadIdx.x;

    float s = 0.f;
    for (int i = tid; i < D_; i += 256) s += h[i];
    red[tid] = s; __syncthreads();
    for (int o = 128; o; o >>= 1) { if (tid < o) red[tid] += red[tid+o]; __syncthreads(); }
    float mu = red[0] / (float)D_;
    __syncthreads();

    float v = 0.f;
    for (int i = tid; i < D_; i += 256) { float d = h[i] - mu; v += d*d; }
    red[tid] = v; __syncthreads();
    for (int o = 128; o; o >>= 1) { if (tid < o) red[tid] += red[tid+o]; __syncthreads(); }
    float rstd = rsqrtf(red[0] / (float)D_ + 1e-5f);

    float* o2 = out + (size_t)row * D_;
    for (int i = tid; i < D_; i += 256)
        o2[i] = roundtf32((h[i] - mu) * rstd * g[i] + bb[i]);
}

// ---------------- per-row cross-entropy (single-pass online softmax) --------
__global__ void loss_rows_kernel(const float* __restrict__ logits,
                                 const int* __restrict__ targets,
                                 float* __restrict__ rowloss)
{
    int row = blockIdx.x;
    const float* l = logits + (size_t)row * V_;
    __shared__ float redm[256];
    __shared__ float reds[256];
    int tid = threadIdx.x;

    float m = -INFINITY, s = 0.f;
    for (int i = tid; i < V_; i += 256) {
        float x = l[i];
        if (x > m) { s = s * __expf(m - x) + 1.f; m = x; }
        else       { s += __expf(x - m); }
    }
    redm[tid] = m; reds[tid] = s; __syncthreads();
    for (int o = 128; o; o >>= 1) {
        if (tid < o) {
            float m2 = redm[tid+o], s2 = reds[tid+o];
            float m1 = redm[tid],   s1 = reds[tid];
            float mm = fmaxf(m1, m2);
            redm[tid] = mm;
            reds[tid] = s1 * __expf(m1 - mm) + s2 * __expf(m2 - mm);
        }
        __syncthreads();
    }
    if (tid == 0)
        rowloss[row] = -(l[targets[row]] - redm[0] - logf(reds[0]));
}

__global__ void loss_reduce_kernel(const float* __restrict__ rowloss,
                                   float* __restrict__ out)
{
    __shared__ float red[256];
    int tid = threadIdx.x;
    float s = 0.f;
    for (int i = tid; i < T_; i += 256) s += rowloss[i];
    red[tid] = s; __syncthreads();
    for (int o = 128; o; o >>= 1) { if (tid < o) red[tid] += red[tid+o]; __syncthreads(); }
    if (tid == 0) out[0] = red[0] / (float)T_;
}

// ---------------- launcher ---------------------------------------------------
extern "C" void kernel_launch(void* const* d_in, const int* in_sizes, int n_in,
                              void* d_out, int out_size)
{
    const int*   inputs  = (const int*)  d_in[0];
    const int*   targets = (const int*)  d_in[1];
    const float* wte     = (const float*)d_in[2];
    const float* wq      = (const float*)d_in[3];
    const float* bq      = (const float*)d_in[4];
    const float* wk      = (const float*)d_in[5];
    const float* bk      = (const float*)d_in[6];
    const float* wv      = (const float*)d_in[7];
    const float* bv      = (const float*)d_in[8];
    const float* wo      = (const float*)d_in[9];
    const float* bo      = (const float*)d_in[10];
    const float* w1      = (const float*)d_in[11];
    const float* b1      = (const float*)d_in[12];
    const float* w2      = (const float*)d_in[13];
    const float* b2      = (const float*)d_in[14];
    const float* ln_g    = (const float*)d_in[15];
    const float* ln_b    = (const float*)d_in[16];
    const float* w_out   = (const float*)d_in[17];
    const float* b_out   = (const float*)d_in[18];
    float* out = (float*)d_out;

    float *x,*q,*k,*v,*ctx,*ao,*h1,*h2,*hn,*rowloss,*w;
    cudaGetSymbolAddress((void**)&x,   g_x);
    cudaGetSymbolAddress((void**)&q,   g_q);
    cudaGetSymbolAddress((void**)&k,   g_k);
    cudaGetSymbolAddress((void**)&v,   g_v);
    cudaGetSymbolAddress((void**)&ctx, g_ctx);
    cudaGetSymbolAddress((void**)&ao,  g_ao);
    cudaGetSymbolAddress((void**)&h1,  g_h1);
    cudaGetSymbolAddress((void**)&h2,  g_h2);
    cudaGetSymbolAddress((void**)&hn,  g_hn);
    cudaGetSymbolAddress((void**)&rowloss, g_rowloss);
    cudaGetSymbolAddress((void**)&w,   g_w);

    const int SMEM_ATTN = 4 * 64 * HDP * (int)sizeof(float);
    cudaFuncSetAttribute(attn_kernel, cudaFuncAttributeMaxDynamicSharedMemorySize, SMEM_ATTN);
    const int SMEM_GEMM = 3 * GSTAGE * (int)sizeof(float);   // 56064
    cudaFuncSetAttribute(mma_gemm_kernel, cudaFuncAttributeMaxDynamicSharedMemorySize, SMEM_GEMM);

    // 0. weight conversion to tf32 grid (scratch)
    convert_w_kernel<<<(D_*D_/4+255)/256, 256>>>(wq, w+OFF_WQ, D_*D_/4);
    convert_w_kernel<<<(D_*D_/4+255)/256, 256>>>(wk, w+OFF_WK, D_*D_/4);
    convert_w_kernel<<<(D_*D_/4+255)/256, 256>>>(wv, w+OFF_WV, D_*D_/4);
    convert_w_kernel<<<(D_*D_/4+255)/256, 256>>>(wo, w+OFF_WO, D_*D_/4);
    convert_w_kernel<<<(D_*HID_/4+255)/256, 256>>>(w1, w+OFF_W1, D_*HID_/4);
    convert_w_kernel<<<(HID_*D_/4+255)/256, 256>>>(w2, w+OFF_W2, HID_*D_/4);
    convert_wout_kernel<<<(D_*(VP_/4)+255)/256, 256>>>(w_out, w+OFF_WOUT);

    // 1. embedding + positional encoding (rounded)
    embed_kernel<<<(T_*D_)/256, 256>>>(inputs, wte, x);

    // 2. Q,K,V projections  (grid: x = M-tiles, y = N-tiles)
    dim3 gDD(T_/128, D_/128);
    mma_gemm_kernel<<<gDD, 256, SMEM_GEMM>>>(x, w+OFF_WQ, bq, q, T_, D_, D_, D_, 0, 0);
    mma_gemm_kernel<<<gDD, 256, SMEM_GEMM>>>(x, w+OFF_WK, bk, k, T_, D_, D_, D_, 0, 0);
    mma_gemm_kernel<<<gDD, 256, SMEM_GEMM>>>(x, w+OFF_WV, bv, v, T_, D_, D_, D_, 0, 0);

    // 3. causal multi-head attention (ctx rounded in-kernel)
    attn_kernel<<<dim3(S_/64, B_*NH_), 256, SMEM_ATTN>>>(q, k, v, ctx);

    // 4. output projection (ao feeds FFN1 -> round)
    mma_gemm_kernel<<<gDD, 256, SMEM_GEMM>>>(ctx, w+OFF_WO, bo, ao, T_, D_, D_, D_, 0, 1);

    // 5. FFN (h1 feeds FFN2 -> round; h2 feeds LN -> no round)
    mma_gemm_kernel<<<dim3(T_/128, HID_/128), 256, SMEM_GEMM>>>(ao, w+OFF_W1, b1, h1, T_, HID_, D_, HID_, 1, 1);
    mma_gemm_kernel<<<gDD, 256, SMEM_GEMM>>>(h1, w+OFF_W2, b2, h2, T_, D_, HID_, D_, 0, 0);

    // 6. LayerNorm (hn rounded in-kernel)
    ln_kernel<<<T_, 256>>>(h2, ln_g, ln_b, hn);

    // 7. vocab projection -> logits
    mma_gemm_kernel<<<dim3(T_/128, (V_+127)/128), 256, SMEM_GEMM>>>(hn, w+OFF_WOUT, b_out, out, T_, V_, D_, VP_, 0, 0);

    // 8. cross-entropy loss
    loss_rows_kernel<<<T_, 256>>>(out, targets, rowloss);
    if (out_size > T_ * V_)
        loss_reduce_kernel<<<1, 256>>>(rowloss, out + (size_t)T_ * V_);
}

// round 7
// speedup vs baseline: 3.5797x; 1.0170x over previous
#include <cuda_runtime.h>
#include <math.h>

#define V_   50257
#define VP_  50260            // padded row stride for w_out scratch (16B-aligned rows)
#define D_   768
#define S_   2048
#define B_   2
#define HID_ 2048
#define NH_  12
#define HD_  64
#define T_   (B_*S_)   // 4096 tokens

// ---------------- scratch (device globals; no allocation allowed) ----------
__device__ float g_x  [T_*D_];
__device__ float g_q  [T_*D_];
__device__ float g_k  [T_*D_];
__device__ float g_v  [T_*D_];
__device__ float g_ctx[T_*D_];
__device__ float g_ao [T_*D_];
__device__ float g_h1 [T_*HID_];
__device__ float g_h2 [T_*D_];
__device__ float g_hn [T_*D_];
__device__ float g_rowloss[T_];
// tf32-rounded weight scratch: wq wk wv wo | w1 | w2 | w_out(padded)
#define OFF_WQ  0
#define OFF_WK  (OFF_WQ + D_*D_)
#define OFF_WV  (OFF_WK + D_*D_)
#define OFF_WO  (OFF_WV + D_*D_)
#define OFF_W1  (OFF_WO + D_*D_)
#define OFF_W2  (OFF_W1 + D_*HID_)
#define OFF_WOUT (OFF_W2 + HID_*D_)
#define W_TOTAL (OFF_WOUT + D_*VP_ + 256)
__device__ float g_w[W_TOTAL];

__device__ __forceinline__ unsigned f2tf32(float f) {
    unsigned u;
    asm volatile("cvt.rna.tf32.f32 %0, %1;" : "=r"(u) : "f"(f));
    return u;
}
__device__ __forceinline__ float roundtf32(float f) {
    return __uint_as_float(f2tf32(f));
}

// ---------------- weight conversion (to tf32 grid) ---------------------------
__global__ void convert_w_kernel(const float* __restrict__ in,
                                 float* __restrict__ out, int n4)
{
    int i = blockIdx.x * blockDim.x + threadIdx.x;
    if (i >= n4) return;
    float4 v = ((const float4*)in)[i];
    v.x = roundtf32(v.x); v.y = roundtf32(v.y);
    v.z = roundtf32(v.z); v.w = roundtf32(v.w);
    ((float4*)out)[i] = v;
}

// w_out: [D_, V_] -> padded [D_, VP_], tf32-rounded, zero pad.
__global__ void convert_wout_kernel(const float* __restrict__ in,
                                    float* __restrict__ out)
{
    const int row4 = VP_ / 4;
    int j = blockIdx.x * blockDim.x + threadIdx.x;
    if (j >= D_ * row4) return;
    int r  = j / row4;
    int jc = j - r * row4;
    int c  = jc * 4;
    const float* src = in + (size_t)r * V_ + c;
    float4 v;
    v.x = (c     < V_) ? roundtf32(__ldg(src + 0)) : 0.f;
    v.y = (c + 1 < V_) ? roundtf32(__ldg(src + 1)) : 0.f;
    v.z = (c + 2 < V_) ? roundtf32(__ldg(src + 2)) : 0.f;
    v.w = (c + 3 < V_) ? roundtf32(__ldg(src + 3)) : 0.f;
    ((float4*)out)[j] = v;
}

// ---------------- embedding + sinusoidal positional encoding ---------------
__global__ void embed_kernel(const int* __restrict__ inputs,
                             const float* __restrict__ wte,
                             float* __restrict__ x)
{
    int idx = blockIdx.x * blockDim.x + threadIdx.x;
    if (idx >= T_*D_) return;
    int t = idx / D_;
    int d = idx - t * D_;
    int s = t & (S_-1);
    int tok = inputs[t];
    int i2 = (d >> 1) * 2;
    float div = expf((float)(-i2) * (logf(10000.0f) / (float)D_));
    float ang = (float)s * div;
    float pe = (d & 1) ? cosf(ang) : sinf(ang);
    x[idx] = roundtf32(wte[(size_t)tok * D_ + d] + pe);
}

// ---------------- tf32 tensor-core GEMM, 3-stage cp.async, BK=32 ------------
// C[M,N] = A[M,K] @ W[K,N] + bias. A/W pre-rounded to tf32 grid.
// BM=BN=128, BK=32, 256 threads = 8 warps (2x4), warp tile 64x32.
// Fragment register double-buffering; conflict-free strides (A 36, B 136).
#define AST 36
#define BST 136
#define STG_A (128*AST)           // 4608 floats
#define STG_B (32*BST)            // 4352 floats
#define STG   (STG_A + STG_B)     // 8960 floats = 35840 B / stage

__global__ __launch_bounds__(256)
void mma_gemm_kernel(const float* __restrict__ A, const float* __restrict__ W,
                     const float* __restrict__ bias, float* __restrict__ C,
                     int M, int N, int K, int ldW, int relu, int round_out)
{
    extern __shared__ float sm[];

    const int tid  = threadIdx.x;
    const int warp = tid >> 5;
    const int lane = tid & 31;
    const int gid  = lane >> 2;      // 0..7
    const int tig  = lane & 3;       // 0..3
    const int wm   = warp >> 2;      // 0..1
    const int wn   = warp & 3;       // 0..3

    const int m0 = blockIdx.x * 128;
    const int n0 = blockIdx.y * 128;

    float acc[4][4][4];
#pragma unroll
    for (int i = 0; i < 4; i++)
#pragma unroll
        for (int j = 0; j < 4; j++)
#pragma unroll
            for (int c = 0; c < 4; c++) acc[i][j][c] = 0.f;

    const int nk = K >> 5;   // 32-wide K chunks

    // stage loader: A 128x32 (1024 16B chunks), B 32x128 (1024 16B chunks)
    auto load_stage = [&](int i) {
        float* As = sm + (i % 3) * STG;
        float* Bs = As + STG_A;
        const float* Ab = A + (size_t)m0 * K + i * 32;
        const float* Bb = W + (size_t)(i * 32) * ldW + n0;
#pragma unroll
        for (int t = 0; t < 4; t++) {
            int slot = t * 256 + tid;
            int r = slot >> 3, c = (slot & 7) * 4;
            unsigned d = (unsigned)__cvta_generic_to_shared(&As[r * AST + c]);
            asm volatile("cp.async.cg.shared.global [%0], [%1], 16;"
                         :: "r"(d), "l"(Ab + (size_t)r * K + c));
        }
#pragma unroll
        for (int t = 0; t < 4; t++) {
            int slot = t * 256 + tid;
            int r = slot >> 5, c = (slot & 31) * 4;
            unsigned d = (unsigned)__cvta_generic_to_shared(&Bs[r * BST + c]);
            asm volatile("cp.async.cg.shared.global [%0], [%1], 16;"
                         :: "r"(d), "l"(Bb + (size_t)r * ldW + c));
        }
        asm volatile("cp.async.commit_group;");
    };

    load_stage(0);
    load_stage(1);
    asm volatile("cp.async.wait_group 1;");
    __syncthreads();

    const float* As = sm;
    const float* Bs = sm + STG_A;

    unsigned af[2][16], bf[2][8];

    auto load_frag = [&](int fb, int kk) {
#pragma unroll
        for (int mi = 0; mi < 4; mi++) {
            int r = wm * 64 + mi * 16 + gid;
            af[fb][mi*4+0] = __float_as_uint(As[(r    ) * AST + kk + tig    ]);
            af[fb][mi*4+1] = __float_as_uint(As[(r + 8) * AST + kk + tig    ]);
            af[fb][mi*4+2] = __float_as_uint(As[(r    ) * AST + kk + tig + 4]);
            af[fb][mi*4+3] = __float_as_uint(As[(r + 8) * AST + kk + tig + 4]);
        }
#pragma unroll
        for (int ni = 0; ni < 4; ni++) {
            int c = wn * 32 + ni * 8 + gid;
            bf[fb][ni*2+0] = __float_as_uint(Bs[(kk + tig    ) * BST + c]);
            bf[fb][ni*2+1] = __float_as_uint(Bs[(kk + tig + 4) * BST + c]);
        }
    };

    auto mma_all = [&](int fb) {
#pragma unroll
        for (int mi = 0; mi < 4; mi++)
#pragma unroll
            for (int ni = 0; ni < 4; ni++) {
                asm volatile(
                    "mma.sync.aligned.m16n8k8.row.col.f32.tf32.tf32.f32 "
                    "{%0,%1,%2,%3},{%4,%5,%6,%7},{%8,%9},{%0,%1,%2,%3};"
                    : "+f"(acc[mi][ni][0]), "+f"(acc[mi][ni][1]),
                      "+f"(acc[mi][ni][2]), "+f"(acc[mi][ni][3])
                    : "r"(af[fb][mi*4+0]), "r"(af[fb][mi*4+1]),
                      "r"(af[fb][mi*4+2]), "r"(af[fb][mi*4+3]),
                      "r"(bf[fb][ni*2+0]), "r"(bf[fb][ni*2+1]));
            }
    };

    load_frag(0, 0);

    for (int i = 0; i < nk; i++) {
#pragma unroll
        for (int kk8 = 0; kk8 < 4; kk8++) {
            const int cur = kk8 & 1, nxt = cur ^ 1;
            if (kk8 == 3) {
                // advance to next stage: commit i+2, wait for i+1, sync
                if (i + 2 < nk) load_stage(i + 2);
                else            asm volatile("cp.async.commit_group;");
                asm volatile("cp.async.wait_group 1;");
                __syncthreads();
                As = sm + ((i + 1) % 3) * STG;
                Bs = As + STG_A;
                load_frag(nxt, 0);           // garbage on last iter; unused
            } else {
                load_frag(nxt, (kk8 + 1) * 8);
            }
            mma_all(cur);
        }
    }

    // epilogue: bias (+ relu / round), N-guarded stores
#pragma unroll
    for (int mi = 0; mi < 4; mi++) {
        int r = m0 + wm * 64 + mi * 16 + gid;
#pragma unroll
        for (int ni = 0; ni < 4; ni++) {
            int c = n0 + wn * 32 + ni * 8 + tig * 2;
#pragma unroll
            for (int half = 0; half < 2; half++) {
                int cc = c + half;
                if (cc < N) {
                    float v0 = acc[mi][ni][0 + half] + bias[cc];
                    float v2 = acc[mi][ni][2 + half] + bias[cc];
                    if (relu) { v0 = fmaxf(v0, 0.f); v2 = fmaxf(v2, 0.f); }
                    if (round_out) { v0 = roundtf32(v0); v2 = roundtf32(v2); }
                    C[(size_t)r * N + cc]       = v0;
                    C[(size_t)(r + 8) * N + cc] = v2;
                }
            }
        }
    }
}

// ---------------- flash attention (online softmax), 64q x 64k tiles --------
#define HDP 65

__global__ __launch_bounds__(256)
void attn_kernel(const float* __restrict__ Q, const float* __restrict__ K,
                 const float* __restrict__ V, float* __restrict__ O)
{
    extern __shared__ float sm[];
    float* Qs = sm;
    float* Ks = Qs + 64*HDP;
    float* Vs = Ks + 64*HDP;
    float* Ps = Vs + 64*HDP;

    int qt = blockIdx.x;
    int bh = blockIdx.y;
    int b  = bh / NH_;
    int h  = bh - b * NH_;

    int tid = threadIdx.x;
    int ty = tid >> 4;
    int tx = tid & 15;
    int r0 = ty * 4;
    int c0 = tx * 4;

    const size_t headoff = (size_t)h * HD_;
    const float* Qg = Q + ((size_t)(b*S_ + qt*64)) * D_ + headoff;

    for (int idx = tid; idx < 64*16; idx += 256) {
        int r = idx >> 4;
        int c = (idx & 15) * 4;
        float4 v = *(const float4*)(Qg + (size_t)r * D_ + c);
        Qs[r*HDP + c+0] = v.x; Qs[r*HDP + c+1] = v.y;
        Qs[r*HDP + c+2] = v.z; Qs[r*HDP + c+3] = v.w;
    }

    float m_i[4], l_i[4], accO[4][4];
#pragma unroll
    for (int i = 0; i < 4; i++) {
        m_i[i] = -INFINITY; l_i[i] = 0.f;
#pragma unroll
        for (int j = 0; j < 4; j++) accO[i][j] = 0.f;
    }

    const float scale = 0.125f;

    for (int kt = 0; kt <= qt; kt++) {
        __syncthreads();
        const float* Kg = K + ((size_t)(b*S_ + kt*64)) * D_ + headoff;
        const float* Vg = V + ((size_t)(b*S_ + kt*64)) * D_ + headoff;
        for (int idx = tid; idx < 64*16; idx += 256) {
            int r = idx >> 4;
            int c = (idx & 15) * 4;
            float4 kv = *(const float4*)(Kg + (size_t)r * D_ + c);
            Ks[r*HDP + c+0] = kv.x; Ks[r*HDP + c+1] = kv.y;
            Ks[r*HDP + c+2] = kv.z; Ks[r*HDP + c+3] = kv.w;
            float4 vv = *(const float4*)(Vg + (size_t)r * D_ + c);
            Vs[r*HDP + c+0] = vv.x; Vs[r*HDP + c+1] = vv.y;
            Vs[r*HDP + c+2] = vv.z; Vs[r*HDP + c+3] = vv.w;
        }
        __syncthreads();

        float s[4][4];
#pragma unroll
        for (int i = 0; i < 4; i++)
#pragma unroll
            for (int j = 0; j < 4; j++) s[i][j] = 0.f;

        for (int d = 0; d < HD_; d++) {
            float qv[4], kv[4];
#pragma unroll
            for (int i = 0; i < 4; i++) qv[i] = Qs[(r0+i)*HDP + d];
#pragma unroll
            for (int j = 0; j < 4; j++) kv[j] = Ks[(c0+j)*HDP + d];
#pragma unroll
            for (int i = 0; i < 4; i++)
#pragma unroll
                for (int j = 0; j < 4; j++)
                    s[i][j] = fmaf(qv[i], kv[j], s[i][j]);
        }

#pragma unroll
        for (int i = 0; i < 4; i++) {
            int qpos = qt*64 + r0 + i;
            float rowmax = -INFINITY;
#pragma unroll
            for (int j = 0; j < 4; j++) {
                int kpos = kt*64 + c0 + j;
                s[i][j] = (kpos <= qpos) ? s[i][j]*scale : -INFINITY;
                rowmax = fmaxf(rowmax, s[i][j]);
            }
#pragma unroll
            for (int off = 8; off; off >>= 1)
                rowmax = fmaxf(rowmax, __shfl_xor_sync(0xffffffffu, rowmax, off, 16));
            float mnew = fmaxf(m_i[i], rowmax);
            float rsum = 0.f;
            float p[4];
#pragma unroll
            for (int j = 0; j < 4; j++) { p[j] = __expf(s[i][j] - mnew); rsum += p[j]; }
#pragma unroll
            for (int off = 8; off; off >>= 1)
                rsum += __shfl_xor_sync(0xffffffffu, rsum, off, 16);
            float corr = __expf(m_i[i] - mnew);
            l_i[i] = l_i[i]*corr + rsum;
#pragma unroll
            for (int j = 0; j < 4; j++) accO[i][j] *= corr;
            m_i[i] = mnew;
#pragma unroll
            for (int j = 0; j < 4; j++) Ps[(r0+i)*HDP + c0 + j] = p[j];
        }
        __syncthreads();

        for (int j = 0; j < 64; j++) {
            float pr[4], vv[4];
#pragma unroll
            for (int i = 0; i < 4; i++) pr[i] = Ps[(r0+i)*HDP + j];
#pragma unroll
            for (int cc = 0; cc < 4; cc++) vv[cc] = Vs[j*HDP + c0 + cc];
#pragma unroll
            for (int i = 0; i < 4; i++)
#pragma unroll
                for (int cc = 0; cc < 4; cc++)
                    accO[i][cc] = fmaf(pr[i], vv[cc], accO[i][cc]);
        }
    }

#pragma unroll
    for (int i = 0; i < 4; i++) {
        float inv = 1.f / l_i[i];
        size_t row = ((size_t)(b*S_ + qt*64 + r0 + i)) * D_ + headoff;
#pragma unroll
        for (int cc = 0; cc < 4; cc++)
            O[row + c0 + cc] = roundtf32(accO[i][cc] * inv);
    }
}

// ---------------- LayerNorm over D -----------------------------------------
__global__ void ln_kernel(const float* __restrict__ H,
                          const float* __restrict__ g,
                          const float* __restrict__ bb,
                          float* __restrict__ out)
{
    int row = blockIdx.x;
    const float* h = H + (size_t)row * D_;
    __shared__ float red[256];
    int tid = threadIdx.x;

    float s = 0.f;
    for (int i = tid; i < D_; i += 256) s += h[i];
    red[tid] = s; __syncthreads();
    for (int o = 128; o; o >>= 1) { if (tid < o) red[tid] += red[tid+o]; __syncthreads(); }
    float mu = red[0] / (float)D_;
    __syncthreads();

    float v = 0.f;
    for (int i = tid; i < D_; i += 256) { float d = h[i] - mu; v += d*d; }
    red[tid] = v; __syncthreads();
    for (int o = 128; o; o >>= 1) { if (tid < o) red[tid] += red[tid+o]; __syncthreads(); }
    float rstd = rsqrtf(red[0] / (float)D_ + 1e-5f);

    float* o2 = out + (size_t)row * D_;
    for (int i = tid; i < D_; i += 256)
        o2[i] = roundtf32((h[i] - mu) * rstd * g[i] + bb[i]);
}

// ---------------- per-row cross-entropy (single-pass online softmax) --------
__global__ void loss_rows_kernel(const float* __restrict__ logits,
                                 const int* __restrict__ targets,
                                 float* __restrict__ rowloss)
{
    int row = blockIdx.x;
    const float* l = logits + (size_t)row * V_;
    __shared__ float redm[256];
    __shared__ float reds[256];
    int tid = threadIdx.x;

    float m = -INFINITY, s = 0.f;
    for (int i = tid; i < V_; i += 256) {
        float x = l[i];
        if (x > m) { s = s * __expf(m - x) + 1.f; m = x; }
        else       { s += __expf(x - m); }
    }
    redm[tid] = m; reds[tid] = s; __syncthreads();
    for (int o = 128; o; o >>= 1) {
        if (tid < o) {
            float m2 = redm[tid+o], s2 = reds[tid+o];
            float m1 = redm[tid],   s1 = reds[tid];
            float mm = fmaxf(m1, m2);
            redm[tid] = mm;
            reds[tid] = s1 * __expf(m1 - mm) + s2 * __expf(m2 - mm);
        }
        __syncthreads();
    }
    if (tid == 0)
        rowloss[row] = -(l[targets[row]] - redm[0] - logf(reds[0]));
}

__global__ void loss_reduce_kernel(const float* __restrict__ rowloss,
                                   float* __restrict__ out)
{
    __shared__ float red[256];
    int tid = threadIdx.x;
    float s = 0.f;
    for (int i = tid; i < T_; i += 256) s += rowloss[i];
    red[tid] = s; __syncthreads();
    for (int o = 128; o; o >>= 1) { if (tid < o) red[tid] += red[tid+o]; __syncthreads(); }
    if (tid == 0) out[0] = red[0] / (float)T_;
}

// ---------------- launcher ---------------------------------------------------
extern "C" void kernel_launch(void* const* d_in, const int* in_sizes, int n_in,
                              void* d_out, int out_size)
{
    const int*   inputs  = (const int*)  d_in[0];
    const int*   targets = (const int*)  d_in[1];
    const float* wte     = (const float*)d_in[2];
    const float* wq      = (const float*)d_in[3];
    const float* bq      = (const float*)d_in[4];
    const float* wk      = (const float*)d_in[5];
    const float* bk      = (const float*)d_in[6];
    const float* wv      = (const float*)d_in[7];
    const float* bv      = (const float*)d_in[8];
    const float* wo      = (const float*)d_in[9];
    const float* bo      = (const float*)d_in[10];
    const float* w1      = (const float*)d_in[11];
    const float* b1      = (const float*)d_in[12];
    const float* w2      = (const float*)d_in[13];
    const float* b2      = (const float*)d_in[14];
    const float* ln_g    = (const float*)d_in[15];
    const float* ln_b    = (const float*)d_in[16];
    const float* w_out   = (const float*)d_in[17];
    const float* b_out   = (const float*)d_in[18];
    float* out = (float*)d_out;

    float *x,*q,*k,*v,*ctx,*ao,*h1,*h2,*hn,*rowloss,*w;
    cudaGetSymbolAddress((void**)&x,   g_x);
    cudaGetSymbolAddress((void**)&q,   g_q);
    cudaGetSymbolAddress((void**)&k,   g_k);
    cudaGetSymbolAddress((void**)&v,   g_v);
    cudaGetSymbolAddress((void**)&ctx, g_ctx);
    cudaGetSymbolAddress((void**)&ao,  g_ao);
    cudaGetSymbolAddress((void**)&h1,  g_h1);
    cudaGetSymbolAddress((void**)&h2,  g_h2);
    cudaGetSymbolAddress((void**)&hn,  g_hn);
    cudaGetSymbolAddress((void**)&rowloss, g_rowloss);
    cudaGetSymbolAddress((void**)&w,   g_w);

    const int SMEM_ATTN = 4 * 64 * HDP * (int)sizeof(float);
    cudaFuncSetAttribute(attn_kernel, cudaFuncAttributeMaxDynamicSharedMemorySize, SMEM_ATTN);
    const int SMEM_GEMM = 3 * STG * (int)sizeof(float);   // 107520
    cudaFuncSetAttribute(mma_gemm_kernel, cudaFuncAttributeMaxDynamicSharedMemorySize, SMEM_GEMM);

    // 0. weight conversion to tf32 grid (scratch)
    convert_w_kernel<<<(D_*D_/4+255)/256, 256>>>(wq, w+OFF_WQ, D_*D_/4);
    convert_w_kernel<<<(D_*D_/4+255)/256, 256>>>(wk, w+OFF_WK, D_*D_/4);
    convert_w_kernel<<<(D_*D_/4+255)/256, 256>>>(wv, w+OFF_WV, D_*D_/4);
    convert_w_kernel<<<(D_*D_/4+255)/256, 256>>>(wo, w+OFF_WO, D_*D_/4);
    convert_w_kernel<<<(D_*HID_/4+255)/256, 256>>>(w1, w+OFF_W1, D_*HID_/4);
    convert_w_kernel<<<(HID_*D_/4+255)/256, 256>>>(w2, w+OFF_W2, HID_*D_/4);
    convert_wout_kernel<<<(D_*(VP_/4)+255)/256, 256>>>(w_out, w+OFF_WOUT);

    // 1. embedding + positional encoding (rounded)
    embed_kernel<<<(T_*D_)/256, 256>>>(inputs, wte, x);

    // 2. Q,K,V projections  (grid: x = M-tiles, y = N-tiles)
    dim3 gDD(T_/128, D_/128);
    mma_gemm_kernel<<<gDD, 256, SMEM_GEMM>>>(x, w+OFF_WQ, bq, q, T_, D_, D_, D_, 0, 0);
    mma_gemm_kernel<<<gDD, 256, SMEM_GEMM>>>(x, w+OFF_WK, bk, k, T_, D_, D_, D_, 0, 0);
    mma_gemm_kernel<<<gDD, 256, SMEM_GEMM>>>(x, w+OFF_WV, bv, v, T_, D_, D_, D_, 0, 0);

    // 3. causal multi-head attention (ctx rounded in-kernel)
    attn_kernel<<<dim3(S_/64, B_*NH_), 256, SMEM_ATTN>>>(q, k, v, ctx);

    // 4. output projection (ao feeds FFN1 -> round)
    mma_gemm_kernel<<<gDD, 256, SMEM_GEMM>>>(ctx, w+OFF_WO, bo, ao, T_, D_, D_, D_, 0, 1);

    // 5. FFN (h1 feeds FFN2 -> round; h2 feeds LN -> no round)
    mma_gemm_kernel<<<dim3(T_/128, HID_/128), 256, SMEM_GEMM>>>(ao, w+OFF_W1, b1, h1, T_, HID_, D_, HID_, 1, 1);
    mma_gemm_kernel<<<gDD, 256, SMEM_GEMM>>>(h1, w+OFF_W2, b2, h2, T_, D_, HID_, D_, 0, 0);

    // 6. LayerNorm (hn rounded in-kernel)
    ln_kernel<<<T_, 256>>>(h2, ln_g, ln_b, hn);

    // 7. vocab projection -> logits (B tail reads stay inside padded scratch)
    mma_gemm_kernel<<<dim3(T_/128, (V_+127)/128), 256, SMEM_GEMM>>>(hn, w+OFF_WOUT, b_out, out, T_, V_, D_, VP_, 0, 0);

    // 8. cross-entropy loss
    loss_rows_kernel<<<T_, 256>>>(out, targets, rowloss);
    if (out_size > T_ * V_)
        loss_reduce_kernel<<<1, 256>>>(rowloss, out + (size_t)T_ * V_);
}

// round 8
// speedup vs baseline: 5.4471x; 1.5217x over previous
#include <cuda_runtime.h>
#include <cuda_fp16.h>
#include <math.h>

#define V_   50257
#define VP2_ 50304            // V padded to multiple of 128 (half scratch row stride)
#define D_   768
#define S_   2048
#define B_   2
#define HID_ 2048
#define NH_  12
#define HD_  64
#define T_   (B_*S_)   // 4096 tokens

// ---------------- scratch (device globals; no allocation allowed) ----------
__device__ __half g_x  [T_*D_];
__device__ __half g_q  [T_*D_];
__device__ __half g_k  [T_*D_];
__device__ __half g_v  [T_*D_];
__device__ __half g_ctx[T_*D_];
__device__ __half g_ao [T_*D_];
__device__ __half g_h1 [T_*HID_];
__device__ float  g_h2 [T_*D_];
__device__ __half g_hn [T_*D_];
__device__ float  g_rowloss[T_];
// fp16 weight scratch: wq wk wv wo | w1 | w2 | w_out(padded)
#define OFF_WQ  0
#define OFF_WK  (OFF_WQ + D_*D_)
#define OFF_WV  (OFF_WK + D_*D_)
#define OFF_WO  (OFF_WV + D_*D_)
#define OFF_W1  (OFF_WO + D_*D_)
#define OFF_W2  (OFF_W1 + D_*HID_)
#define OFF_WOUT (OFF_W2 + HID_*D_)
#define W_TOTAL (OFF_WOUT + D_*VP2_ + 64)
__device__ __half g_w[W_TOTAL];

// ---------------- weight conversion (fp32 -> fp16) ---------------------------
__global__ void convert_w_kernel(const float* __restrict__ in,
                                 __half* __restrict__ out, int n4)
{
    int i = blockIdx.x * blockDim.x + threadIdx.x;
    if (i >= n4) return;
    float4 v = ((const float4*)in)[i];
    __half2 h0 = __floats2half2_rn(v.x, v.y);
    __half2 h1 = __floats2half2_rn(v.z, v.w);
    ((__half2*)out)[i*2+0] = h0;
    ((__half2*)out)[i*2+1] = h1;
}

// w_out: [D_, V_] f32 -> padded [D_, VP2_] f16, zero pad.
__global__ void convert_wout_kernel(const float* __restrict__ in,
                                    __half* __restrict__ out)
{
    const int row8 = VP2_ / 8;                  // 6288 8-half chunks per row
    int j = blockIdx.x * blockDim.x + threadIdx.x;
    if (j >= D_ * row8) return;
    int r  = j / row8;
    int c  = (j - r * row8) * 8;
    const float* src = in + (size_t)r * V_ + c;
    __half tmp[8];
#pragma unroll
    for (int e = 0; e < 8; e++)
        tmp[e] = (c + e < V_) ? __float2half(__ldg(src + e)) : __half(0.f);
    ((uint4*)out)[j] = *(const uint4*)tmp;
}

// ---------------- embedding + sinusoidal positional encoding ---------------
__global__ void embed_kernel(const int* __restrict__ inputs,
                             const float* __restrict__ wte,
                             __half* __restrict__ x)
{
    int idx = blockIdx.x * blockDim.x + threadIdx.x;
    if (idx >= T_*D_) return;
    int t = idx / D_;
    int d = idx - t * D_;
    int s = t & (S_-1);
    int tok = inputs[t];
    int i2 = (d >> 1) * 2;
    float div = expf((float)(-i2) * (logf(10000.0f) / (float)D_));
    float ang = (float)s * div;
    float pe = (d & 1) ? cosf(ang) : sinf(ang);
    x[idx] = __float2half(wte[(size_t)tok * D_ + d] + pe);
}

// ---------------- fp16 tensor-core GEMM, 3-stage cp.async, BK=32 -------------
// C[M,N] = A[M,K] @ W[K,N] + bias. A/W fp16, accum fp32.
// BM=BN=128, BK=32, 256 threads = 8 warps (2x4), warp tile 64x32,
// mma.sync.m16n8k16.f16, ldmatrix fragment loads, 2 CTAs/SM.
#define AST2 40                   // A smem row stride (halves): 80B, 80/16 odd
#define BST2 136                  // B smem row stride (halves): 272B, 272/16 odd
#define ASTB (128*AST2*2)         // 10240 B
#define STGB (ASTB + 32*BST2*2)   // 18944 B per stage

__global__ __launch_bounds__(256, 2)
void hgemm_kernel(const __half* __restrict__ A, const __half* __restrict__ W,
                  const float* __restrict__ bias, void* __restrict__ Cout,
                  int M, int N, int K, int ldW, int relu, int out_half)
{
    extern __shared__ char smc[];
    const int tid  = threadIdx.x;
    const int warp = tid >> 5;
    const int lane = tid & 31;
    const int gid  = lane >> 2;      // 0..7
    const int tig  = lane & 3;       // 0..3
    const int wm   = warp >> 2;      // 0..1
    const int wn   = warp & 3;       // 0..3
    const int m0 = blockIdx.x * 128;
    const int n0 = blockIdx.y * 128;
    const unsigned smem0 = (unsigned)__cvta_generic_to_shared(smc);

    float acc[4][4][4];
#pragma unroll
    for (int i = 0; i < 4; i++)
#pragma unroll
        for (int j = 0; j < 4; j++)
#pragma unroll
            for (int c = 0; c < 4; c++) acc[i][j][c] = 0.f;

    const int nk = K >> 5;

    auto load_stage = [&](int i) {
        unsigned sa = smem0 + (i % 3) * STGB;
        unsigned sb = sa + ASTB;
        const __half* Ab = A + (size_t)m0 * K + i * 32;
        const __half* Bb = W + (size_t)(i * 32) * ldW + n0;
#pragma unroll
        for (int t = 0; t < 2; t++) {
            int slot = t * 256 + tid;
            int r = slot >> 2, c = (slot & 3) * 8;
            asm volatile("cp.async.cg.shared.global [%0], [%1], 16;"
                         :: "r"(sa + (r * AST2 + c) * 2), "l"(Ab + (size_t)r * K + c));
        }
#pragma unroll
        for (int t = 0; t < 2; t++) {
            int slot = t * 256 + tid;
            int r = slot >> 4, c = (slot & 15) * 8;
            asm volatile("cp.async.cg.shared.global [%0], [%1], 16;"
                         :: "r"(sb + (r * BST2 + c) * 2), "l"(Bb + (size_t)r * ldW + c));
        }
        asm volatile("cp.async.commit_group;");
    };

    load_stage(0);
    load_stage(1);
    asm volatile("cp.async.wait_group 1;");
    __syncthreads();

    const int arow = lane & 15;
    const int acol = (lane >> 4) * 8;

    for (int i = 0; i < nk; i++) {
        unsigned sa = smem0 + (i % 3) * STGB;
        unsigned sb = sa + ASTB;

        // prefetch stage i+2 before computing stage i (buffer freed last iter)
        if (i + 2 < nk) load_stage(i + 2);
        else            asm volatile("cp.async.commit_group;");

#pragma unroll
        for (int kk = 0; kk < 32; kk += 16) {
            unsigned af[4][4], bf[4][2];
#pragma unroll
            for (int mi = 0; mi < 4; mi++) {
                unsigned ad = sa + ((wm * 64 + mi * 16 + arow) * AST2 + kk + acol) * 2;
                asm volatile("ldmatrix.sync.aligned.m8n8.x4.shared.b16 {%0,%1,%2,%3}, [%4];"
                             : "=r"(af[mi][0]), "=r"(af[mi][1]),
                               "=r"(af[mi][2]), "=r"(af[mi][3]) : "r"(ad));
            }
#pragma unroll
            for (int ni = 0; ni < 4; ni++) {
                unsigned bd = sb + ((kk + arow) * BST2 + wn * 32 + ni * 8) * 2;
                asm volatile("ldmatrix.sync.aligned.m8n8.x2.trans.shared.b16 {%0,%1}, [%2];"
                             : "=r"(bf[ni][0]), "=r"(bf[ni][1]) : "r"(bd));
            }
#pragma unroll
            for (int mi = 0; mi < 4; mi++)
#pragma unroll
                for (int ni = 0; ni < 4; ni++) {
                    asm volatile(
                        "mma.sync.aligned.m16n8k16.row.col.f32.f16.f16.f32 "
                        "{%0,%1,%2,%3},{%4,%5,%6,%7},{%8,%9},{%0,%1,%2,%3};"
                        : "+f"(acc[mi][ni][0]), "+f"(acc[mi][ni][1]),
                          "+f"(acc[mi][ni][2]), "+f"(acc[mi][ni][3])
                        : "r"(af[mi][0]), "r"(af[mi][1]),
                          "r"(af[mi][2]), "r"(af[mi][3]),
                          "r"(bf[ni][0]), "r"(bf[ni][1]));
                }
        }

        asm volatile("cp.async.wait_group 1;");
        __syncthreads();
    }

    // epilogue
#pragma unroll
    for (int mi = 0; mi < 4; mi++) {
        int r = m0 + wm * 64 + mi * 16 + gid;
#pragma unroll
        for (int ni = 0; ni < 4; ni++) {
            int c = n0 + wn * 32 + ni * 8 + tig * 2;
#pragma unroll
            for (int hh = 0; hh < 2; hh++) {
                int cc = c + hh;
                if (cc < N) {
                    float v0 = acc[mi][ni][0 + hh] + bias[cc];
                    float v2 = acc[mi][ni][2 + hh] + bias[cc];
                    if (relu) { v0 = fmaxf(v0, 0.f); v2 = fmaxf(v2, 0.f); }
                    if (out_half) {
                        ((__half*)Cout)[(size_t)r * N + cc]       = __float2half(v0);
                        ((__half*)Cout)[(size_t)(r + 8) * N + cc] = __float2half(v2);
                    } else {
                        ((float*)Cout)[(size_t)r * N + cc]       = v0;
                        ((float*)Cout)[(size_t)(r + 8) * N + cc] = v2;
                    }
                }
            }
        }
    }
}

// ---------------- flash attention (online softmax), 64q x 64k tiles --------
#define HDP 65

__global__ __launch_bounds__(256)
void attn_kernel(const __half* __restrict__ Q, const __half* __restrict__ K,
                 const __half* __restrict__ V, __half* __restrict__ O)
{
    extern __shared__ float sm[];
    float* Qs = sm;
    float* Ks = Qs + 64*HDP;
    float* Vs = Ks + 64*HDP;
    float* Ps = Vs + 64*HDP;

    int qt = blockIdx.x;
    int bh = blockIdx.y;
    int b  = bh / NH_;
    int h  = bh - b * NH_;

    int tid = threadIdx.x;
    int ty = tid >> 4;
    int tx = tid & 15;
    int r0 = ty * 4;
    int c0 = tx * 4;

    const size_t headoff = (size_t)h * HD_;
    const __half* Qg = Q + ((size_t)(b*S_ + qt*64)) * D_ + headoff;

    for (int idx = tid; idx < 64*16; idx += 256) {
        int r = idx >> 4;
        int c = (idx & 15) * 4;
        __half2 a = *(const __half2*)(Qg + (size_t)r * D_ + c);
        __half2 bq = *(const __half2*)(Qg + (size_t)r * D_ + c + 2);
        float2 f0 = __half22float2(a), f1 = __half22float2(bq);
        Qs[r*HDP + c+0] = f0.x; Qs[r*HDP + c+1] = f0.y;
        Qs[r*HDP + c+2] = f1.x; Qs[r*HDP + c+3] = f1.y;
    }

    float m_i[4], l_i[4], accO[4][4];
#pragma unroll
    for (int i = 0; i < 4; i++) {
        m_i[i] = -INFINITY; l_i[i] = 0.f;
#pragma unroll
        for (int j = 0; j < 4; j++) accO[i][j] = 0.f;
    }

    const float scale = 0.125f;

    for (int kt = 0; kt <= qt; kt++) {
        __syncthreads();
        const __half* Kg = K + ((size_t)(b*S_ + kt*64)) * D_ + headoff;
        const __half* Vg = V + ((size_t)(b*S_ + kt*64)) * D_ + headoff;
        for (int idx = tid; idx < 64*16; idx += 256) {
            int r = idx >> 4;
            int c = (idx & 15) * 4;
            __half2 k0 = *(const __half2*)(Kg + (size_t)r * D_ + c);
            __half2 k1 = *(const __half2*)(Kg + (size_t)r * D_ + c + 2);
            float2 f0 = __half22float2(k0), f1 = __half22float2(k1);
            Ks[r*HDP + c+0] = f0.x; Ks[r*HDP + c+1] = f0.y;
            Ks[r*HDP + c+2] = f1.x; Ks[r*HDP + c+3] = f1.y;
            __half2 v0 = *(const __half2*)(Vg + (size_t)r * D_ + c);
            __half2 v1 = *(const __half2*)(Vg + (size_t)r * D_ + c + 2);
            float2 g0 = __half22float2(v0), g1 = __half22float2(v1);
            Vs[r*HDP + c+0] = g0.x; Vs[r*HDP + c+1] = g0.y;
            Vs[r*HDP + c+2] = g1.x; Vs[r*HDP + c+3] = g1.y;
        }
        __syncthreads();

        float s[4][4];
#pragma unroll
        for (int i = 0; i < 4; i++)
#pragma unroll
            for (int j = 0; j < 4; j++) s[i][j] = 0.f;

        for (int d = 0; d < HD_; d++) {
            float qv[4], kv[4];
#pragma unroll
            for (int i = 0; i < 4; i++) qv[i] = Qs[(r0+i)*HDP + d];
#pragma unroll
            for (int j = 0; j < 4; j++) kv[j] = Ks[(c0+j)*HDP + d];
#pragma unroll
            for (int i = 0; i < 4; i++)
#pragma unroll
                for (int j = 0; j < 4; j++)
                    s[i][j] = fmaf(qv[i], kv[j], s[i][j]);
        }

#pragma unroll
        for (int i = 0; i < 4; i++) {
            int qpos = qt*64 + r0 + i;
            float rowmax = -INFINITY;
#pragma unroll
            for (int j = 0; j < 4; j++) {
                int kpos = kt*64 + c0 + j;
                s[i][j] = (kpos <= qpos) ? s[i][j]*scale : -INFINITY;
                rowmax = fmaxf(rowmax, s[i][j]);
            }
#pragma unroll
            for (int off = 8; off; off >>= 1)
                rowmax = fmaxf(rowmax, __shfl_xor_sync(0xffffffffu, rowmax, off, 16));
            float mnew = fmaxf(m_i[i], rowmax);
            float rsum = 0.f;
            float p[4];
#pragma unroll
            for (int j = 0; j < 4; j++) { p[j] = __expf(s[i][j] - mnew); rsum += p[j]; }
#pragma unroll
            for (int off = 8; off; off >>= 1)
                rsum += __shfl_xor_sync(0xffffffffu, rsum, off, 16);
            float corr = __expf(m_i[i] - mnew);
            l_i[i] = l_i[i]*corr + rsum;
#pragma unroll
            for (int j = 0; j < 4; j++) accO[i][j] *= corr;
            m_i[i] = mnew;
#pragma unroll
            for (int j = 0; j < 4; j++) Ps[(r0+i)*HDP + c0 + j] = p[j];
        }
        __syncthreads();

        for (int j = 0; j < 64; j++) {
            float pr[4], vv[4];
#pragma unroll
            for (int i = 0; i < 4; i++) pr[i] = Ps[(r0+i)*HDP + j];
#pragma unroll
            for (int cc = 0; cc < 4; cc++) vv[cc] = Vs[j*HDP + c0 + cc];
#pragma unroll
            for (int i = 0; i < 4; i++)
#pragma unroll
                for (int cc = 0; cc < 4; cc++)
                    accO[i][cc] = fmaf(pr[i], vv[cc], accO[i][cc]);
        }
    }

#pragma unroll
    for (int i = 0; i < 4; i++) {
        float inv = 1.f / l_i[i];
        size_t row = ((size_t)(b*S_ + qt*64 + r0 + i)) * D_ + headoff;
#pragma unroll
        for (int cc = 0; cc < 4; cc++)
            O[row + c0 + cc] = __float2half(accO[i][cc] * inv);
    }
}

// ---------------- LayerNorm over D (f32 in, f16 out) ------------------------
__global__ void ln_kernel(const float* __restrict__ H,
                          const float* __restrict__ g,
                          const float* __restrict__ bb,
                          __half* __restrict__ out)
{
    int row = blockIdx.x;
    const float* h = H + (size_t)row * D_;
    __shared__ float red[256];
    int tid = threadIdx.x;

    float s = 0.f;
    for (int i = tid; i < D_; i += 256) s += h[i];
    red[tid] = s; __syncthreads();
    for (int o = 128; o; o >>= 1) { if (tid < o) red[tid] += red[tid+o]; __syncthreads(); }
    float mu = red[0] / (float)D_;
    __syncthreads();

    float v = 0.f;
    for (int i = tid; i < D_; i += 256) { float d = h[i] - mu; v += d*d; }
    red[tid] = v; __syncthreads();
    for (int o = 128; o; o >>= 1) { if (tid < o) red[tid] += red[tid+o]; __syncthreads(); }
    float rstd = rsqrtf(red[0] / (float)D_ + 1e-5f);

    __half* o2 = out + (size_t)row * D_;
    for (int i = tid; i < D_; i += 256)
        o2[i] = __float2half((h[i] - mu) * rstd * g[i] + bb[i]);
}

// ---------------- per-row cross-entropy (single-pass online softmax) --------
__global__ void loss_rows_kernel(const float* __restrict__ logits,
                                 const int* __restrict__ targets,
                                 float* __restrict__ rowloss)
{
    int row = blockIdx.x;
    const float* l = logits + (size_t)row * V_;
    __shared__ float redm[256];
    __shared__ float reds[256];
    int tid = threadIdx.x;

    float m = -INFINITY, s = 0.f;
    for (int i = tid; i < V_; i += 256) {
        float x = l[i];
        if (x > m) { s = s * __expf(m - x) + 1.f; m = x; }
        else       { s += __expf(x - m); }
    }
    redm[tid] = m; reds[tid] = s; __syncthreads();
    for (int o = 128; o; o >>= 1) {
        if (tid < o) {
            float m2 = redm[tid+o], s2 = reds[tid+o];
            float m1 = redm[tid],   s1 = reds[tid];
            float mm = fmaxf(m1, m2);
            redm[tid] = mm;
            reds[tid] = s1 * __expf(m1 - mm) + s2 * __expf(m2 - mm);
        }
        __syncthreads();
    }
    if (tid == 0)
        rowloss[row] = -(l[targets[row]] - redm[0] - logf(reds[0]));
}

__global__ void loss_reduce_kernel(const float* __restrict__ rowloss,
                                   float* __restrict__ out)
{
    __shared__ float red[256];
    int tid = threadIdx.x;
    float s = 0.f;
    for (int i = tid; i < T_; i += 256) s += rowloss[i];
    red[tid] = s; __syncthreads();
    for (int o = 128; o; o >>= 1) { if (tid < o) red[tid] += red[tid+o]; __syncthreads(); }
    if (tid == 0) out[0] = red[0] / (float)T_;
}

// ---------------- launcher ---------------------------------------------------
extern "C" void kernel_launch(void* const* d_in, const int* in_sizes, int n_in,
                              void* d_out, int out_size)
{
    const int*   inputs  = (const int*)  d_in[0];
    const int*   targets = (const int*)  d_in[1];
    const float* wte     = (const float*)d_in[2];
    const float* wq      = (const float*)d_in[3];
    const float* bq      = (const float*)d_in[4];
    const float* wk      = (const float*)d_in[5];
    const float* bk      = (const float*)d_in[6];
    const float* wv      = (const float*)d_in[7];
    const float* bv      = (const float*)d_in[8];
    const float* wo      = (const float*)d_in[9];
    const float* bo      = (const float*)d_in[10];
    const float* w1      = (const float*)d_in[11];
    const float* b1      = (const float*)d_in[12];
    const float* w2      = (const float*)d_in[13];
    const float* b2      = (const float*)d_in[14];
    const float* ln_g    = (const float*)d_in[15];
    const float* ln_b    = (const float*)d_in[16];
    const float* w_out   = (const float*)d_in[17];
    const float* b_out   = (const float*)d_in[18];
    float* out = (float*)d_out;

    __half *x,*q,*k,*v,*ctx,*ao,*h1,*hn,*w;
    float *h2,*rowloss;
    cudaGetSymbolAddress((void**)&x,   g_x);
    cudaGetSymbolAddress((void**)&q,   g_q);
    cudaGetSymbolAddress((void**)&k,   g_k);
    cudaGetSymbolAddress((void**)&v,   g_v);
    cudaGetSymbolAddress((void**)&ctx, g_ctx);
    cudaGetSymbolAddress((void**)&ao,  g_ao);
    cudaGetSymbolAddress((void**)&h1,  g_h1);
    cudaGetSymbolAddress((void**)&h2,  g_h2);
    cudaGetSymbolAddress((void**)&hn,  g_hn);
    cudaGetSymbolAddress((void**)&rowloss, g_rowloss);
    cudaGetSymbolAddress((void**)&w,   g_w);

    const int SMEM_ATTN = 4 * 64 * HDP * (int)sizeof(float);
    cudaFuncSetAttribute(attn_kernel, cudaFuncAttributeMaxDynamicSharedMemorySize, SMEM_ATTN);
    const int SMEM_GEMM = 3 * STGB;   // 56832
    cudaFuncSetAttribute(hgemm_kernel, cudaFuncAttributeMaxDynamicSharedMemorySize, SMEM_GEMM);

    // 0. weight conversion to fp16 scratch
    convert_w_kernel<<<(D_*D_/4+255)/256, 256>>>(wq, w+OFF_WQ, D_*D_/4);
    convert_w_kernel<<<(D_*D_/4+255)/256, 256>>>(wk, w+OFF_WK, D_*D_/4);
    convert_w_kernel<<<(D_*D_/4+255)/256, 256>>>(wv, w+OFF_WV, D_*D_/4);
    convert_w_kernel<<<(D_*D_/4+255)/256, 256>>>(wo, w+OFF_WO, D_*D_/4);
    convert_w_kernel<<<(D_*HID_/4+255)/256, 256>>>(w1, w+OFF_W1, D_*HID_/4);
    convert_w_kernel<<<(HID_*D_/4+255)/256, 256>>>(w2, w+OFF_W2, HID_*D_/4);
    convert_wout_kernel<<<(D_*(VP2_/8)+255)/256, 256>>>(w_out, w+OFF_WOUT);

    // 1. embedding + positional encoding (fp16)
    embed_kernel<<<(T_*D_)/256, 256>>>(inputs, wte, x);

    // 2. Q,K,V projections
    dim3 gDD(T_/128, D_/128);
    hgemm_kernel<<<gDD, 256, SMEM_GEMM>>>(x, w+OFF_WQ, bq, q, T_, D_, D_, D_, 0, 1);
    hgemm_kernel<<<gDD, 256, SMEM_GEMM>>>(x, w+OFF_WK, bk, k, T_, D_, D_, D_, 0, 1);
    hgemm_kernel<<<gDD, 256, SMEM_GEMM>>>(x, w+OFF_WV, bv, v, T_, D_, D_, D_, 0, 1);

    // 3. causal multi-head attention (fp32 math, fp16 I/O)
    attn_kernel<<<dim3(S_/64, B_*NH_), 256, SMEM_ATTN>>>(q, k, v, ctx);

    // 4. output projection -> fp16 ao
    hgemm_kernel<<<gDD, 256, SMEM_GEMM>>>(ctx, w+OFF_WO, bo, ao, T_, D_, D_, D_, 0, 1);

    // 5. FFN (h1 fp16 + relu; h2 fp32 for LN)
    hgemm_kernel<<<dim3(T_/128, HID_/128), 256, SMEM_GEMM>>>(ao, w+OFF_W1, b1, h1, T_, HID_, D_, HID_, 1, 1);
    hgemm_kernel<<<gDD, 256, SMEM_GEMM>>>(h1, w+OFF_W2, b2, h2, T_, D_, HID_, D_, 0, 0);

    // 6. LayerNorm (fp32 in -> fp16 hn)
    ln_kernel<<<T_, 256>>>(h2, ln_g, ln_b, hn);

    // 7. vocab projection -> fp32 logits
    hgemm_kernel<<<dim3(T_/128, (V_+127)/128), 256, SMEM_GEMM>>>(hn, w+OFF_WOUT, b_out, out, T_, V_, D_, VP2_, 0, 0);

    // 8. cross-entropy loss
    loss_rows_kernel<<<T_, 256>>>(out, targets, rowloss);
    if (out_size > T_ * V_)
        loss_reduce_kernel<<<1, 256>>>(rowloss, out + (size_t)T_ * V_);
}

// round 9
// speedup vs baseline: 7.2216x; 1.3258x over previous
#include <cuda_runtime.h>
#include <cuda_fp16.h>
#include <math.h>

#define V_   50257
#define VP2_ 50304            // V padded to multiple of 128 (half scratch row stride)
#define D_   768
#define S_   2048
#define B_   2
#define HID_ 2048
#define NH_  12
#define HD_  64
#define T_   (B_*S_)   // 4096 tokens

// ---------------- scratch (device globals; no allocation allowed) ----------
__device__ __half g_x  [T_*D_];
__device__ __half g_q  [T_*D_];
__device__ __half g_k  [T_*D_];
__device__ __half g_v  [T_*D_];
__device__ __half g_ctx[T_*D_];
__device__ __half g_ao [T_*D_];
__device__ __half g_h1 [T_*HID_];
__device__ float  g_h2 [T_*D_];
__device__ __half g_hn [T_*D_];
__device__ float  g_rowloss[T_];
// fp16 weight scratch: wq wk wv wo | w1 | w2 | w_out(padded)
#define OFF_WQ  0
#define OFF_WK  (OFF_WQ + D_*D_)
#define OFF_WV  (OFF_WK + D_*D_)
#define OFF_WO  (OFF_WV + D_*D_)
#define OFF_W1  (OFF_WO + D_*D_)
#define OFF_W2  (OFF_W1 + D_*HID_)
#define OFF_WOUT (OFF_W2 + HID_*D_)
#define W_TOTAL (OFF_WOUT + D_*VP2_ + 64)
__device__ __half g_w[W_TOTAL];

// ---------------- weight conversion (fp32 -> fp16) ---------------------------
__global__ void convert_w_kernel(const float* __restrict__ in,
                                 __half* __restrict__ out, int n4)
{
    int i = blockIdx.x * blockDim.x + threadIdx.x;
    if (i >= n4) return;
    float4 v = ((const float4*)in)[i];
    __half2 h0 = __floats2half2_rn(v.x, v.y);
    __half2 h1 = __floats2half2_rn(v.z, v.w);
    ((__half2*)out)[i*2+0] = h0;
    ((__half2*)out)[i*2+1] = h1;
}

// w_out: [D_, V_] f32 -> padded [D_, VP2_] f16, zero pad.
__global__ void convert_wout_kernel(const float* __restrict__ in,
                                    __half* __restrict__ out)
{
    const int row8 = VP2_ / 8;
    int j = blockIdx.x * blockDim.x + threadIdx.x;
    if (j >= D_ * row8) return;
    int r  = j / row8;
    int c  = (j - r * row8) * 8;
    const float* src = in + (size_t)r * V_ + c;
    __half tmp[8];
#pragma unroll
    for (int e = 0; e < 8; e++)
        tmp[e] = (c + e < V_) ? __float2half(__ldg(src + e)) : __half(0.f);
    ((uint4*)out)[j] = *(const uint4*)tmp;
}

// ---------------- embedding + sinusoidal positional encoding ---------------
__global__ void embed_kernel(const int* __restrict__ inputs,
                             const float* __restrict__ wte,
                             __half* __restrict__ x)
{
    int idx = blockIdx.x * blockDim.x + threadIdx.x;
    if (idx >= T_*D_) return;
    int t = idx / D_;
    int d = idx - t * D_;
    int s = t & (S_-1);
    int tok = inputs[t];
    int i2 = (d >> 1) * 2;
    float div = expf((float)(-i2) * (logf(10000.0f) / (float)D_));
    float ang = (float)s * div;
    float pe = (d & 1) ? cosf(ang) : sinf(ang);
    x[idx] = __float2half(wte[(size_t)tok * D_ + d] + pe);
}

// ---------------- fp16 tensor-core GEMM, 3-stage cp.async, BK=32 -------------
#define AST2 40
#define BST2 136
#define ASTB (128*AST2*2)
#define STGB (ASTB + 32*BST2*2)

__global__ __launch_bounds__(256, 2)
void hgemm_kernel(const __half* __restrict__ A, const __half* __restrict__ W,
                  const float* __restrict__ bias, void* __restrict__ Cout,
                  int M, int N, int K, int ldW, int relu, int out_half)
{
    extern __shared__ char smc[];
    const int tid  = threadIdx.x;
    const int warp = tid >> 5;
    const int lane = tid & 31;
    const int gid  = lane >> 2;
    const int tig  = lane & 3;
    const int wm   = warp >> 2;
    const int wn   = warp & 3;
    const int m0 = blockIdx.x * 128;
    const int n0 = blockIdx.y * 128;
    const unsigned smem0 = (unsigned)__cvta_generic_to_shared(smc);

    float acc[4][4][4];
#pragma unroll
    for (int i = 0; i < 4; i++)
#pragma unroll
        for (int j = 0; j < 4; j++)
#pragma unroll
            for (int c = 0; c < 4; c++) acc[i][j][c] = 0.f;

    const int nk = K >> 5;

    auto load_stage = [&](int i) {
        unsigned sa = smem0 + (i % 3) * STGB;
        unsigned sb = sa + ASTB;
        const __half* Ab = A + (size_t)m0 * K + i * 32;
        const __half* Bb = W + (size_t)(i * 32) * ldW + n0;
#pragma unroll
        for (int t = 0; t < 2; t++) {
            int slot = t * 256 + tid;
            int r = slot >> 2, c = (slot & 3) * 8;
            asm volatile("cp.async.cg.shared.global [%0], [%1], 16;"
                         :: "r"(sa + (r * AST2 + c) * 2), "l"(Ab + (size_t)r * K + c));
        }
#pragma unroll
        for (int t = 0; t < 2; t++) {
            int slot = t * 256 + tid;
            int r = slot >> 4, c = (slot & 15) * 8;
            asm volatile("cp.async.cg.shared.global [%0], [%1], 16;"
                         :: "r"(sb + (r * BST2 + c) * 2), "l"(Bb + (size_t)r * ldW + c));
        }
        asm volatile("cp.async.commit_group;");
    };

    load_stage(0);
    load_stage(1);
    asm volatile("cp.async.wait_group 1;");
    __syncthreads();

    const int arow = lane & 15;
    const int acol = (lane >> 4) * 8;

    for (int i = 0; i < nk; i++) {
        unsigned sa = smem0 + (i % 3) * STGB;
        unsigned sb = sa + ASTB;

        if (i + 2 < nk) load_stage(i + 2);
        else            asm volatile("cp.async.commit_group;");

#pragma unroll
        for (int kk = 0; kk < 32; kk += 16) {
            unsigned af[4][4], bf[4][2];
#pragma unroll
            for (int mi = 0; mi < 4; mi++) {
                unsigned ad = sa + ((wm * 64 + mi * 16 + arow) * AST2 + kk + acol) * 2;
                asm volatile("ldmatrix.sync.aligned.m8n8.x4.shared.b16 {%0,%1,%2,%3}, [%4];"
                             : "=r"(af[mi][0]), "=r"(af[mi][1]),
                               "=r"(af[mi][2]), "=r"(af[mi][3]) : "r"(ad));
            }
#pragma unroll
            for (int ni = 0; ni < 4; ni++) {
                unsigned bd = sb + ((kk + arow) * BST2 + wn * 32 + ni * 8) * 2;
                asm volatile("ldmatrix.sync.aligned.m8n8.x2.trans.shared.b16 {%0,%1}, [%2];"
                             : "=r"(bf[ni][0]), "=r"(bf[ni][1]) : "r"(bd));
            }
#pragma unroll
            for (int mi = 0; mi < 4; mi++)
#pragma unroll
                for (int ni = 0; ni < 4; ni++) {
                    asm volatile(
                        "mma.sync.aligned.m16n8k16.row.col.f32.f16.f16.f32 "
                        "{%0,%1,%2,%3},{%4,%5,%6,%7},{%8,%9},{%0,%1,%2,%3};"
                        : "+f"(acc[mi][ni][0]), "+f"(acc[mi][ni][1]),
                          "+f"(acc[mi][ni][2]), "+f"(acc[mi][ni][3])
                        : "r"(af[mi][0]), "r"(af[mi][1]),
                          "r"(af[mi][2]), "r"(af[mi][3]),
                          "r"(bf[ni][0]), "r"(bf[ni][1]));
                }
        }

        asm volatile("cp.async.wait_group 1;");
        __syncthreads();
    }

#pragma unroll
    for (int mi = 0; mi < 4; mi++) {
        int r = m0 + wm * 64 + mi * 16 + gid;
#pragma unroll
        for (int ni = 0; ni < 4; ni++) {
            int c = n0 + wn * 32 + ni * 8 + tig * 2;
#pragma unroll
            for (int hh = 0; hh < 2; hh++) {
                int cc = c + hh;
                if (cc < N) {
                    float v0 = acc[mi][ni][0 + hh] + bias[cc];
                    float v2 = acc[mi][ni][2 + hh] + bias[cc];
                    if (relu) { v0 = fmaxf(v0, 0.f); v2 = fmaxf(v2, 0.f); }
                    if (out_half) {
                        ((__half*)Cout)[(size_t)r * N + cc]       = __float2half(v0);
                        ((__half*)Cout)[(size_t)(r + 8) * N + cc] = __float2half(v2);
                    } else {
                        ((float*)Cout)[(size_t)r * N + cc]       = v0;
                        ((float*)Cout)[(size_t)(r + 8) * N + cc] = v2;
                    }
                }
            }
        }
    }
}

// ---------------- tensor-core flash attention (FA2 layout) -------------------
// 64 q-rows per block, 4 warps x 16 rows, 64-key tiles, fp16 MMA, fp32 softmax.
// Q pre-scaled by 0.125 (exact) at smem load.
#define ATS 72   // smem row stride in halves (144B: conflict-free ldmatrix)

__global__ __launch_bounds__(128)
void attn_tc_kernel(const __half* __restrict__ Q, const __half* __restrict__ K,
                    const __half* __restrict__ V, __half* __restrict__ O)
{
    __shared__ __half Qs[64*ATS];
    __shared__ __half Ks[64*ATS];
    __shared__ __half Vs[64*ATS];

    const int qt = blockIdx.x;
    const int bh = blockIdx.y;
    const int b  = bh / NH_;
    const int h  = bh - b * NH_;

    const int tid  = threadIdx.x;
    const int w    = tid >> 5;
    const int lane = tid & 31;
    const int gid  = lane >> 2;
    const int tig  = lane & 3;

    const size_t hoff = (size_t)h * HD_;
    const __half* Qg = Q + ((size_t)(b*S_ + qt*64)) * D_ + hoff;

    // load Q tile (scale by 0.125 — exact in fp16)
    const __half2 sc2 = __floats2half2_rn(0.125f, 0.125f);
    for (int i = tid; i < 512; i += 128) {
        int r = i >> 3, c = (i & 7) * 8;
        uint4 u = *(const uint4*)(Qg + (size_t)r * D_ + c);
        __half2* hp = (__half2*)&u;
#pragma unroll
        for (int t = 0; t < 4; t++) hp[t] = __hmul2(hp[t], sc2);
        *(uint4*)&Qs[r*ATS + c] = u;
    }
    __syncthreads();

    const unsigned qb = (unsigned)__cvta_generic_to_shared(Qs);
    const unsigned kb = (unsigned)__cvta_generic_to_shared(Ks);
    const unsigned vb = (unsigned)__cvta_generic_to_shared(Vs);
    const int lrow = lane & 15;
    const int lcb  = (lane >> 4) * 8;

    // Q fragments: rows w*16..+15, 4 k-steps of 16
    unsigned aQ[4][4];
#pragma unroll
    for (int t = 0; t < 4; t++) {
        unsigned ad = qb + (unsigned)(((w*16 + lrow) * ATS + t*16 + lcb) * 2);
        asm volatile("ldmatrix.sync.aligned.m8n8.x4.shared.b16 {%0,%1,%2,%3}, [%4];"
                     : "=r"(aQ[t][0]), "=r"(aQ[t][1]), "=r"(aQ[t][2]), "=r"(aQ[t][3])
                     : "r"(ad));
    }

    float oacc[8][4];
#pragma unroll
    for (int j = 0; j < 8; j++)
#pragma unroll
        for (int c = 0; c < 4; c++) oacc[j][c] = 0.f;
    float m0 = -INFINITY, m1 = -INFINITY, l0 = 0.f, l1 = 0.f;

    const int r0l = w*16 + gid;    // local row (half 0)
    const int r1l = r0l + 8;       // local row (half 1)

    for (int kt = 0; kt <= qt; kt++) {
        __syncthreads();
        const __half* Kg = K + ((size_t)(b*S_ + kt*64)) * D_ + hoff;
        const __half* Vg = V + ((size_t)(b*S_ + kt*64)) * D_ + hoff;
        for (int i = tid; i < 1024; i += 128) {
            int r = (i >> 3) & 63, c = (i & 7) * 8;
            if (i < 512)
                *(uint4*)&Ks[r*ATS + c] = *(const uint4*)(Kg + (size_t)r * D_ + c);
            else
                *(uint4*)&Vs[r*ATS + c] = *(const uint4*)(Vg + (size_t)r * D_ + c);
        }
        __syncthreads();

        // ---- scores: S[16 x 64] per warp ----
        float sacc[8][4];
#pragma unroll
        for (int j = 0; j < 8; j++)
#pragma unroll
            for (int c = 0; c < 4; c++) sacc[j][c] = 0.f;

#pragma unroll
        for (int t = 0; t < 4; t++) {
#pragma unroll
            for (int jp = 0; jp < 4; jp++) {
                unsigned bk[4];
                unsigned ad = kb + (unsigned)(((jp*16 + lrow) * ATS + t*16 + lcb) * 2);
                asm volatile("ldmatrix.sync.aligned.m8n8.x4.shared.b16 {%0,%1,%2,%3}, [%4];"
                             : "=r"(bk[0]), "=r"(bk[1]), "=r"(bk[2]), "=r"(bk[3])
                             : "r"(ad));
                asm volatile(
                    "mma.sync.aligned.m16n8k16.row.col.f32.f16.f16.f32 "
                    "{%0,%1,%2,%3},{%4,%5,%6,%7},{%8,%9},{%0,%1,%2,%3};"
                    : "+f"(sacc[2*jp][0]), "+f"(sacc[2*jp][1]),
                      "+f"(sacc[2*jp][2]), "+f"(sacc[2*jp][3])
                    : "r"(aQ[t][0]), "r"(aQ[t][1]), "r"(aQ[t][2]), "r"(aQ[t][3]),
                      "r"(bk[0]), "r"(bk[2]));
                asm volatile(
                    "mma.sync.aligned.m16n8k16.row.col.f32.f16.f16.f32 "
                    "{%0,%1,%2,%3},{%4,%5,%6,%7},{%8,%9},{%0,%1,%2,%3};"
                    : "+f"(sacc[2*jp+1][0]), "+f"(sacc[2*jp+1][1]),
                      "+f"(sacc[2*jp+1][2]), "+f"(sacc[2*jp+1][3])
                    : "r"(aQ[t][0]), "r"(aQ[t][1]), "r"(aQ[t][2]), "r"(aQ[t][3]),
                      "r"(bk[1]), "r"(bk[3]));
            }
        }

        // ---- causal mask (diagonal tile only) ----
        if (kt == qt) {
#pragma unroll
            for (int j = 0; j < 8; j++) {
                int c0 = j*8 + tig*2;
                if (c0     > r0l) sacc[j][0] = -INFINITY;
                if (c0 + 1 > r0l) sacc[j][1] = -INFINITY;
                if (c0     > r1l) sacc[j][2] = -INFINITY;
                if (c0 + 1 > r1l) sacc[j][3] = -INFINITY;
            }
        }

        // ---- online softmax ----
        float mx0 = -INFINITY, mx1 = -INFINITY;
#pragma unroll
        for (int j = 0; j < 8; j++) {
            mx0 = fmaxf(mx0, fmaxf(sacc[j][0], sacc[j][1]));
            mx1 = fmaxf(mx1, fmaxf(sacc[j][2], sacc[j][3]));
        }
#pragma unroll
        for (int o = 1; o <= 2; o <<= 1) {
            mx0 = fmaxf(mx0, __shfl_xor_sync(0xffffffffu, mx0, o));
            mx1 = fmaxf(mx1, __shfl_xor_sync(0xffffffffu, mx1, o));
        }
        float nm0 = fmaxf(m0, mx0), nm1 = fmaxf(m1, mx1);
        float corr0 = __expf(m0 - nm0), corr1 = __expf(m1 - nm1);

        unsigned pa0[8], pa1[8];
        float sum0 = 0.f, sum1 = 0.f;
#pragma unroll
        for (int j = 0; j < 8; j++) {
            float p00 = __expf(sacc[j][0] - nm0);
            float p01 = __expf(sacc[j][1] - nm0);
            float p10 = __expf(sacc[j][2] - nm1);
            float p11 = __expf(sacc[j][3] - nm1);
            sum0 += p00 + p01;
            sum1 += p10 + p11;
            __half2 h0 = __floats2half2_rn(p00, p01);
            __half2 h1 = __floats2half2_rn(p10, p11);
            pa0[j] = *(unsigned*)&h0;
            pa1[j] = *(unsigned*)&h1;
        }
#pragma unroll
        for (int o = 1; o <= 2; o <<= 1) {
            sum0 += __shfl_xor_sync(0xffffffffu, sum0, o);
            sum1 += __shfl_xor_sync(0xffffffffu, sum1, o);
        }
        l0 = l0 * corr0 + sum0;
        l1 = l1 * corr1 + sum1;
        m0 = nm0; m1 = nm1;
#pragma unroll
        for (int j = 0; j < 8; j++) {
            oacc[j][0] *= corr0; oacc[j][1] *= corr0;
            oacc[j][2] *= corr1; oacc[j][3] *= corr1;
        }

        // ---- PV: O += P[16x64] @ V[64x64] ----
#pragma unroll
        for (int kc = 0; kc < 4; kc++) {
            unsigned a0 = pa0[2*kc], a1 = pa1[2*kc], a2 = pa0[2*kc+1], a3 = pa1[2*kc+1];
#pragma unroll
            for (int dp = 0; dp < 4; dp++) {
                unsigned bv[4];
                unsigned ad = vb + (unsigned)(((kc*16 + lrow) * ATS + dp*16 + lcb) * 2);
                asm volatile("ldmatrix.sync.aligned.m8n8.x4.trans.shared.b16 {%0,%1,%2,%3}, [%4];"
                             : "=r"(bv[0]), "=r"(bv[1]), "=r"(bv[2]), "=r"(bv[3])
                             : "r"(ad));
                asm volatile(
                    "mma.sync.aligned.m16n8k16.row.col.f32.f16.f16.f32 "
                    "{%0,%1,%2,%3},{%4,%5,%6,%7},{%8,%9},{%0,%1,%2,%3};"
                    : "+f"(oacc[2*dp][0]), "+f"(oacc[2*dp][1]),
                      "+f"(oacc[2*dp][2]), "+f"(oacc[2*dp][3])
                    : "r"(a0), "r"(a1), "r"(a2), "r"(a3),
                      "r"(bv[0]), "r"(bv[1]));
                asm volatile(
                    "mma.sync.aligned.m16n8k16.row.col.f32.f16.f16.f32 "
                    "{%0,%1,%2,%3},{%4,%5,%6,%7},{%8,%9},{%0,%1,%2,%3};"
                    : "+f"(oacc[2*dp+1][0]), "+f"(oacc[2*dp+1][1]),
                      "+f"(oacc[2*dp+1][2]), "+f"(oacc[2*dp+1][3])
                    : "r"(a0), "r"(a1), "r"(a2), "r"(a3),
                      "r"(bv[2]), "r"(bv[3]));
            }
        }
    }

    // ---- write out ----
    float inv0 = 1.f / l0, inv1 = 1.f / l1;
    size_t row0 = ((size_t)(b*S_ + qt*64 + r0l)) * D_ + hoff;
    size_t row1 = ((size_t)(b*S_ + qt*64 + r1l)) * D_ + hoff;
#pragma unroll
    for (int j = 0; j < 8; j++) {
        int c = j*8 + tig*2;
        __half2 o0 = __floats2half2_rn(oacc[j][0]*inv0, oacc[j][1]*inv0);
        __half2 o1 = __floats2half2_rn(oacc[j][2]*inv1, oacc[j][3]*inv1);
        *(__half2*)(O + row0 + c) = o0;
        *(__half2*)(O + row1 + c) = o1;
    }
}

// ---------------- LayerNorm over D (f32 in, f16 out) ------------------------
__global__ void ln_kernel(const float* __restrict__ H,
                          const float* __restrict__ g,
                          const float* __restrict__ bb,
                          __half* __restrict__ out)
{
    int row = blockIdx.x;
    const float* h = H + (size_t)row * D_;
    __shared__ float red[256];
    int tid = threadIdx.x;

    float s = 0.f;
    for (int i = tid; i < D_; i += 256) s += h[i];
    red[tid] = s; __syncthreads();
    for (int o = 128; o; o >>= 1) { if (tid < o) red[tid] += red[tid+o]; __syncthreads(); }
    float mu = red[0] / (float)D_;
    __syncthreads();

    float v = 0.f;
    for (int i = tid; i < D_; i += 256) { float d = h[i] - mu; v += d*d; }
    red[tid] = v; __syncthreads();
    for (int o = 128; o; o >>= 1) { if (tid < o) red[tid] += red[tid+o]; __syncthreads(); }
    float rstd = rsqrtf(red[0] / (float)D_ + 1e-5f);

    __half* o2 = out + (size_t)row * D_;
    for (int i = tid; i < D_; i += 256)
        o2[i] = __float2half((h[i] - mu) * rstd * g[i] + bb[i]);
}

// ---------------- per-row cross-entropy (single-pass online softmax) --------
__global__ void loss_rows_kernel(const float* __restrict__ logits,
                                 const int* __restrict__ targets,
                                 float* __restrict__ rowloss)
{
    int row = blockIdx.x;
    const float* l = logits + (size_t)row * V_;
    __shared__ float redm[256];
    __shared__ float reds[256];
    int tid = threadIdx.x;

    float m = -INFINITY, s = 0.f;
    for (int i = tid; i < V_; i += 256) {
        float x = l[i];
        if (x > m) { s = s * __expf(m - x) + 1.f; m = x; }
        else       { s += __expf(x - m); }
    }
    redm[tid] = m; reds[tid] = s; __syncthreads();
    for (int o = 128; o; o >>= 1) {
        if (tid < o) {
            float m2 = redm[tid+o], s2 = reds[tid+o];
            float m1 = redm[tid],   s1 = reds[tid];
            float mm = fmaxf(m1, m2);
            redm[tid] = mm;
            reds[tid] = s1 * __expf(m1 - mm) + s2 * __expf(m2 - mm);
        }
        __syncthreads();
    }
    if (tid == 0)
        rowloss[row] = -(l[targets[row]] - redm[0] - logf(reds[0]));
}

__global__ void loss_reduce_kernel(const float* __restrict__ rowloss,
                                   float* __restrict__ out)
{
    __shared__ float red[256];
    int tid = threadIdx.x;
    float s = 0.f;
    for (int i = tid; i < T_; i += 256) s += rowloss[i];
    red[tid] = s; __syncthreads();
    for (int o = 128; o; o >>= 1) { if (tid < o) red[tid] += red[tid+o]; __syncthreads(); }
    if (tid == 0) out[0] = red[0] / (float)T_;
}

// ---------------- launcher ---------------------------------------------------
extern "C" void kernel_launch(void* const* d_in, const int* in_sizes, int n_in,
                              void* d_out, int out_size)
{
    const int*   inputs  = (const int*)  d_in[0];
    const int*   targets = (const int*)  d_in[1];
    const float* wte     = (const float*)d_in[2];
    const float* wq      = (const float*)d_in[3];
    const float* bq      = (const float*)d_in[4];
    const float* wk      = (const float*)d_in[5];
    const float* bk      = (const float*)d_in[6];
    const float* wv      = (const float*)d_in[7];
    const float* bv      = (const float*)d_in[8];
    const float* wo      = (const float*)d_in[9];
    const float* bo      = (const float*)d_in[10];
    const float* w1      = (const float*)d_in[11];
    const float* b1      = (const float*)d_in[12];
    const float* w2      = (const float*)d_in[13];
    const float* b2      = (const float*)d_in[14];
    const float* ln_g    = (const float*)d_in[15];
    const float* ln_b    = (const float*)d_in[16];
    const float* w_out   = (const float*)d_in[17];
    const float* b_out   = (const float*)d_in[18];
    float* out = (float*)d_out;

    __half *x,*q,*k,*v,*ctx,*ao,*h1,*hn,*w;
    float *h2,*rowloss;
    cudaGetSymbolAddress((void**)&x,   g_x);
    cudaGetSymbolAddress((void**)&q,   g_q);
    cudaGetSymbolAddress((void**)&k,   g_k);
    cudaGetSymbolAddress((void**)&v,   g_v);
    cudaGetSymbolAddress((void**)&ctx, g_ctx);
    cudaGetSymbolAddress((void**)&ao,  g_ao);
    cudaGetSymbolAddress((void**)&h1,  g_h1);
    cudaGetSymbolAddress((void**)&h2,  g_h2);
    cudaGetSymbolAddress((void**)&hn,  g_hn);
    cudaGetSymbolAddress((void**)&rowloss, g_rowloss);
    cudaGetSymbolAddress((void**)&w,   g_w);

    const int SMEM_GEMM = 3 * STGB;
    cudaFuncSetAttribute(hgemm_kernel, cudaFuncAttributeMaxDynamicSharedMemorySize, SMEM_GEMM);

    // 0. weight conversion to fp16 scratch
    convert_w_kernel<<<(D_*D_/4+255)/256, 256>>>(wq, w+OFF_WQ, D_*D_/4);
    convert_w_kernel<<<(D_*D_/4+255)/256, 256>>>(wk, w+OFF_WK, D_*D_/4);
    convert_w_kernel<<<(D_*D_/4+255)/256, 256>>>(wv, w+OFF_WV, D_*D_/4);
    convert_w_kernel<<<(D_*D_/4+255)/256, 256>>>(wo, w+OFF_WO, D_*D_/4);
    convert_w_kernel<<<(D_*HID_/4+255)/256, 256>>>(w1, w+OFF_W1, D_*HID_/4);
    convert_w_kernel<<<(HID_*D_/4+255)/256, 256>>>(w2, w+OFF_W2, HID_*D_/4);
    convert_wout_kernel<<<(D_*(VP2_/8)+255)/256, 256>>>(w_out, w+OFF_WOUT);

    // 1. embedding + positional encoding (fp16)
    embed_kernel<<<(T_*D_)/256, 256>>>(inputs, wte, x);

    // 2. Q,K,V projections
    dim3 gDD(T_/128, D_/128);
    hgemm_kernel<<<gDD, 256, SMEM_GEMM>>>(x, w+OFF_WQ, bq, q, T_, D_, D_, D_, 0, 1);
    hgemm_kernel<<<gDD, 256, SMEM_GEMM>>>(x, w+OFF_WK, bk, k, T_, D_, D_, D_, 0, 1);
    hgemm_kernel<<<gDD, 256, SMEM_GEMM>>>(x, w+OFF_WV, bv, v, T_, D_, D_, D_, 0, 1);

    // 3. causal multi-head attention (fp16 tensor cores, fp32 softmax)
    attn_tc_kernel<<<dim3(S_/64, B_*NH_), 128>>>(q, k, v, ctx);

    // 4. output projection -> fp16 ao
    hgemm_kernel<<<gDD, 256, SMEM_GEMM>>>(ctx, w+OFF_WO, bo, ao, T_, D_, D_, D_, 0, 1);

    // 5. FFN (h1 fp16 + relu; h2 fp32 for LN)
    hgemm_kernel<<<dim3(T_/128, HID_/128), 256, SMEM_GEMM>>>(ao, w+OFF_W1, b1, h1, T_, HID_, D_, HID_, 1, 1);
    hgemm_kernel<<<gDD, 256, SMEM_GEMM>>>(h1, w+OFF_W2, b2, h2, T_, D_, HID_, D_, 0, 0);

    // 6. LayerNorm (fp32 in -> fp16 hn)
    ln_kernel<<<T_, 256>>>(h2, ln_g, ln_b, hn);

    // 7. vocab projection -> fp32 logits
    hgemm_kernel<<<dim3(T_/128, (V_+127)/128), 256, SMEM_GEMM>>>(hn, w+OFF_WOUT, b_out, out, T_, V_, D_, VP2_, 0, 0);

    // 8. cross-entropy loss
    loss_rows_kernel<<<T_, 256>>>(out, targets, rowloss);
    if (out_size > T_ * V_)
        loss_reduce_kernel<<<1, 256>>>(rowloss, out + (size_t)T_ * V_);
}

// round 10
// speedup vs baseline: 7.9672x; 1.1032x over previous
#include <cuda_runtime.h>
#include <cuda_fp16.h>
#include <math.h>

#define V_   50257
#define VP2_ 50304            // V padded to multiple of 128 (half scratch row stride)
#define NBLK_ 393             // vocab n-tiles of 128
#define D_   768
#define S_   2048
#define B_   2
#define HID_ 2048
#define NH_  12
#define HD_  64
#define T_   (B_*S_)   // 4096 tokens
#define NEG_ -1e30f

// ---------------- scratch (device globals; no allocation allowed) ----------
__device__ __half g_x  [T_*D_];
__device__ __half g_q  [T_*D_];
__device__ __half g_k  [T_*D_];
__device__ __half g_v  [T_*D_];
__device__ __half g_ctx[T_*D_];
__device__ __half g_ao [T_*D_];
__device__ __half g_h1 [T_*HID_];
__device__ float  g_h2 [T_*D_];
__device__ __half g_hn [T_*D_];
__device__ float  g_rowloss[T_];
__device__ float  g_pmax[T_*NBLK_];
__device__ float  g_psum[T_*NBLK_];
__device__ float  g_bqkv[3*D_];
// fp16 weight scratch: wqkv | wo | w1 | w2 | w_out(padded)
#define OFF_WQKV 0
#define OFF_WO   (OFF_WQKV + D_*3*D_)
#define OFF_W1   (OFF_WO + D_*D_)
#define OFF_W2   (OFF_W1 + D_*HID_)
#define OFF_WOUT (OFF_W2 + HID_*D_)
#define W_TOTAL  (OFF_WOUT + D_*VP2_ + 64)
__device__ __half g_w[W_TOTAL];

// ---------------- weight conversion kernels ---------------------------------
__global__ void convert_w_kernel(const float* __restrict__ in,
                                 __half* __restrict__ out, int n4)
{
    int i = blockIdx.x * blockDim.x + threadIdx.x;
    if (i >= n4) return;
    float4 v = ((const float4*)in)[i];
    __half2 h0 = __floats2half2_rn(v.x, v.y);
    __half2 h1 = __floats2half2_rn(v.z, v.w);
    ((__half2*)out)[i*2+0] = h0;
    ((__half2*)out)[i*2+1] = h1;
}

// wq/wk/wv [D,768] -> interleaved [D, 2304] fp16
__global__ void convert_qkv_kernel(const float* __restrict__ wq,
                                   const float* __restrict__ wk,
                                   const float* __restrict__ wv,
                                   __half* __restrict__ out)
{
    int idx = blockIdx.x * blockDim.x + threadIdx.x;  // over D_*576
    if (idx >= D_*576) return;
    int r = idx / 576, rem = idx - r * 576;
    int sel = rem / 192, c = (rem - sel * 192) * 4;
    const float* src = (sel == 0 ? wq : sel == 1 ? wk : wv) + (size_t)r * D_ + c;
    float4 v = *(const float4*)src;
    __half tmp[4] = { __float2half(v.x), __float2half(v.y),
                      __float2half(v.z), __float2half(v.w) };
    *(uint2*)(out + (size_t)r * (3*D_) + sel * D_ + c) = *(const uint2*)tmp;
}

__global__ void concat_bias_kernel(const float* __restrict__ bq,
                                   const float* __restrict__ bk,
                                   const float* __restrict__ bv,
                                   float* __restrict__ out)
{
    int i = blockIdx.x * blockDim.x + threadIdx.x;
    if (i >= 3*D_) return;
    int sel = i / D_, c = i - sel * D_;
    out[i] = (sel == 0 ? bq : sel == 1 ? bk : bv)[c];
}

// w_out: [D_, V_] f32 -> padded [D_, VP2_] f16, zero pad.
__global__ void convert_wout_kernel(const float* __restrict__ in,
                                    __half* __restrict__ out)
{
    const int row8 = VP2_ / 8;
    int j = blockIdx.x * blockDim.x + threadIdx.x;
    if (j >= D_ * row8) return;
    int r  = j / row8;
    int c  = (j - r * row8) * 8;
    const float* src = in + (size_t)r * V_ + c;
    __half tmp[8];
#pragma unroll
    for (int e = 0; e < 8; e++)
        tmp[e] = (c + e < V_) ? __float2half(__ldg(src + e)) : __half(0.f);
    ((uint4*)out)[j] = *(const uint4*)tmp;
}

// ---------------- embedding + sinusoidal positional encoding ---------------
__global__ void embed_kernel(const int* __restrict__ inputs,
                             const float* __restrict__ wte,
                             __half* __restrict__ x)
{
    int idx = blockIdx.x * blockDim.x + threadIdx.x;
    if (idx >= T_*D_) return;
    int t = idx / D_;
    int d = idx - t * D_;
    int s = t & (S_-1);
    int tok = inputs[t];
    int i2 = (d >> 1) * 2;
    float div = expf((float)(-i2) * (logf(10000.0f) / (float)D_));
    float ang = (float)s * div;
    float pe = (d & 1) ? cosf(ang) : sinf(ang);
    x[idx] = __float2half(wte[(size_t)tok * D_ + d] + pe);
}

// ---------------- fp16 tensor-core GEMM, 3-stage cp.async, BK=32 -------------
// modes: 0 = f32 out, 1 = f16 out, 2 = qkv split f16 out, 3 = f32 out + loss partials
#define AST2 40
#define BST2 136
#define ASTB (128*AST2*2)
#define STGB (ASTB + 32*BST2*2)

__global__ __launch_bounds__(256, 2)
void hgemm_kernel(const __half* __restrict__ A, const __half* __restrict__ W,
                  const float* __restrict__ bias, void* __restrict__ Cout,
                  __half* __restrict__ dq, __half* __restrict__ dk, __half* __restrict__ dv,
                  float* __restrict__ pmax, float* __restrict__ psum, int nblk,
                  int M, int N, int K, int ldW, int relu, int mode)
{
    extern __shared__ char smc[];
    const int tid  = threadIdx.x;
    const int warp = tid >> 5;
    const int lane = tid & 31;
    const int gid  = lane >> 2;
    const int tig  = lane & 3;
    const int wm   = warp >> 2;
    const int wn   = warp & 3;
    const int m0 = blockIdx.x * 128;
    const int n0 = blockIdx.y * 128;
    const unsigned smem0 = (unsigned)__cvta_generic_to_shared(smc);

    float acc[4][4][4];
#pragma unroll
    for (int i = 0; i < 4; i++)
#pragma unroll
        for (int j = 0; j < 4; j++)
#pragma unroll
            for (int c = 0; c < 4; c++) acc[i][j][c] = 0.f;

    const int nk = K >> 5;

    auto load_stage = [&](int i) {
        unsigned sa = smem0 + (i % 3) * STGB;
        unsigned sb = sa + ASTB;
        const __half* Ab = A + (size_t)m0 * K + i * 32;
        const __half* Bb = W + (size_t)(i * 32) * ldW + n0;
#pragma unroll
        for (int t = 0; t < 2; t++) {
            int slot = t * 256 + tid;
            int r = slot >> 2, c = (slot & 3) * 8;
            asm volatile("cp.async.cg.shared.global [%0], [%1], 16;"
                         :: "r"(sa + (r * AST2 + c) * 2), "l"(Ab + (size_t)r * K + c));
        }
#pragma unroll
        for (int t = 0; t < 2; t++) {
            int slot = t * 256 + tid;
            int r = slot >> 4, c = (slot & 15) * 8;
            asm volatile("cp.async.cg.shared.global [%0], [%1], 16;"
                         :: "r"(sb + (r * BST2 + c) * 2), "l"(Bb + (size_t)r * ldW + c));
        }
        asm volatile("cp.async.commit_group;");
    };

    load_stage(0);
    load_stage(1);
    asm volatile("cp.async.wait_group 1;");
    __syncthreads();

    const int arow = lane & 15;
    const int acol = (lane >> 4) * 8;

    for (int i = 0; i < nk; i++) {
        unsigned sa = smem0 + (i % 3) * STGB;
        unsigned sb = sa + ASTB;

        if (i + 2 < nk) load_stage(i + 2);
        else            asm volatile("cp.async.commit_group;");

#pragma unroll
        for (int kk = 0; kk < 32; kk += 16) {
            unsigned af[4][4], bf[4][2];
#pragma unroll
            for (int mi = 0; mi < 4; mi++) {
                unsigned ad = sa + ((wm * 64 + mi * 16 + arow) * AST2 + kk + acol) * 2;
                asm volatile("ldmatrix.sync.aligned.m8n8.x4.shared.b16 {%0,%1,%2,%3}, [%4];"
                             : "=r"(af[mi][0]), "=r"(af[mi][1]),
                               "=r"(af[mi][2]), "=r"(af[mi][3]) : "r"(ad));
            }
#pragma unroll
            for (int ni = 0; ni < 4; ni++) {
                unsigned bd = sb + ((kk + arow) * BST2 + wn * 32 + ni * 8) * 2;
                asm volatile("ldmatrix.sync.aligned.m8n8.x2.trans.shared.b16 {%0,%1}, [%2];"
                             : "=r"(bf[ni][0]), "=r"(bf[ni][1]) : "r"(bd));
            }
#pragma unroll
            for (int mi = 0; mi < 4; mi++)
#pragma unroll
                for (int ni = 0; ni < 4; ni++) {
                    asm volatile(
                        "mma.sync.aligned.m16n8k16.row.col.f32.f16.f16.f32 "
                        "{%0,%1,%2,%3},{%4,%5,%6,%7},{%8,%9},{%0,%1,%2,%3};"
                        : "+f"(acc[mi][ni][0]), "+f"(acc[mi][ni][1]),
                          "+f"(acc[mi][ni][2]), "+f"(acc[mi][ni][3])
                        : "r"(af[mi][0]), "r"(af[mi][1]),
                          "r"(af[mi][2]), "r"(af[mi][3]),
                          "r"(bf[ni][0]), "r"(bf[ni][1]));
                }
        }

        asm volatile("cp.async.wait_group 1;");
        __syncthreads();
    }

    // qkv destination select (each 128-col tile lies inside one segment)
    __half* qdst = 0; int qcol0 = 0;
    if (mode == 2) {
        int sel = n0 / D_;
        qdst  = (sel == 0 ? dq : sel == 1 ? dk : dv);
        qcol0 = n0 - sel * D_;
    }

    float* red = (float*)smc;   // [128][4][2] reuse after pipeline (4KB)

#pragma unroll
    for (int mi = 0; mi < 4; mi++) {
        int rl = wm * 64 + mi * 16 + gid;     // local row (half 0); +8 for half 1
        int r  = m0 + rl;
        float mA = NEG_, sA = 0.f, mB = NEG_, sB = 0.f;
#pragma unroll
        for (int ni = 0; ni < 4; ni++) {
            int c = n0 + wn * 32 + ni * 8 + tig * 2;
#pragma unroll
            for (int hh = 0; hh < 2; hh++) {
                int cc = c + hh;
                if (cc < N) {
                    float v0 = acc[mi][ni][0 + hh] + bias[cc];
                    float v2 = acc[mi][ni][2 + hh] + bias[cc];
                    if (relu) { v0 = fmaxf(v0, 0.f); v2 = fmaxf(v2, 0.f); }
                    if (mode == 1) {
                        ((__half*)Cout)[(size_t)r * N + cc]       = __float2half(v0);
                        ((__half*)Cout)[(size_t)(r + 8) * N + cc] = __float2half(v2);
                    } else if (mode == 2) {
                        int lc = qcol0 + (cc - n0);
                        qdst[(size_t)r * D_ + lc]       = __float2half(v0);
                        qdst[(size_t)(r + 8) * D_ + lc] = __float2half(v2);
                    } else {
                        ((float*)Cout)[(size_t)r * N + cc]       = v0;
                        ((float*)Cout)[(size_t)(r + 8) * N + cc] = v2;
                        if (mode == 3) {
                            if (v0 > mA) { sA = sA * __expf(mA - v0) + 1.f; mA = v0; }
                            else         { sA += __expf(v0 - mA); }
                            if (v2 > mB) { sB = sB * __expf(mB - v2) + 1.f; mB = v2; }
                            else         { sB += __expf(v2 - mB); }
                        }
                    }
                }
            }
        }
        if (mode == 3) {
            // quad reduce over tig lanes
#pragma unroll
            for (int o = 1; o <= 2; o <<= 1) {
                float m2 = __shfl_xor_sync(0xffffffffu, mA, o);
                float s2 = __shfl_xor_sync(0xffffffffu, sA, o);
                float mm = fmaxf(mA, m2);
                sA = sA * __expf(mA - mm) + s2 * __expf(m2 - mm);
                mA = mm;
                m2 = __shfl_xor_sync(0xffffffffu, mB, o);
                s2 = __shfl_xor_sync(0xffffffffu, sB, o);
                mm = fmaxf(mB, m2);
                sB = sB * __expf(mB - mm) + s2 * __expf(m2 - mm);
                mB = mm;
            }
            if (tig == 0) {
                red[((rl    ) * 4 + wn) * 2 + 0] = mA;
                red[((rl    ) * 4 + wn) * 2 + 1] = sA;
                red[((rl + 8) * 4 + wn) * 2 + 0] = mB;
                red[((rl + 8) * 4 + wn) * 2 + 1] = sB;
            }
        }
    }

    if (mode == 3) {
        __syncthreads();
        if (tid < 128) {
            float m = NEG_, s = 0.f;
#pragma unroll
            for (int wnn = 0; wnn < 4; wnn++) {
                float m2 = red[(tid * 4 + wnn) * 2 + 0];
                float s2 = red[(tid * 4 + wnn) * 2 + 1];
                float mm = fmaxf(m, m2);
                s = s * __expf(m - mm) + s2 * __expf(m2 - mm);
                m = mm;
            }
            pmax[(size_t)(m0 + tid) * nblk + blockIdx.y] = m;
            psum[(size_t)(m0 + tid) * nblk + blockIdx.y] = s;
        }
    }
}

// ---------------- tensor-core flash attention (FA2 layout) -------------------
#define ATS 72

__global__ __launch_bounds__(128)
void attn_tc_kernel(const __half* __restrict__ Q, const __half* __restrict__ K,
                    const __half* __restrict__ V, __half* __restrict__ O)
{
    __shared__ __half Qs[64*ATS];
    __shared__ __half Ks[64*ATS];
    __shared__ __half Vs[64*ATS];

    const int qt = blockIdx.x;
    const int bh = blockIdx.y;
    const int b  = bh / NH_;
    const int h  = bh - b * NH_;

    const int tid  = threadIdx.x;
    const int w    = tid >> 5;
    const int lane = tid & 31;
    const int gid  = lane >> 2;
    const int tig  = lane & 3;

    const size_t hoff = (size_t)h * HD_;
    const __half* Qg = Q + ((size_t)(b*S_ + qt*64)) * D_ + hoff;

    const __half2 sc2 = __floats2half2_rn(0.125f, 0.125f);
    for (int i = tid; i < 512; i += 128) {
        int r = i >> 3, c = (i & 7) * 8;
        uint4 u = *(const uint4*)(Qg + (size_t)r * D_ + c);
        __half2* hp = (__half2*)&u;
#pragma unroll
        for (int t = 0; t < 4; t++) hp[t] = __hmul2(hp[t], sc2);
        *(uint4*)&Qs[r*ATS + c] = u;
    }
    __syncthreads();

    const unsigned qb = (unsigned)__cvta_generic_to_shared(Qs);
    const unsigned kb = (unsigned)__cvta_generic_to_shared(Ks);
    const unsigned vb = (unsigned)__cvta_generic_to_shared(Vs);
    const int lrow = lane & 15;
    const int lcb  = (lane >> 4) * 8;

    unsigned aQ[4][4];
#pragma unroll
    for (int t = 0; t < 4; t++) {
        unsigned ad = qb + (unsigned)(((w*16 + lrow) * ATS + t*16 + lcb) * 2);
        asm volatile("ldmatrix.sync.aligned.m8n8.x4.shared.b16 {%0,%1,%2,%3}, [%4];"
                     : "=r"(aQ[t][0]), "=r"(aQ[t][1]), "=r"(aQ[t][2]), "=r"(aQ[t][3])
                     : "r"(ad));
    }

    float oacc[8][4];
#pragma unroll
    for (int j = 0; j < 8; j++)
#pragma unroll
        for (int c = 0; c < 4; c++) oacc[j][c] = 0.f;
    float m0 = -INFINITY, m1 = -INFINITY, l0 = 0.f, l1 = 0.f;

    const int r0l = w*16 + gid;
    const int r1l = r0l + 8;

    for (int kt = 0; kt <= qt; kt++) {
        __syncthreads();
        const __half* Kg = K + ((size_t)(b*S_ + kt*64)) * D_ + hoff;
        const __half* Vg = V + ((size_t)(b*S_ + kt*64)) * D_ + hoff;
        for (int i = tid; i < 1024; i += 128) {
            int r = (i >> 3) & 63, c = (i & 7) * 8;
            if (i < 512)
                *(uint4*)&Ks[r*ATS + c] = *(const uint4*)(Kg + (size_t)r * D_ + c);
            else
                *(uint4*)&Vs[r*ATS + c] = *(const uint4*)(Vg + (size_t)r * D_ + c);
        }
        __syncthreads();

        float sacc[8][4];
#pragma unroll
        for (int j = 0; j < 8; j++)
#pragma unroll
            for (int c = 0; c < 4; c++) sacc[j][c] = 0.f;

#pragma unroll
        for (int t = 0; t < 4; t++) {
#pragma unroll
            for (int jp = 0; jp < 4; jp++) {
                unsigned bk[4];
                unsigned ad = kb + (unsigned)(((jp*16 + lrow) * ATS + t*16 + lcb) * 2);
                asm volatile("ldmatrix.sync.aligned.m8n8.x4.shared.b16 {%0,%1,%2,%3}, [%4];"
                             : "=r"(bk[0]), "=r"(bk[1]), "=r"(bk[2]), "=r"(bk[3])
                             : "r"(ad));
                asm volatile(
                    "mma.sync.aligned.m16n8k16.row.col.f32.f16.f16.f32 "
                    "{%0,%1,%2,%3},{%4,%5,%6,%7},{%8,%9},{%0,%1,%2,%3};"
                    : "+f"(sacc[2*jp][0]), "+f"(sacc[2*jp][1]),
                      "+f"(sacc[2*jp][2]), "+f"(sacc[2*jp][3])
                    : "r"(aQ[t][0]), "r"(aQ[t][1]), "r"(aQ[t][2]), "r"(aQ[t][3]),
                      "r"(bk[0]), "r"(bk[2]));
                asm volatile(
                    "mma.sync.aligned.m16n8k16.row.col.f32.f16.f16.f32 "
                    "{%0,%1,%2,%3},{%4,%5,%6,%7},{%8,%9},{%0,%1,%2,%3};"
                    : "+f"(sacc[2*jp+1][0]), "+f"(sacc[2*jp+1][1]),
                      "+f"(sacc[2*jp+1][2]), "+f"(sacc[2*jp+1][3])
                    : "r"(aQ[t][0]), "r"(aQ[t][1]), "r"(aQ[t][2]), "r"(aQ[t][3]),
                      "r"(bk[1]), "r"(bk[3]));
            }
        }

        if (kt == qt) {
#pragma unroll
            for (int j = 0; j < 8; j++) {
                int c0 = j*8 + tig*2;
                if (c0     > r0l) sacc[j][0] = -INFINITY;
                if (c0 + 1 > r0l) sacc[j][1] = -INFINITY;
                if (c0     > r1l) sacc[j][2] = -INFINITY;
                if (c0 + 1 > r1l) sacc[j][3] = -INFINITY;
            }
        }

        float mx0 = -INFINITY, mx1 = -INFINITY;
#pragma unroll
        for (int j = 0; j < 8; j++) {
            mx0 = fmaxf(mx0, fmaxf(sacc[j][0], sacc[j][1]));
            mx1 = fmaxf(mx1, fmaxf(sacc[j][2], sacc[j][3]));
        }
#pragma unroll
        for (int o = 1; o <= 2; o <<= 1) {
            mx0 = fmaxf(mx0, __shfl_xor_sync(0xffffffffu, mx0, o));
            mx1 = fmaxf(mx1, __shfl_xor_sync(0xffffffffu, mx1, o));
        }
        float nm0 = fmaxf(m0, mx0), nm1 = fmaxf(m1, mx1);
        float corr0 = __expf(m0 - nm0), corr1 = __expf(m1 - nm1);

        unsigned pa0[8], pa1[8];
        float sum0 = 0.f, sum1 = 0.f;
#pragma unroll
        for (int j = 0; j < 8; j++) {
            float p00 = __expf(sacc[j][0] - nm0);
            float p01 = __expf(sacc[j][1] - nm0);
            float p10 = __expf(sacc[j][2] - nm1);
            float p11 = __expf(sacc[j][3] - nm1);
            sum0 += p00 + p01;
            sum1 += p10 + p11;
            __half2 h0 = __floats2half2_rn(p00, p01);
            __half2 h1 = __floats2half2_rn(p10, p11);
            pa0[j] = *(unsigned*)&h0;
            pa1[j] = *(unsigned*)&h1;
        }
#pragma unroll
        for (int o = 1; o <= 2; o <<= 1) {
            sum0 += __shfl_xor_sync(0xffffffffu, sum0, o);
            sum1 += __shfl_xor_sync(0xffffffffu, sum1, o);
        }
        l0 = l0 * corr0 + sum0;
        l1 = l1 * corr1 + sum1;
        m0 = nm0; m1 = nm1;
#pragma unroll
        for (int j = 0; j < 8; j++) {
            oacc[j][0] *= corr0; oacc[j][1] *= corr0;
            oacc[j][2] *= corr1; oacc[j][3] *= corr1;
        }

#pragma unroll
        for (int kc = 0; kc < 4; kc++) {
            unsigned a0 = pa0[2*kc], a1 = pa1[2*kc], a2 = pa0[2*kc+1], a3 = pa1[2*kc+1];
#pragma unroll
            for (int dp = 0; dp < 4; dp++) {
                unsigned bv[4];
                unsigned ad = vb + (unsigned)(((kc*16 + lrow) * ATS + dp*16 + lcb) * 2);
                asm volatile("ldmatrix.sync.aligned.m8n8.x4.trans.shared.b16 {%0,%1,%2,%3}, [%4];"
                             : "=r"(bv[0]), "=r"(bv[1]), "=r"(bv[2]), "=r"(bv[3])
                             : "r"(ad));
                asm volatile(
                    "mma.sync.aligned.m16n8k16.row.col.f32.f16.f16.f32 "
                    "{%0,%1,%2,%3},{%4,%5,%6,%7},{%8,%9},{%0,%1,%2,%3};"
                    : "+f"(oacc[2*dp][0]), "+f"(oacc[2*dp][1]),
                      "+f"(oacc[2*dp][2]), "+f"(oacc[2*dp][3])
                    : "r"(a0), "r"(a1), "r"(a2), "r"(a3),
                      "r"(bv[0]), "r"(bv[1]));
                asm volatile(
                    "mma.sync.aligned.m16n8k16.row.col.f32.f16.f16.f32 "
                    "{%0,%1,%2,%3},{%4,%5,%6,%7},{%8,%9},{%0,%1,%2,%3};"
                    : "+f"(oacc[2*dp+1][0]), "+f"(oacc[2*dp+1][1]),
                      "+f"(oacc[2*dp+1][2]), "+f"(oacc[2*dp+1][3])
                    : "r"(a0), "r"(a1), "r"(a2), "r"(a3),
                      "r"(bv[2]), "r"(bv[3]));
            }
        }
    }

    float inv0 = 1.f / l0, inv1 = 1.f / l1;
    size_t row0 = ((size_t)(b*S_ + qt*64 + r0l)) * D_ + hoff;
    size_t row1 = ((size_t)(b*S_ + qt*64 + r1l)) * D_ + hoff;
#pragma unroll
    for (int j = 0; j < 8; j++) {
        int c = j*8 + tig*2;
        __half2 o0 = __floats2half2_rn(oacc[j][0]*inv0, oacc[j][1]*inv0);
        __half2 o1 = __floats2half2_rn(oacc[j][2]*inv1, oacc[j][3]*inv1);
        *(__half2*)(O + row0 + c) = o0;
        *(__half2*)(O + row1 + c) = o1;
    }
}

// ---------------- LayerNorm over D (f32 in, f16 out) ------------------------
__global__ void ln_kernel(const float* __restrict__ H,
                          const float* __restrict__ g,
                          const float* __restrict__ bb,
                          __half* __restrict__ out)
{
    int row = blockIdx.x;
    const float* h = H + (size_t)row * D_;
    __shared__ float red[256];
    int tid = threadIdx.x;

    float s = 0.f;
    for (int i = tid; i < D_; i += 256) s += h[i];
    red[tid] = s; __syncthreads();
    for (int o = 128; o; o >>= 1) { if (tid < o) red[tid] += red[tid+o]; __syncthreads(); }
    float mu = red[0] / (float)D_;
    __syncthreads();

    float v = 0.f;
    for (int i = tid; i < D_; i += 256) { float d = h[i] - mu; v += d*d; }
    red[tid] = v; __syncthreads();
    for (int o = 128; o; o >>= 1) { if (tid < o) red[tid] += red[tid+o]; __syncthreads(); }
    float rstd = rsqrtf(red[0] / (float)D_ + 1e-5f);

    __half* o2 = out + (size_t)row * D_;
    for (int i = tid; i < D_; i += 256)
        o2[i] = __float2half((h[i] - mu) * rstd * g[i] + bb[i]);
}

// ---------------- loss from per-block partials -------------------------------
__global__ void loss_partials_kernel(const float* __restrict__ logits,
                                     const int* __restrict__ targets,
                                     const float* __restrict__ pmax,
                                     const float* __restrict__ psum,
                                     float* __restrict__ rowloss)
{
    int row = blockIdx.x;
    int tid = threadIdx.x;
    __shared__ float rm[128], rs[128];

    float m = NEG_, s = 0.f;
    for (int j = tid; j < NBLK_; j += 128) {
        float m2 = pmax[(size_t)row * NBLK_ + j];
        float s2 = psum[(size_t)row * NBLK_ + j];
        float mm = fmaxf(m, m2);
        s = s * __expf(m - mm) + s2 * __expf(m2 - mm);
        m = mm;
    }
    rm[tid] = m; rs[tid] = s; __syncthreads();
    for (int o = 64; o; o >>= 1) {
        if (tid < o) {
            float m1 = rm[tid], s1 = rs[tid];
            float m2 = rm[tid+o], s2 = rs[tid+o];
            float mm = fmaxf(m1, m2);
            rm[tid] = mm;
            rs[tid] = s1 * __expf(m1 - mm) + s2 * __expf(m2 - mm);
        }
        __syncthreads();
    }
    if (tid == 0)
        rowloss[row] = -(logits[(size_t)row * V_ + targets[row]] - rm[0] - logf(rs[0]));
}

__global__ void loss_reduce_kernel(const float* __restrict__ rowloss,
                                   float* __restrict__ out)
{
    __shared__ float red[256];
    int tid = threadIdx.x;
    float s = 0.f;
    for (int i = tid; i < T_; i += 256) s += rowloss[i];
    red[tid] = s; __syncthreads();
    for (int o = 128; o; o >>= 1) { if (tid < o) red[tid] += red[tid+o]; __syncthreads(); }
    if (tid == 0) out[0] = red[0] / (float)T_;
}

// ---------------- launcher ---------------------------------------------------
extern "C" void kernel_launch(void* const* d_in, const int* in_sizes, int n_in,
                              void* d_out, int out_size)
{
    const int*   inputs  = (const int*)  d_in[0];
    const int*   targets = (const int*)  d_in[1];
    const float* wte     = (const float*)d_in[2];
    const float* wq      = (const float*)d_in[3];
    const float* bq      = (const float*)d_in[4];
    const float* wk      = (const float*)d_in[5];
    const float* bk      = (const float*)d_in[6];
    const float* wv      = (const float*)d_in[7];
    const float* bv      = (const float*)d_in[8];
    const float* wo      = (const float*)d_in[9];
    const float* bo      = (const float*)d_in[10];
    const float* w1      = (const float*)d_in[11];
    const float* b1      = (const float*)d_in[12];
    const float* w2      = (const float*)d_in[13];
    const float* b2      = (const float*)d_in[14];
    const float* ln_g    = (const float*)d_in[15];
    const float* ln_b    = (const float*)d_in[16];
    const float* w_out   = (const float*)d_in[17];
    const float* b_out   = (const float*)d_in[18];
    float* out = (float*)d_out;

    __half *x,*q,*k,*v,*ctx,*ao,*h1,*hn,*w;
    float *h2,*rowloss,*pmax,*psum,*bqkv;
    cudaGetSymbolAddress((void**)&x,   g_x);
    cudaGetSymbolAddress((void**)&q,   g_q);
    cudaGetSymbolAddress((void**)&k,   g_k);
    cudaGetSymbolAddress((void**)&v,   g_v);
    cudaGetSymbolAddress((void**)&ctx, g_ctx);
    cudaGetSymbolAddress((void**)&ao,  g_ao);
    cudaGetSymbolAddress((void**)&h1,  g_h1);
    cudaGetSymbolAddress((void**)&h2,  g_h2);
    cudaGetSymbolAddress((void**)&hn,  g_hn);
    cudaGetSymbolAddress((void**)&rowloss, g_rowloss);
    cudaGetSymbolAddress((void**)&pmax, g_pmax);
    cudaGetSymbolAddress((void**)&psum, g_psum);
    cudaGetSymbolAddress((void**)&bqkv, g_bqkv);
    cudaGetSymbolAddress((void**)&w,   g_w);

    const int SMEM_GEMM = 3 * STGB;
    cudaFuncSetAttribute(hgemm_kernel, cudaFuncAttributeMaxDynamicSharedMemorySize, SMEM_GEMM);

    // 0. weight conversion to fp16 scratch
    convert_qkv_kernel<<<(D_*576+255)/256, 256>>>(wq, wk, wv, w+OFF_WQKV);
    concat_bias_kernel<<<(3*D_+255)/256, 256>>>(bq, bk, bv, bqkv);
    convert_w_kernel<<<(D_*D_/4+255)/256, 256>>>(wo, w+OFF_WO, D_*D_/4);
    convert_w_kernel<<<(D_*HID_/4+255)/256, 256>>>(w1, w+OFF_W1, D_*HID_/4);
    convert_w_kernel<<<(HID_*D_/4+255)/256, 256>>>(w2, w+OFF_W2, HID_*D_/4);
    convert_wout_kernel<<<(D_*(VP2_/8)+255)/256, 256>>>(w_out, w+OFF_WOUT);

    // 1. embedding + positional encoding (fp16)
    embed_kernel<<<(T_*D_)/256, 256>>>(inputs, wte, x);

    // 2. fused Q,K,V projection (one GEMM, split epilogue)
    hgemm_kernel<<<dim3(T_/128, 3*D_/128), 256, SMEM_GEMM>>>(
        x, w+OFF_WQKV, bqkv, 0, q, k, v, 0, 0, 0, T_, 3*D_, D_, 3*D_, 0, 2);

    // 3. causal multi-head attention (fp16 tensor cores, fp32 softmax)
    attn_tc_kernel<<<dim3(S_/64, B_*NH_), 128>>>(q, k, v, ctx);

    // 4. output projection -> fp16 ao
    dim3 gDD(T_/128, D_/128);
    hgemm_kernel<<<gDD, 256, SMEM_GEMM>>>(
        ctx, w+OFF_WO, bo, ao, 0,0,0, 0,0,0, T_, D_, D_, D_, 0, 1);

    // 5. FFN (h1 fp16 + relu; h2 fp32 for LN)
    hgemm_kernel<<<dim3(T_/128, HID_/128), 256, SMEM_GEMM>>>(
        ao, w+OFF_W1, b1, h1, 0,0,0, 0,0,0, T_, HID_, D_, HID_, 1, 1);
    hgemm_kernel<<<gDD, 256, SMEM_GEMM>>>(
        h1, w+OFF_W2, b2, h2, 0,0,0, 0,0,0, T_, D_, HID_, D_, 0, 0);

    // 6. LayerNorm (fp32 in -> fp16 hn)
    ln_kernel<<<T_, 256>>>(h2, ln_g, ln_b, hn);

    // 7. vocab projection -> fp32 logits + fused per-block softmax partials
    hgemm_kernel<<<dim3(T_/128, NBLK_), 256, SMEM_GEMM>>>(
        hn, w+OFF_WOUT, b_out, out, 0,0,0, pmax, psum, NBLK_,
        T_, V_, D_, VP2_, 0, 3);

    // 8. cross-entropy loss from partials
    loss_partials_kernel<<<T_, 128>>>(out, targets, pmax, psum, rowloss);
    if (out_size > T_ * V_)
        loss_reduce_kernel<<<1, 256>>>(rowloss, out + (size_t)T_ * V_);
}

// round 11
// speedup vs baseline: 8.0624x; 1.0120x over previous
#include <cuda_runtime.h>
#include <cuda_fp16.h>
#include <math.h>

#define V_   50257
#define VP2_ 50304            // V padded to multiple of 128 (half scratch row stride)
#define NBLK_ 393             // vocab n-tiles of 128
#define D_   768
#define S_   2048
#define B_   2
#define HID_ 2048
#define NH_  12
#define HD_  64
#define T_   (B_*S_)   // 4096 tokens
#define NEG_ -1e30f

// ---------------- scratch (device globals; no allocation allowed) ----------
__device__ __half g_x  [T_*D_];
__device__ __half g_q  [T_*D_];
__device__ __half g_k  [T_*D_];
__device__ __half g_v  [T_*D_];
__device__ __half g_ctx[T_*D_];
__device__ __half g_ao [T_*D_];
__device__ __half g_h1 [T_*HID_];
__device__ float  g_h2 [T_*D_];
__device__ __half g_hn [T_*D_];
__device__ float  g_rowloss[T_];
__device__ float  g_pmax[T_*NBLK_];
__device__ float  g_psum[T_*NBLK_];
__device__ float  g_bqkv[3*D_];
// fp16 weight scratch: wqkv | wo | w1 | w2 | w_out(padded)
#define OFF_WQKV 0
#define OFF_WO   (OFF_WQKV + D_*3*D_)
#define OFF_W1   (OFF_WO + D_*D_)
#define OFF_W2   (OFF_W1 + D_*HID_)
#define OFF_WOUT (OFF_W2 + HID_*D_)
#define W_TOTAL  (OFF_WOUT + D_*VP2_ + 64)
__device__ __half g_w[W_TOTAL];

// ---------------- weight conversion kernels ---------------------------------
__global__ void convert_w_kernel(const float* __restrict__ in,
                                 __half* __restrict__ out, int n4)
{
    int i = blockIdx.x * blockDim.x + threadIdx.x;
    if (i >= n4) return;
    float4 v = ((const float4*)in)[i];
    __half2 h0 = __floats2half2_rn(v.x, v.y);
    __half2 h1 = __floats2half2_rn(v.z, v.w);
    ((__half2*)out)[i*2+0] = h0;
    ((__half2*)out)[i*2+1] = h1;
}

// wq/wk/wv [D,768] -> interleaved [D, 2304] fp16
__global__ void convert_qkv_kernel(const float* __restrict__ wq,
                                   const float* __restrict__ wk,
                                   const float* __restrict__ wv,
                                   __half* __restrict__ out)
{
    int idx = blockIdx.x * blockDim.x + threadIdx.x;  // over D_*576
    if (idx >= D_*576) return;
    int r = idx / 576, rem = idx - r * 576;
    int sel = rem / 192, c = (rem - sel * 192) * 4;
    const float* src = (sel == 0 ? wq : sel == 1 ? wk : wv) + (size_t)r * D_ + c;
    float4 v = *(const float4*)src;
    __half tmp[4] = { __float2half(v.x), __float2half(v.y),
                      __float2half(v.z), __float2half(v.w) };
    *(uint2*)(out + (size_t)r * (3*D_) + sel * D_ + c) = *(const uint2*)tmp;
}

__global__ void concat_bias_kernel(const float* __restrict__ bq,
                                   const float* __restrict__ bk,
                                   const float* __restrict__ bv,
                                   float* __restrict__ out)
{
    int i = blockIdx.x * blockDim.x + threadIdx.x;
    if (i >= 3*D_) return;
    int sel = i / D_, c = i - sel * D_;
    out[i] = (sel == 0 ? bq : sel == 1 ? bk : bv)[c];
}

// w_out: [D_, V_] f32 -> padded [D_, VP2_] f16, zero pad.
__global__ void convert_wout_kernel(const float* __restrict__ in,
                                    __half* __restrict__ out)
{
    const int row8 = VP2_ / 8;
    int j = blockIdx.x * blockDim.x + threadIdx.x;
    if (j >= D_ * row8) return;
    int r  = j / row8;
    int c  = (j - r * row8) * 8;
    const float* src = in + (size_t)r * V_ + c;
    __half tmp[8];
#pragma unroll
    for (int e = 0; e < 8; e++)
        tmp[e] = (c + e < V_) ? __float2half(__ldg(src + e)) : __half(0.f);
    ((uint4*)out)[j] = *(const uint4*)tmp;
}

// ---------------- embedding + sinusoidal positional encoding ---------------
__global__ void embed_kernel(const int* __restrict__ inputs,
                             const float* __restrict__ wte,
                             __half* __restrict__ x)
{
    int idx = blockIdx.x * blockDim.x + threadIdx.x;
    if (idx >= T_*D_) return;
    int t = idx / D_;
    int d = idx - t * D_;
    int s = t & (S_-1);
    int tok = inputs[t];
    int i2 = (d >> 1) * 2;
    float div = expf((float)(-i2) * (logf(10000.0f) / (float)D_));
    float ang = (float)s * div;
    float pe = (d & 1) ? cosf(ang) : sinf(ang);
    x[idx] = __float2half(wte[(size_t)tok * D_ + d] + pe);
}

// ---------------- fp16 tensor-core GEMM, 3-stage cp.async, BK=32 -------------
// modes: 0 = f32 out, 1 = f16 out, 2 = qkv split f16 out, 3 = f32 out + loss partials
#define AST2 40
#define BST2 136
#define ASTB (128*AST2*2)
#define STGB (ASTB + 32*BST2*2)

__global__ __launch_bounds__(256, 2)
void hgemm_kernel(const __half* __restrict__ A, const __half* __restrict__ W,
                  const float* __restrict__ bias, void* __restrict__ Cout,
                  __half* __restrict__ dq, __half* __restrict__ dk, __half* __restrict__ dv,
                  float* __restrict__ pmax, float* __restrict__ psum, int nblk,
                  int M, int N, int K, int ldW, int relu, int mode)
{
    extern __shared__ char smc[];
    const int tid  = threadIdx.x;
    const int warp = tid >> 5;
    const int lane = tid & 31;
    const int gid  = lane >> 2;
    const int tig  = lane & 3;
    const int wm   = warp >> 2;
    const int wn   = warp & 3;
    const int m0 = blockIdx.x * 128;
    const int n0 = blockIdx.y * 128;
    const unsigned smem0 = (unsigned)__cvta_generic_to_shared(smc);

    float acc[4][4][4];
#pragma unroll
    for (int i = 0; i < 4; i++)
#pragma unroll
        for (int j = 0; j < 4; j++)
#pragma unroll
            for (int c = 0; c < 4; c++) acc[i][j][c] = 0.f;

    const int nk = K >> 5;

    auto load_stage = [&](int i) {
        unsigned sa = smem0 + (i % 3) * STGB;
        unsigned sb = sa + ASTB;
        const __half* Ab = A + (size_t)m0 * K + i * 32;
        const __half* Bb = W + (size_t)(i * 32) * ldW + n0;
#pragma unroll
        for (int t = 0; t < 2; t++) {
            int slot = t * 256 + tid;
            int r = slot >> 2, c = (slot & 3) * 8;
            asm volatile("cp.async.cg.shared.global [%0], [%1], 16;"
                         :: "r"(sa + (r * AST2 + c) * 2), "l"(Ab + (size_t)r * K + c));
        }
#pragma unroll
        for (int t = 0; t < 2; t++) {
            int slot = t * 256 + tid;
            int r = slot >> 4, c = (slot & 15) * 8;
            asm volatile("cp.async.cg.shared.global [%0], [%1], 16;"
                         :: "r"(sb + (r * BST2 + c) * 2), "l"(Bb + (size_t)r * ldW + c));
        }
        asm volatile("cp.async.commit_group;");
    };

    load_stage(0);
    load_stage(1);
    asm volatile("cp.async.wait_group 1;");
    __syncthreads();

    const int arow = lane & 15;
    const int acol = (lane >> 4) * 8;

    for (int i = 0; i < nk; i++) {
        unsigned sa = smem0 + (i % 3) * STGB;
        unsigned sb = sa + ASTB;

        if (i + 2 < nk) load_stage(i + 2);
        else            asm volatile("cp.async.commit_group;");

#pragma unroll
        for (int kk = 0; kk < 32; kk += 16) {
            unsigned af[4][4], bf[4][2];
#pragma unroll
            for (int mi = 0; mi < 4; mi++) {
                unsigned ad = sa + ((wm * 64 + mi * 16 + arow) * AST2 + kk + acol) * 2;
                asm volatile("ldmatrix.sync.aligned.m8n8.x4.shared.b16 {%0,%1,%2,%3}, [%4];"
                             : "=r"(af[mi][0]), "=r"(af[mi][1]),
                               "=r"(af[mi][2]), "=r"(af[mi][3]) : "r"(ad));
            }
            // B fragments via x4.trans: one ldmatrix covers 16 k-rows x 16 n-cols
            // (two ni fragments) — halves LDSM pressure vs 4x x2.trans.
#pragma unroll
            for (int nh = 0; nh < 2; nh++) {
                unsigned bd = sb + ((kk + arow) * BST2 + wn * 32 + nh * 16 + acol) * 2;
                asm volatile("ldmatrix.sync.aligned.m8n8.x4.trans.shared.b16 {%0,%1,%2,%3}, [%4];"
                             : "=r"(bf[2*nh][0]), "=r"(bf[2*nh][1]),
                               "=r"(bf[2*nh+1][0]), "=r"(bf[2*nh+1][1]) : "r"(bd));
            }
#pragma unroll
            for (int mi = 0; mi < 4; mi++)
#pragma unroll
                for (int ni = 0; ni < 4; ni++) {
                    asm volatile(
                        "mma.sync.aligned.m16n8k16.row.col.f32.f16.f16.f32 "
                        "{%0,%1,%2,%3},{%4,%5,%6,%7},{%8,%9},{%0,%1,%2,%3};"
                        : "+f"(acc[mi][ni][0]), "+f"(acc[mi][ni][1]),
                          "+f"(acc[mi][ni][2]), "+f"(acc[mi][ni][3])
                        : "r"(af[mi][0]), "r"(af[mi][1]),
                          "r"(af[mi][2]), "r"(af[mi][3]),
                          "r"(bf[ni][0]), "r"(bf[ni][1]));
                }
        }

        asm volatile("cp.async.wait_group 1;");
        __syncthreads();
    }

    // qkv destination select (each 128-col tile lies inside one segment)
    __half* qdst = 0; int qcol0 = 0;
    if (mode == 2) {
        int sel = n0 / D_;
        qdst  = (sel == 0 ? dq : sel == 1 ? dk : dv);
        qcol0 = n0 - sel * D_;
    }

    float* red = (float*)smc;   // [128][4][2] reuse after pipeline (4KB)

#pragma unroll
    for (int mi = 0; mi < 4; mi++) {
        int rl = wm * 64 + mi * 16 + gid;     // local row (half 0); +8 for half 1
        int r  = m0 + rl;
        float mA = NEG_, sA = 0.f, mB = NEG_, sB = 0.f;
#pragma unroll
        for (int ni = 0; ni < 4; ni++) {
            int c = n0 + wn * 32 + ni * 8 + tig * 2;
#pragma unroll
            for (int hh = 0; hh < 2; hh++) {
                int cc = c + hh;
                if (cc < N) {
                    float v0 = acc[mi][ni][0 + hh] + bias[cc];
                    float v2 = acc[mi][ni][2 + hh] + bias[cc];
                    if (relu) { v0 = fmaxf(v0, 0.f); v2 = fmaxf(v2, 0.f); }
                    if (mode == 1) {
                        ((__half*)Cout)[(size_t)r * N + cc]       = __float2half(v0);
                        ((__half*)Cout)[(size_t)(r + 8) * N + cc] = __float2half(v2);
                    } else if (mode == 2) {
                        int lc = qcol0 + (cc - n0);
                        qdst[(size_t)r * D_ + lc]       = __float2half(v0);
                        qdst[(size_t)(r + 8) * D_ + lc] = __float2half(v2);
                    } else {
                        ((float*)Cout)[(size_t)r * N + cc]       = v0;
                        ((float*)Cout)[(size_t)(r + 8) * N + cc] = v2;
                        if (mode == 3) {
                            if (v0 > mA) { sA = sA * __expf(mA - v0) + 1.f; mA = v0; }
                            else         { sA += __expf(v0 - mA); }
                            if (v2 > mB) { sB = sB * __expf(mB - v2) + 1.f; mB = v2; }
                            else         { sB += __expf(v2 - mB); }
                        }
                    }
                }
            }
        }
        if (mode == 3) {
#pragma unroll
            for (int o = 1; o <= 2; o <<= 1) {
                float m2 = __shfl_xor_sync(0xffffffffu, mA, o);
                float s2 = __shfl_xor_sync(0xffffffffu, sA, o);
                float mm = fmaxf(mA, m2);
                sA = sA * __expf(mA - mm) + s2 * __expf(m2 - mm);
                mA = mm;
                m2 = __shfl_xor_sync(0xffffffffu, mB, o);
                s2 = __shfl_xor_sync(0xffffffffu, sB, o);
                mm = fmaxf(mB, m2);
                sB = sB * __expf(mB - mm) + s2 * __expf(m2 - mm);
                mB = mm;
            }
            if (tig == 0) {
                red[((rl    ) * 4 + wn) * 2 + 0] = mA;
                red[((rl    ) * 4 + wn) * 2 + 1] = sA;
                red[((rl + 8) * 4 + wn) * 2 + 0] = mB;
                red[((rl + 8) * 4 + wn) * 2 + 1] = sB;
            }
        }
    }

    if (mode == 3) {
        __syncthreads();
        if (tid < 128) {
            float m = NEG_, s = 0.f;
#pragma unroll
            for (int wnn = 0; wnn < 4; wnn++) {
                float m2 = red[(tid * 4 + wnn) * 2 + 0];
                float s2 = red[(tid * 4 + wnn) * 2 + 1];
                float mm = fmaxf(m, m2);
                s = s * __expf(m - mm) + s2 * __expf(m2 - mm);
                m = mm;
            }
            pmax[(size_t)(m0 + tid) * nblk + blockIdx.y] = m;
            psum[(size_t)(m0 + tid) * nblk + blockIdx.y] = s;
        }
    }
}

// ---------------- tensor-core flash attention (FA2 layout) -------------------
#define ATS 72

__global__ __launch_bounds__(128)
void attn_tc_kernel(const __half* __restrict__ Q, const __half* __restrict__ K,
                    const __half* __restrict__ V, __half* __restrict__ O)
{
    __shared__ __half Qs[64*ATS];
    __shared__ __half Ks[64*ATS];
    __shared__ __half Vs[64*ATS];

    const int qt = blockIdx.x;
    const int bh = blockIdx.y;
    const int b  = bh / NH_;
    const int h  = bh - b * NH_;

    const int tid  = threadIdx.x;
    const int w    = tid >> 5;
    const int lane = tid & 31;
    const int gid  = lane >> 2;
    const int tig  = lane & 3;

    const size_t hoff = (size_t)h * HD_;
    const __half* Qg = Q + ((size_t)(b*S_ + qt*64)) * D_ + hoff;

    const __half2 sc2 = __floats2half2_rn(0.125f, 0.125f);
    for (int i = tid; i < 512; i += 128) {
        int r = i >> 3, c = (i & 7) * 8;
        uint4 u = *(const uint4*)(Qg + (size_t)r * D_ + c);
        __half2* hp = (__half2*)&u;
#pragma unroll
        for (int t = 0; t < 4; t++) hp[t] = __hmul2(hp[t], sc2);
        *(uint4*)&Qs[r*ATS + c] = u;
    }
    __syncthreads();

    const unsigned qb = (unsigned)__cvta_generic_to_shared(Qs);
    const unsigned kb = (unsigned)__cvta_generic_to_shared(Ks);
    const unsigned vb = (unsigned)__cvta_generic_to_shared(Vs);
    const int lrow = lane & 15;
    const int lcb  = (lane >> 4) * 8;

    unsigned aQ[4][4];
#pragma unroll
    for (int t = 0; t < 4; t++) {
        unsigned ad = qb + (unsigned)(((w*16 + lrow) * ATS + t*16 + lcb) * 2);
        asm volatile("ldmatrix.sync.aligned.m8n8.x4.shared.b16 {%0,%1,%2,%3}, [%4];"
                     : "=r"(aQ[t][0]), "=r"(aQ[t][1]), "=r"(aQ[t][2]), "=r"(aQ[t][3])
                     : "r"(ad));
    }

    float oacc[8][4];
#pragma unroll
    for (int j = 0; j < 8; j++)
#pragma unroll
        for (int c = 0; c < 4; c++) oacc[j][c] = 0.f;
    float m0 = -INFINITY, m1 = -INFINITY, l0 = 0.f, l1 = 0.f;

    const int r0l = w*16 + gid;
    const int r1l = r0l + 8;

    for (int kt = 0; kt <= qt; kt++) {
        __syncthreads();
        const __half* Kg = K + ((size_t)(b*S_ + kt*64)) * D_ + hoff;
        const __half* Vg = V + ((size_t)(b*S_ + kt*64)) * D_ + hoff;
        for (int i = tid; i < 1024; i += 128) {
            int r = (i >> 3) & 63, c = (i & 7) * 8;
            if (i < 512)
                *(uint4*)&Ks[r*ATS + c] = *(const uint4*)(Kg + (size_t)r * D_ + c);
            else
                *(uint4*)&Vs[r*ATS + c] = *(const uint4*)(Vg + (size_t)r * D_ + c);
        }
        __syncthreads();

        float sacc[8][4];
#pragma unroll
        for (int j = 0; j < 8; j++)
#pragma unroll
            for (int c = 0; c < 4; c++) sacc[j][c] = 0.f;

#pragma unroll
        for (int t = 0; t < 4; t++) {
#pragma unroll
            for (int jp = 0; jp < 4; jp++) {
                unsigned bk[4];
                unsigned ad = kb + (unsigned)(((jp*16 + lrow) * ATS + t*16 + lcb) * 2);
                asm volatile("ldmatrix.sync.aligned.m8n8.x4.shared.b16 {%0,%1,%2,%3}, [%4];"
                             : "=r"(bk[0]), "=r"(bk[1]), "=r"(bk[2]), "=r"(bk[3])
                             : "r"(ad));
                asm volatile(
                    "mma.sync.aligned.m16n8k16.row.col.f32.f16.f16.f32 "
                    "{%0,%1,%2,%3},{%4,%5,%6,%7},{%8,%9},{%0,%1,%2,%3};"
                    : "+f"(sacc[2*jp][0]), "+f"(sacc[2*jp][1]),
                      "+f"(sacc[2*jp][2]), "+f"(sacc[2*jp][3])
                    : "r"(aQ[t][0]), "r"(aQ[t][1]), "r"(aQ[t][2]), "r"(aQ[t][3]),
                      "r"(bk[0]), "r"(bk[2]));
                asm volatile(
                    "mma.sync.aligned.m16n8k16.row.col.f32.f16.f16.f32 "
                    "{%0,%1,%2,%3},{%4,%5,%6,%7},{%8,%9},{%0,%1,%2,%3};"
                    : "+f"(sacc[2*jp+1][0]), "+f"(sacc[2*jp+1][1]),
                      "+f"(sacc[2*jp+1][2]), "+f"(sacc[2*jp+1][3])
                    : "r"(aQ[t][0]), "r"(aQ[t][1]), "r"(aQ[t][2]), "r"(aQ[t][3]),
                      "r"(bk[1]), "r"(bk[3]));
            }
        }

        if (kt == qt) {
#pragma unroll
            for (int j = 0; j < 8; j++) {
                int c0 = j*8 + tig*2;
                if (c0     > r0l) sacc[j][0] = -INFINITY;
                if (c0 + 1 > r0l) sacc[j][1] = -INFINITY;
                if (c0     > r1l) sacc[j][2] = -INFINITY;
                if (c0 + 1 > r1l) sacc[j][3] = -INFINITY;
            }
        }

        float mx0 = -INFINITY, mx1 = -INFINITY;
#pragma unroll
        for (int j = 0; j < 8; j++) {
            mx0 = fmaxf(mx0, fmaxf(sacc[j][0], sacc[j][1]));
            mx1 = fmaxf(mx1, fmaxf(sacc[j][2], sacc[j][3]));
        }
#pragma unroll
        for (int o = 1; o <= 2; o <<= 1) {
            mx0 = fmaxf(mx0, __shfl_xor_sync(0xffffffffu, mx0, o));
            mx1 = fmaxf(mx1, __shfl_xor_sync(0xffffffffu, mx1, o));
        }
        float nm0 = fmaxf(m0, mx0), nm1 = fmaxf(m1, mx1);
        float corr0 = __expf(m0 - nm0), corr1 = __expf(m1 - nm1);

        unsigned pa0[8], pa1[8];
        float sum0 = 0.f, sum1 = 0.f;
#pragma unroll
        for (int j = 0; j < 8; j++) {
            float p00 = __expf(sacc[j][0] - nm0);
            float p01 = __expf(sacc[j][1] - nm0);
            float p10 = __expf(sacc[j][2] - nm1);
            float p11 = __expf(sacc[j][3] - nm1);
            sum0 += p00 + p01;
            sum1 += p10 + p11;
            __half2 h0 = __floats2half2_rn(p00, p01);
            __half2 h1 = __floats2half2_rn(p10, p11);
            pa0[j] = *(unsigned*)&h0;
            pa1[j] = *(unsigned*)&h1;
        }
#pragma unroll
        for (int o = 1; o <= 2; o <<= 1) {
            sum0 += __shfl_xor_sync(0xffffffffu, sum0, o);
            sum1 += __shfl_xor_sync(0xffffffffu, sum1, o);
        }
        l0 = l0 * corr0 + sum0;
        l1 = l1 * corr1 + sum1;
        m0 = nm0; m1 = nm1;
#pragma unroll
        for (int j = 0; j < 8; j++) {
            oacc[j][0] *= corr0; oacc[j][1] *= corr0;
            oacc[j][2] *= corr1; oacc[j][3] *= corr1;
        }

#pragma unroll
        for (int kc = 0; kc < 4; kc++) {
            unsigned a0 = pa0[2*kc], a1 = pa1[2*kc], a2 = pa0[2*kc+1], a3 = pa1[2*kc+1];
#pragma unroll
            for (int dp = 0; dp < 4; dp++) {
                unsigned bv[4];
                unsigned ad = vb + (unsigned)(((kc*16 + lrow) * ATS + dp*16 + lcb) * 2);
                asm volatile("ldmatrix.sync.aligned.m8n8.x4.trans.shared.b16 {%0,%1,%2,%3}, [%4];"
                             : "=r"(bv[0]), "=r"(bv[1]), "=r"(bv[2]), "=r"(bv[3])
                             : "r"(ad));
                asm volatile(
                    "mma.sync.aligned.m16n8k16.row.col.f32.f16.f16.f32 "
                    "{%0,%1,%2,%3},{%4,%5,%6,%7},{%8,%9},{%0,%1,%2,%3};"
                    : "+f"(oacc[2*dp][0]), "+f"(oacc[2*dp][1]),
                      "+f"(oacc[2*dp][2]), "+f"(oacc[2*dp][3])
                    : "r"(a0), "r"(a1), "r"(a2), "r"(a3),
                      "r"(bv[0]), "r"(bv[1]));
                asm volatile(
                    "mma.sync.aligned.m16n8k16.row.col.f32.f16.f16.f32 "
                    "{%0,%1,%2,%3},{%4,%5,%6,%7},{%8,%9},{%0,%1,%2,%3};"
                    : "+f"(oacc[2*dp+1][0]), "+f"(oacc[2*dp+1][1]),
                      "+f"(oacc[2*dp+1][2]), "+f"(oacc[2*dp+1][3])
                    : "r"(a0), "r"(a1), "r"(a2), "r"(a3),
                      "r"(bv[2]), "r"(bv[3]));
            }
        }
    }

    float inv0 = 1.f / l0, inv1 = 1.f / l1;
    size_t row0 = ((size_t)(b*S_ + qt*64 + r0l)) * D_ + hoff;
    size_t row1 = ((size_t)(b*S_ + qt*64 + r1l)) * D_ + hoff;
#pragma unroll
    for (int j = 0; j < 8; j++) {
        int c = j*8 + tig*2;
        __half2 o0 = __floats2half2_rn(oacc[j][0]*inv0, oacc[j][1]*inv0);
        __half2 o1 = __floats2half2_rn(oacc[j][2]*inv1, oacc[j][3]*inv1);
        *(__half2*)(O + row0 + c) = o0;
        *(__half2*)(O + row1 + c) = o1;
    }
}

// ---------------- LayerNorm over D (f32 in, f16 out) ------------------------
__global__ void ln_kernel(const float* __restrict__ H,
                          const float* __restrict__ g,
                          const float* __restrict__ bb,
                          __half* __restrict__ out)
{
    int row = blockIdx.x;
    const float* h = H + (size_t)row * D_;
    __shared__ float red[256];
    int tid = threadIdx.x;

    float s = 0.f;
    for (int i = tid; i < D_; i += 256) s += h[i];
    red[tid] = s; __syncthreads();
    for (int o = 128; o; o >>= 1) { if (tid < o) red[tid] += red[tid+o]; __syncthreads(); }
    float mu = red[0] / (float)D_;
    __syncthreads();

    float v = 0.f;
    for (int i = tid; i < D_; i += 256) { float d = h[i] - mu; v += d*d; }
    red[tid] = v; __syncthreads();
    for (int o = 128; o; o >>= 1) { if (tid < o) red[tid] += red[tid+o]; __syncthreads(); }
    float rstd = rsqrtf(red[0] / (float)D_ + 1e-5f);

    __half* o2 = out + (size_t)row * D_;
    for (int i = tid; i < D_; i += 256)
        o2[i] = __float2half((h[i] - mu) * rstd * g[i] + bb[i]);
}

// ---------------- loss from per-block partials -------------------------------
__global__ void loss_partials_kernel(const float* __restrict__ logits,
                                     const int* __restrict__ targets,
                                     const float* __restrict__ pmax,
                                     const float* __restrict__ psum,
                                     float* __restrict__ rowloss)
{
    int row = blockIdx.x;
    int tid = threadIdx.x;
    __shared__ float rm[128], rs[128];

    float m = NEG_, s = 0.f;
    for (int j = tid; j < NBLK_; j += 128) {
        float m2 = pmax[(size_t)row * NBLK_ + j];
        float s2 = psum[(size_t)row * NBLK_ + j];
        float mm = fmaxf(m, m2);
        s = s * __expf(m - mm) + s2 * __expf(m2 - mm);
        m = mm;
    }
    rm[tid] = m; rs[tid] = s; __syncthreads();
    for (int o = 64; o; o >>= 1) {
        if (tid < o) {
            float m1 = rm[tid], s1 = rs[tid];
            float m2 = rm[tid+o], s2 = rs[tid+o];
            float mm = fmaxf(m1, m2);
            rm[tid] = mm;
            rs[tid] = s1 * __expf(m1 - mm) + s2 * __expf(m2 - mm);
        }
        __syncthreads();
    }
    if (tid == 0)
        rowloss[row] = -(logits[(size_t)row * V_ + targets[row]] - rm[0] - logf(rs[0]));
}

__global__ void loss_reduce_kernel(const float* __restrict__ rowloss,
                                   float* __restrict__ out)
{
    __shared__ float red[256];
    int tid = threadIdx.x;
    float s = 0.f;
    for (int i = tid; i < T_; i += 256) s += rowloss[i];
    red[tid] = s; __syncthreads();
    for (int o = 128; o; o >>= 1) { if (tid < o) red[tid] += red[tid+o]; __syncthreads(); }
    if (tid == 0) out[0] = red[0] / (float)T_;
}

// ---------------- launcher ---------------------------------------------------
extern "C" void kernel_launch(void* const* d_in, const int* in_sizes, int n_in,
                              void* d_out, int out_size)
{
    const int*   inputs  = (const int*)  d_in[0];
    const int*   targets = (const int*)  d_in[1];
    const float* wte     = (const float*)d_in[2];
    const float* wq      = (const float*)d_in[3];
    const float* bq      = (const float*)d_in[4];
    const float* wk      = (const float*)d_in[5];
    const float* bk      = (const float*)d_in[6];
    const float* wv      = (const float*)d_in[7];
    const float* bv      = (const float*)d_in[8];
    const float* wo      = (const float*)d_in[9];
    const float* bo      = (const float*)d_in[10];
    const float* w1      = (const float*)d_in[11];
    const float* b1      = (const float*)d_in[12];
    const float* w2      = (const float*)d_in[13];
    const float* b2      = (const float*)d_in[14];
    const float* ln_g    = (const float*)d_in[15];
    const float* ln_b    = (const float*)d_in[16];
    const float* w_out   = (const float*)d_in[17];
    const float* b_out   = (const float*)d_in[18];
    float* out = (float*)d_out;

    __half *x,*q,*k,*v,*ctx,*ao,*h1,*hn,*w;
    float *h2,*rowloss,*pmax,*psum,*bqkv;
    cudaGetSymbolAddress((void**)&x,   g_x);
    cudaGetSymbolAddress((void**)&q,   g_q);
    cudaGetSymbolAddress((void**)&k,   g_k);
    cudaGetSymbolAddress((void**)&v,   g_v);
    cudaGetSymbolAddress((void**)&ctx, g_ctx);
    cudaGetSymbolAddress((void**)&ao,  g_ao);
    cudaGetSymbolAddress((void**)&h1,  g_h1);
    cudaGetSymbolAddress((void**)&h2,  g_h2);
    cudaGetSymbolAddress((void**)&hn,  g_hn);
    cudaGetSymbolAddress((void**)&rowloss, g_rowloss);
    cudaGetSymbolAddress((void**)&pmax, g_pmax);
    cudaGetSymbolAddress((void**)&psum, g_psum);
    cudaGetSymbolAddress((void**)&bqkv, g_bqkv);
    cudaGetSymbolAddress((void**)&w,   g_w);

    const int SMEM_GEMM = 3 * STGB;
    cudaFuncSetAttribute(hgemm_kernel, cudaFuncAttributeMaxDynamicSharedMemorySize, SMEM_GEMM);

    // 0. weight conversion to fp16 scratch
    convert_qkv_kernel<<<(D_*576+255)/256, 256>>>(wq, wk, wv, w+OFF_WQKV);
    concat_bias_kernel<<<(3*D_+255)/256, 256>>>(bq, bk, bv, bqkv);
    convert_w_kernel<<<(D_*D_/4+255)/256, 256>>>(wo, w+OFF_WO, D_*D_/4);
    convert_w_kernel<<<(D_*HID_/4+255)/256, 256>>>(w1, w+OFF_W1, D_*HID_/4);
    convert_w_kernel<<<(HID_*D_/4+255)/256, 256>>>(w2, w+OFF_W2, HID_*D_/4);
    convert_wout_kernel<<<(D_*(VP2_/8)+255)/256, 256>>>(w_out, w+OFF_WOUT);

    // 1. embedding + positional encoding (fp16)
    embed_kernel<<<(T_*D_)/256, 256>>>(inputs, wte, x);

    // 2. fused Q,K,V projection (one GEMM, split epilogue)
    hgemm_kernel<<<dim3(T_/128, 3*D_/128), 256, SMEM_GEMM>>>(
        x, w+OFF_WQKV, bqkv, 0, q, k, v, 0, 0, 0, T_, 3*D_, D_, 3*D_, 0, 2);

    // 3. causal multi-head attention (fp16 tensor cores, fp32 softmax)
    attn_tc_kernel<<<dim3(S_/64, B_*NH_), 128>>>(q, k, v, ctx);

    // 4. output projection -> fp16 ao
    dim3 gDD(T_/128, D_/128);
    hgemm_kernel<<<gDD, 256, SMEM_GEMM>>>(
        ctx, w+OFF_WO, bo, ao, 0,0,0, 0,0,0, T_, D_, D_, D_, 0, 1);

    // 5. FFN (h1 fp16 + relu; h2 fp32 for LN)
    hgemm_kernel<<<dim3(T_/128, HID_/128), 256, SMEM_GEMM>>>(
        ao, w+OFF_W1, b1, h1, 0,0,0, 0,0,0, T_, HID_, D_, HID_, 1, 1);
    hgemm_kernel<<<gDD, 256, SMEM_GEMM>>>(
        h1, w+OFF_W2, b2, h2, 0,0,0, 0,0,0, T_, D_, HID_, D_, 0, 0);

    // 6. LayerNorm (fp32 in -> fp16 hn)
    ln_kernel<<<T_, 256>>>(h2, ln_g, ln_b, hn);

    // 7. vocab projection -> fp32 logits + fused per-block softmax partials
    hgemm_kernel<<<dim3(T_/128, NBLK_), 256, SMEM_GEMM>>>(
        hn, w+OFF_WOUT, b_out, out, 0,0,0, pmax, psum, NBLK_,
        T_, V_, D_, VP2_, 0, 3);

    // 8. cross-entropy loss from partials
    loss_partials_kernel<<<T_, 128>>>(out, targets, pmax, psum, rowloss);
    if (out_size > T_ * V_)
        loss_reduce_kernel<<<1, 256>>>(rowloss, out + (size_t)T_ * V_);
}

// round 12
// speedup vs baseline: 8.2715x; 1.0259x over previous
#include <cuda_runtime.h>
#include <cuda_fp16.h>
#include <math.h>

#define V_   50257
#define VP2_ 50304            // V padded to multiple of 128 (half scratch row stride)
#define NBLK_ 393             // vocab n-tiles of 128
#define D_   768
#define S_   2048
#define B_   2
#define HID_ 2048
#define NH_  12
#define HD_  64
#define T_   (B_*S_)   // 4096 tokens
#define NEG_ -1e30f

// ---------------- scratch (device globals; no allocation allowed) ----------
__device__ __half g_x  [T_*D_];
__device__ __half g_q  [T_*D_];
__device__ __half g_k  [T_*D_];
__device__ __half g_v  [T_*D_];
__device__ __half g_ctx[T_*D_];
__device__ __half g_ao [T_*D_];
__device__ __half g_h1 [T_*HID_];
__device__ float  g_h2 [T_*D_];
__device__ __half g_hn [T_*D_];
__device__ float  g_rowloss[T_];
__device__ float  g_pmax[T_*NBLK_];
__device__ float  g_psum[T_*NBLK_];
__device__ float  g_bqkv[3*D_];
// fp16 weight scratch: wqkv | wo | w1 | w2 | w_out(padded)  — CONTIGUOUS regions
#define OFF_WQKV 0
#define OFF_WO   (OFF_WQKV + D_*3*D_)
#define OFF_W1   (OFF_WO + D_*D_)
#define OFF_W2   (OFF_W1 + D_*HID_)
#define OFF_WOUT (OFF_W2 + HID_*D_)
#define W_TOTAL  (OFF_WOUT + D_*VP2_ + 64)
__device__ __half g_w[W_TOTAL];

// ---------------- fused weight conversion (ONE launch) -----------------------
// Regions (8-half chunks), output offset = j*8 into g_w for all weight regions:
//   R0 wqkv interleave | R1 wo | R2 w1 | R3 w2 | R4 w_out (padded) | R5 bias concat
#define CN0 221184L                      // D*3D/8
#define CN1 (CN0 + 73728L)               // + D*D/8
#define CN2 (CN1 + 196608L)              // + D*HID/8
#define CN3 (CN2 + 196608L)              // + HID*D/8
#define CN4 (CN3 + 4829184L)             // + D*VP2/8
#define CN5 (CN4 + 288L)                 // + 3*D/8 (bias, fp32)

__device__ __forceinline__ void cvt8(const float* __restrict__ src, __half* dst) {
    float4 a = *(const float4*)src;
    float4 b = *(const float4*)(src + 4);
    __half h[8] = { __float2half(a.x), __float2half(a.y), __float2half(a.z), __float2half(a.w),
                    __float2half(b.x), __float2half(b.y), __float2half(b.z), __float2half(b.w) };
    *(uint4*)dst = *(const uint4*)h;
}

__global__ void convert_all_kernel(const float* __restrict__ wq, const float* __restrict__ wk,
                                   const float* __restrict__ wv, const float* __restrict__ wo,
                                   const float* __restrict__ w1, const float* __restrict__ w2,
                                   const float* __restrict__ wout,
                                   const float* __restrict__ bq, const float* __restrict__ bk,
                                   const float* __restrict__ bv,
                                   __half* __restrict__ w, float* __restrict__ bqkv)
{
    long j = (long)blockIdx.x * blockDim.x + threadIdx.x;
    if (j >= CN5) return;
    if (j < CN0) {                       // wqkv interleave: out[r,sel*768+c] = in_sel[r,c]
        long off = j * 8;
        int r = (int)(off / (3*D_)), rem = (int)(off % (3*D_));
        int sel = rem / D_, c = rem % D_;
        const float* src = (sel == 0 ? wq : sel == 1 ? wk : wv) + (size_t)r * D_ + c;
        cvt8(src, w + off);
    } else if (j < CN1) {
        long off = (j - CN0) * 8;
        cvt8(wo + off, w + j * 8);
    } else if (j < CN2) {
        long off = (j - CN1) * 8;
        cvt8(w1 + off, w + j * 8);
    } else if (j < CN3) {
        long off = (j - CN2) * 8;
        cvt8(w2 + off, w + j * 8);
    } else if (j < CN4) {                // w_out padded rows (src rows misaligned: scalar)
        long jj = j - CN3;
        int r = (int)(jj / (VP2_/8));
        int c = (int)(jj % (VP2_/8)) * 8;
        const float* src = wout + (size_t)r * V_ + c;
        __half tmp[8];
#pragma unroll
        for (int e = 0; e < 8; e++)
            tmp[e] = (c + e < V_) ? __float2half(__ldg(src + e)) : __half(0.f);
        *(uint4*)(w + j * 8) = *(const uint4*)tmp;
    } else {                             // bias concat (fp32)
        int i = (int)(j - CN4) * 8;
#pragma unroll
        for (int e = 0; e < 8; e++) {
            int idx = i + e;
            int sel = idx / D_, c = idx - sel * D_;
            bqkv[idx] = (sel == 0 ? bq : sel == 1 ? bk : bv)[c];
        }
    }
}

// ---------------- embedding + sinusoidal positional encoding ---------------
__global__ void embed_kernel(const int* __restrict__ inputs,
                             const float* __restrict__ wte,
                             __half* __restrict__ x)
{
    int idx = blockIdx.x * blockDim.x + threadIdx.x;
    if (idx >= T_*D_) return;
    int t = idx / D_;
    int d = idx - t * D_;
    int s = t & (S_-1);
    int tok = inputs[t];
    int i2 = (d >> 1) * 2;
    float div = expf((float)(-i2) * (logf(10000.0f) / (float)D_));
    float ang = (float)s * div;
    float pe = (d & 1) ? cosf(ang) : sinf(ang);
    x[idx] = __float2half(wte[(size_t)tok * D_ + d] + pe);
}

// ---------------- fp16 tensor-core GEMM, 3-stage cp.async, BK=32 -------------
// modes: 0 = f32 out, 1 = f16 out, 2 = qkv split f16 out, 3 = f32 out + loss partials
#define AST2 40
#define BST2 136
#define ASTB (128*AST2*2)
#define STGB (ASTB + 32*BST2*2)

__global__ __launch_bounds__(256, 2)
void hgemm_kernel(const __half* __restrict__ A, const __half* __restrict__ W,
                  const float* __restrict__ bias, void* __restrict__ Cout,
                  __half* __restrict__ dq, __half* __restrict__ dk, __half* __restrict__ dv,
                  float* __restrict__ pmax, float* __restrict__ psum, int nblk,
                  int M, int N, int K, int ldW, int relu, int mode)
{
    extern __shared__ char smc[];
    const int tid  = threadIdx.x;
    const int warp = tid >> 5;
    const int lane = tid & 31;
    const int gid  = lane >> 2;
    const int tig  = lane & 3;
    const int wm   = warp >> 2;
    const int wn   = warp & 3;
    const int m0 = blockIdx.x * 128;
    const int n0 = blockIdx.y * 128;
    const unsigned smem0 = (unsigned)__cvta_generic_to_shared(smc);

    float acc[4][4][4];
#pragma unroll
    for (int i = 0; i < 4; i++)
#pragma unroll
        for (int j = 0; j < 4; j++)
#pragma unroll
            for (int c = 0; c < 4; c++) acc[i][j][c] = 0.f;

    const int nk = K >> 5;

    auto load_stage = [&](int i) {
        unsigned sa = smem0 + (i % 3) * STGB;
        unsigned sb = sa + ASTB;
        const __half* Ab = A + (size_t)m0 * K + i * 32;
        const __half* Bb = W + (size_t)(i * 32) * ldW + n0;
#pragma unroll
        for (int t = 0; t < 2; t++) {
            int slot = t * 256 + tid;
            int r = slot >> 2, c = (slot & 3) * 8;
            asm volatile("cp.async.cg.shared.global [%0], [%1], 16;"
                         :: "r"(sa + (r * AST2 + c) * 2), "l"(Ab + (size_t)r * K + c));
        }
#pragma unroll
        for (int t = 0; t < 2; t++) {
            int slot = t * 256 + tid;
            int r = slot >> 4, c = (slot & 15) * 8;
            asm volatile("cp.async.cg.shared.global [%0], [%1], 16;"
                         :: "r"(sb + (r * BST2 + c) * 2), "l"(Bb + (size_t)r * ldW + c));
        }
        asm volatile("cp.async.commit_group;");
    };

    load_stage(0);
    load_stage(1);
    asm volatile("cp.async.wait_group 1;");
    __syncthreads();

    const int arow = lane & 15;
    const int acol = (lane >> 4) * 8;

    for (int i = 0; i < nk; i++) {
        unsigned sa = smem0 + (i % 3) * STGB;
        unsigned sb = sa + ASTB;

        if (i + 2 < nk) load_stage(i + 2);
        else            asm volatile("cp.async.commit_group;");

#pragma unroll
        for (int kk = 0; kk < 32; kk += 16) {
            unsigned af[4][4], bf[4][2];
#pragma unroll
            for (int mi = 0; mi < 4; mi++) {
                unsigned ad = sa + ((wm * 64 + mi * 16 + arow) * AST2 + kk + acol) * 2;
                asm volatile("ldmatrix.sync.aligned.m8n8.x4.shared.b16 {%0,%1,%2,%3}, [%4];"
                             : "=r"(af[mi][0]), "=r"(af[mi][1]),
                               "=r"(af[mi][2]), "=r"(af[mi][3]) : "r"(ad));
            }
#pragma unroll
            for (int nh = 0; nh < 2; nh++) {
                unsigned bd = sb + ((kk + arow) * BST2 + wn * 32 + nh * 16 + acol) * 2;
                asm volatile("ldmatrix.sync.aligned.m8n8.x4.trans.shared.b16 {%0,%1,%2,%3}, [%4];"
                             : "=r"(bf[2*nh][0]), "=r"(bf[2*nh][1]),
                               "=r"(bf[2*nh+1][0]), "=r"(bf[2*nh+1][1]) : "r"(bd));
            }
#pragma unroll
            for (int mi = 0; mi < 4; mi++)
#pragma unroll
                for (int ni = 0; ni < 4; ni++) {
                    asm volatile(
                        "mma.sync.aligned.m16n8k16.row.col.f32.f16.f16.f32 "
                        "{%0,%1,%2,%3},{%4,%5,%6,%7},{%8,%9},{%0,%1,%2,%3};"
                        : "+f"(acc[mi][ni][0]), "+f"(acc[mi][ni][1]),
                          "+f"(acc[mi][ni][2]), "+f"(acc[mi][ni][3])
                        : "r"(af[mi][0]), "r"(af[mi][1]),
                          "r"(af[mi][2]), "r"(af[mi][3]),
                          "r"(bf[ni][0]), "r"(bf[ni][1]));
                }
        }

        asm volatile("cp.async.wait_group 1;");
        __syncthreads();
    }

    // qkv destination select (each 128-col tile lies inside one segment)
    __half* qdst = 0; int qcol0 = 0;
    if (mode == 2) {
        int sel = n0 / D_;
        qdst  = (sel == 0 ? dq : sel == 1 ? dk : dv);
        qcol0 = n0 - sel * D_;
    }

    float* red = (float*)smc;   // [128][4][2] reuse after pipeline (4KB)

#pragma unroll
    for (int mi = 0; mi < 4; mi++) {
        int rl = wm * 64 + mi * 16 + gid;     // local row (half 0); +8 for half 1
        int r  = m0 + rl;
        float mA = NEG_, sA = 0.f, mB = NEG_, sB = 0.f;
#pragma unroll
        for (int ni = 0; ni < 4; ni++) {
            int cc = n0 + wn * 32 + ni * 8 + tig * 2;
            bool full = (cc + 1 < N);
            bool any  = (cc < N);
            float b0 = any  ? bias[cc]     : 0.f;
            float b1 = full ? bias[cc + 1] : 0.f;
            float v0 = acc[mi][ni][0] + b0;
            float v1 = acc[mi][ni][1] + b1;
            float v2 = acc[mi][ni][2] + b0;
            float v3 = acc[mi][ni][3] + b1;
            if (relu) {
                v0 = fmaxf(v0, 0.f); v1 = fmaxf(v1, 0.f);
                v2 = fmaxf(v2, 0.f); v3 = fmaxf(v3, 0.f);
            }
            if (mode == 1) {
                if (full) {
                    __half2 h0 = __floats2half2_rn(v0, v1);
                    __half2 h1 = __floats2half2_rn(v2, v3);
                    *(__half2*)((__half*)Cout + (size_t)r * N + cc)       = h0;
                    *(__half2*)((__half*)Cout + (size_t)(r + 8) * N + cc) = h1;
                } else if (any) {
                    ((__half*)Cout)[(size_t)r * N + cc]       = __float2half(v0);
                    ((__half*)Cout)[(size_t)(r + 8) * N + cc] = __float2half(v2);
                }
            } else if (mode == 2) {
                int lc = qcol0 + (cc - n0);
                if (full) {
                    __half2 h0 = __floats2half2_rn(v0, v1);
                    __half2 h1 = __floats2half2_rn(v2, v3);
                    *(__half2*)(qdst + (size_t)r * D_ + lc)       = h0;
                    *(__half2*)(qdst + (size_t)(r + 8) * D_ + lc) = h1;
                } else if (any) {
                    qdst[(size_t)r * D_ + lc]       = __float2half(v0);
                    qdst[(size_t)(r + 8) * D_ + lc] = __float2half(v2);
                }
            } else {
                // f32 out (V odd -> scalar); streaming stores keep L2 clean
                float* C = (float*)Cout;
                if (any) {
                    asm volatile("st.global.cs.f32 [%0], %1;" :: "l"(C + (size_t)r * N + cc), "f"(v0));
                    asm volatile("st.global.cs.f32 [%0], %1;" :: "l"(C + (size_t)(r + 8) * N + cc), "f"(v2));
                    if (mode == 3) {
                        if (v0 > mA) { sA = sA * __expf(mA - v0) + 1.f; mA = v0; }
                        else         { sA += __expf(v0 - mA); }
                        if (v2 > mB) { sB = sB * __expf(mB - v2) + 1.f; mB = v2; }
                        else         { sB += __expf(v2 - mB); }
                    }
                }
                if (full) {
                    asm volatile("st.global.cs.f32 [%0], %1;" :: "l"(C + (size_t)r * N + cc + 1), "f"(v1));
                    asm volatile("st.global.cs.f32 [%0], %1;" :: "l"(C + (size_t)(r + 8) * N + cc + 1), "f"(v3));
                    if (mode == 3) {
                        if (v1 > mA) { sA = sA * __expf(mA - v1) + 1.f; mA = v1; }
                        else         { sA += __expf(v1 - mA); }
                        if (v3 > mB) { sB = sB * __expf(mB - v3) + 1.f; mB = v3; }
                        else         { sB += __expf(v3 - mB); }
                    }
                }
            }
        }
        if (mode == 3) {
#pragma unroll
            for (int o = 1; o <= 2; o <<= 1) {
                float m2 = __shfl_xor_sync(0xffffffffu, mA, o);
                float s2 = __shfl_xor_sync(0xffffffffu, sA, o);
                float mm = fmaxf(mA, m2);
                sA = sA * __expf(mA - mm) + s2 * __expf(m2 - mm);
                mA = mm;
                m2 = __shfl_xor_sync(0xffffffffu, mB, o);
                s2 = __shfl_xor_sync(0xffffffffu, sB, o);
                mm = fmaxf(mB, m2);
                sB = sB * __expf(mB - mm) + s2 * __expf(m2 - mm);
                mB = mm;
            }
            if (tig == 0) {
                red[((rl    ) * 4 + wn) * 2 + 0] = mA;
                red[((rl    ) * 4 + wn) * 2 + 1] = sA;
                red[((rl + 8) * 4 + wn) * 2 + 0] = mB;
                red[((rl + 8) * 4 + wn) * 2 + 1] = sB;
            }
        }
    }

    if (mode == 3) {
        __syncthreads();
        if (tid < 128) {
            float m = NEG_, s = 0.f;
#pragma unroll
            for (int wnn = 0; wnn < 4; wnn++) {
                float m2 = red[(tid * 4 + wnn) * 2 + 0];
                float s2 = red[(tid * 4 + wnn) * 2 + 1];
                float mm = fmaxf(m, m2);
                s = s * __expf(m - mm) + s2 * __expf(m2 - mm);
                m = mm;
            }
            pmax[(size_t)(m0 + tid) * nblk + blockIdx.y] = m;
            psum[(size_t)(m0 + tid) * nblk + blockIdx.y] = s;
        }
    }
}

// ---------------- tensor-core flash attention (FA2 layout) -------------------
#define ATS 72

__global__ __launch_bounds__(128)
void attn_tc_kernel(const __half* __restrict__ Q, const __half* __restrict__ K,
                    const __half* __restrict__ V, __half* __restrict__ O)
{
    __shared__ __half Qs[64*ATS];
    __shared__ __half Ks[64*ATS];
    __shared__ __half Vs[64*ATS];

    const int qt = blockIdx.x;
    const int bh = blockIdx.y;
    const int b  = bh / NH_;
    const int h  = bh - b * NH_;

    const int tid  = threadIdx.x;
    const int w    = tid >> 5;
    const int lane = tid & 31;
    const int gid  = lane >> 2;
    const int tig  = lane & 3;

    const size_t hoff = (size_t)h * HD_;
    const __half* Qg = Q + ((size_t)(b*S_ + qt*64)) * D_ + hoff;

    const __half2 sc2 = __floats2half2_rn(0.125f, 0.125f);
    for (int i = tid; i < 512; i += 128) {
        int r = i >> 3, c = (i & 7) * 8;
        uint4 u = *(const uint4*)(Qg + (size_t)r * D_ + c);
        __half2* hp = (__half2*)&u;
#pragma unroll
        for (int t = 0; t < 4; t++) hp[t] = __hmul2(hp[t], sc2);
        *(uint4*)&Qs[r*ATS + c] = u;
    }
    __syncthreads();

    const unsigned qb = (unsigned)__cvta_generic_to_shared(Qs);
    const unsigned kb = (unsigned)__cvta_generic_to_shared(Ks);
    const unsigned vb = (unsigned)__cvta_generic_to_shared(Vs);
    const int lrow = lane & 15;
    const int lcb  = (lane >> 4) * 8;

    unsigned aQ[4][4];
#pragma unroll
    for (int t = 0; t < 4; t++) {
        unsigned ad = qb + (unsigned)(((w*16 + lrow) * ATS + t*16 + lcb) * 2);
        asm volatile("ldmatrix.sync.aligned.m8n8.x4.shared.b16 {%0,%1,%2,%3}, [%4];"
                     : "=r"(aQ[t][0]), "=r"(aQ[t][1]), "=r"(aQ[t][2]), "=r"(aQ[t][3])
                     : "r"(ad));
    }

    float oacc[8][4];
#pragma unroll
    for (int j = 0; j < 8; j++)
#pragma unroll
        for (int c = 0; c < 4; c++) oacc[j][c] = 0.f;
    float m0 = -INFINITY, m1 = -INFINITY, l0 = 0.f, l1 = 0.f;

    const int r0l = w*16 + gid;
    const int r1l = r0l + 8;

    for (int kt = 0; kt <= qt; kt++) {
        __syncthreads();
        const __half* Kg = K + ((size_t)(b*S_ + kt*64)) * D_ + hoff;
        const __half* Vg = V + ((size_t)(b*S_ + kt*64)) * D_ + hoff;
        for (int i = tid; i < 1024; i += 128) {
            int r = (i >> 3) & 63, c = (i & 7) * 8;
            if (i < 512)
                *(uint4*)&Ks[r*ATS + c] = *(const uint4*)(Kg + (size_t)r * D_ + c);
            else
                *(uint4*)&Vs[r*ATS + c] = *(const uint4*)(Vg + (size_t)r * D_ + c);
        }
        __syncthreads();

        float sacc[8][4];
#pragma unroll
        for (int j = 0; j < 8; j++)
#pragma unroll
            for (int c = 0; c < 4; c++) sacc[j][c] = 0.f;

#pragma unroll
        for (int t = 0; t < 4; t++) {
#pragma unroll
            for (int jp = 0; jp < 4; jp++) {
                unsigned bk[4];
                unsigned ad = kb + (unsigned)(((jp*16 + lrow) * ATS + t*16 + lcb) * 2);
                asm volatile("ldmatrix.sync.aligned.m8n8.x4.shared.b16 {%0,%1,%2,%3}, [%4];"
                             : "=r"(bk[0]), "=r"(bk[1]), "=r"(bk[2]), "=r"(bk[3])
                             : "r"(ad));
                asm volatile(
                    "mma.sync.aligned.m16n8k16.row.col.f32.f16.f16.f32 "
                    "{%0,%1,%2,%3},{%4,%5,%6,%7},{%8,%9},{%0,%1,%2,%3};"
                    : "+f"(sacc[2*jp][0]), "+f"(sacc[2*jp][1]),
                      "+f"(sacc[2*jp][2]), "+f"(sacc[2*jp][3])
                    : "r"(aQ[t][0]), "r"(aQ[t][1]), "r"(aQ[t][2]), "r"(aQ[t][3]),
                      "r"(bk[0]), "r"(bk[2]));
                asm volatile(
                    "mma.sync.aligned.m16n8k16.row.col.f32.f16.f16.f32 "
                    "{%0,%1,%2,%3},{%4,%5,%6,%7},{%8,%9},{%0,%1,%2,%3};"
                    : "+f"(sacc[2*jp+1][0]), "+f"(sacc[2*jp+1][1]),
                      "+f"(sacc[2*jp+1][2]), "+f"(sacc[2*jp+1][3])
                    : "r"(aQ[t][0]), "r"(aQ[t][1]), "r"(aQ[t][2]), "r"(aQ[t][3]),
                      "r"(bk[1]), "r"(bk[3]));
            }
        }

        if (kt == qt) {
#pragma unroll
            for (int j = 0; j < 8; j++) {
                int c0 = j*8 + tig*2;
                if (c0     > r0l) sacc[j][0] = -INFINITY;
                if (c0 + 1 > r0l) sacc[j][1] = -INFINITY;
                if (c0     > r1l) sacc[j][2] = -INFINITY;
                if (c0 + 1 > r1l) sacc[j][3] = -INFINITY;
            }
        }

        float mx0 = -INFINITY, mx1 = -INFINITY;
#pragma unroll
        for (int j = 0; j < 8; j++) {
            mx0 = fmaxf(mx0, fmaxf(sacc[j][0], sacc[j][1]));
            mx1 = fmaxf(mx1, fmaxf(sacc[j][2], sacc[j][3]));
        }
#pragma unroll
        for (int o = 1; o <= 2; o <<= 1) {
            mx0 = fmaxf(mx0, __shfl_xor_sync(0xffffffffu, mx0, o));
            mx1 = fmaxf(mx1, __shfl_xor_sync(0xffffffffu, mx1, o));
        }
        float nm0 = fmaxf(m0, mx0), nm1 = fmaxf(m1, mx1);
        float corr0 = __expf(m0 - nm0), corr1 = __expf(m1 - nm1);

        unsigned pa0[8], pa1[8];
        float sum0 = 0.f, sum1 = 0.f;
#pragma unroll
        for (int j = 0; j < 8; j++) {
            float p00 = __expf(sacc[j][0] - nm0);
            float p01 = __expf(sacc[j][1] - nm0);
            float p10 = __expf(sacc[j][2] - nm1);
            float p11 = __expf(sacc[j][3] - nm1);
            sum0 += p00 + p01;
            sum1 += p10 + p11;
            __half2 h0 = __floats2half2_rn(p00, p01);
            __half2 h1 = __floats2half2_rn(p10, p11);
            pa0[j] = *(unsigned*)&h0;
            pa1[j] = *(unsigned*)&h1;
        }
#pragma unroll
        for (int o = 1; o <= 2; o <<= 1) {
            sum0 += __shfl_xor_sync(0xffffffffu, sum0, o);
            sum1 += __shfl_xor_sync(0xffffffffu, sum1, o);
        }
        l0 = l0 * corr0 + sum0;
        l1 = l1 * corr1 + sum1;
        m0 = nm0; m1 = nm1;
#pragma unroll
        for (int j = 0; j < 8; j++) {
            oacc[j][0] *= corr0; oacc[j][1] *= corr0;
            oacc[j][2] *= corr1; oacc[j][3] *= corr1;
        }

#pragma unroll
        for (int kc = 0; kc < 4; kc++) {
            unsigned a0 = pa0[2*kc], a1 = pa1[2*kc], a2 = pa0[2*kc+1], a3 = pa1[2*kc+1];
#pragma unroll
            for (int dp = 0; dp < 4; dp++) {
                unsigned bv[4];
                unsigned ad = vb + (unsigned)(((kc*16 + lrow) * ATS + dp*16 + lcb) * 2);
                asm volatile("ldmatrix.sync.aligned.m8n8.x4.trans.shared.b16 {%0,%1,%2,%3}, [%4];"
                             : "=r"(bv[0]), "=r"(bv[1]), "=r"(bv[2]), "=r"(bv[3])
                             : "r"(ad));
                asm volatile(
                    "mma.sync.aligned.m16n8k16.row.col.f32.f16.f16.f32 "
                    "{%0,%1,%2,%3},{%4,%5,%6,%7},{%8,%9},{%0,%1,%2,%3};"
                    : "+f"(oacc[2*dp][0]), "+f"(oacc[2*dp][1]),
                      "+f"(oacc[2*dp][2]), "+f"(oacc[2*dp][3])
                    : "r"(a0), "r"(a1), "r"(a2), "r"(a3),
                      "r"(bv[0]), "r"(bv[1]));
                asm volatile(
                    "mma.sync.aligned.m16n8k16.row.col.f32.f16.f16.f32 "
                    "{%0,%1,%2,%3},{%4,%5,%6,%7},{%8,%9},{%0,%1,%2,%3};"
                    : "+f"(oacc[2*dp+1][0]), "+f"(oacc[2*dp+1][1]),
                      "+f"(oacc[2*dp+1][2]), "+f"(oacc[2*dp+1][3])
                    : "r"(a0), "r"(a1), "r"(a2), "r"(a3),
                      "r"(bv[2]), "r"(bv[3]));
            }
        }
    }

    float inv0 = 1.f / l0, inv1 = 1.f / l1;
    size_t row0 = ((size_t)(b*S_ + qt*64 + r0l)) * D_ + hoff;
    size_t row1 = ((size_t)(b*S_ + qt*64 + r1l)) * D_ + hoff;
#pragma unroll
    for (int j = 0; j < 8; j++) {
        int c = j*8 + tig*2;
        __half2 o0 = __floats2half2_rn(oacc[j][0]*inv0, oacc[j][1]*inv0);
        __half2 o1 = __floats2half2_rn(oacc[j][2]*inv1, oacc[j][3]*inv1);
        *(__half2*)(O + row0 + c) = o0;
        *(__half2*)(O + row1 + c) = o1;
    }
}

// ---------------- LayerNorm over D (f32 in, f16 out) ------------------------
__global__ void ln_kernel(const float* __restrict__ H,
                          const float* __restrict__ g,
                          const float* __restrict__ bb,
                          __half* __restrict__ out)
{
    int row = blockIdx.x;
    const float* h = H + (size_t)row * D_;
    __shared__ float red[256];
    int tid = threadIdx.x;

    float s = 0.f;
    for (int i = tid; i < D_; i += 256) s += h[i];
    red[tid] = s; __syncthreads();
    for (int o = 128; o; o >>= 1) { if (tid < o) red[tid] += red[tid+o]; __syncthreads(); }
    float mu = red[0] / (float)D_;
    __syncthreads();

    float v = 0.f;
    for (int i = tid; i < D_; i += 256) { float d = h[i] - mu; v += d*d; }
    red[tid] = v; __syncthreads();
    for (int o = 128; o; o >>= 1) { if (tid < o) red[tid] += red[tid+o]; __syncthreads(); }
    float rstd = rsqrtf(red[0] / (float)D_ + 1e-5f);

    __half* o2 = out + (size_t)row * D_;
    for (int i = tid; i < D_; i += 256)
        o2[i] = __float2half((h[i] - mu) * rstd * g[i] + bb[i]);
}

// ---------------- loss from per-block partials -------------------------------
__global__ void loss_partials_kernel(const float* __restrict__ logits,
                                     const int* __restrict__ targets,
                                     const float* __restrict__ pmax,
                                     const float* __restrict__ psum,
                                     float* __restrict__ rowloss)
{
    int row = blockIdx.x;
    int tid = threadIdx.x;
    __shared__ float rm[128], rs[128];

    float m = NEG_, s = 0.f;
    for (int j = tid; j < NBLK_; j += 128) {
        float m2 = pmax[(size_t)row * NBLK_ + j];
        float s2 = psum[(size_t)row * NBLK_ + j];
        float mm = fmaxf(m, m2);
        s = s * __expf(m - mm) + s2 * __expf(m2 - mm);
        m = mm;
    }
    rm[tid] = m; rs[tid] = s; __syncthreads();
    for (int o = 64; o; o >>= 1) {
        if (tid < o) {
            float m1 = rm[tid], s1 = rs[tid];
            float m2 = rm[tid+o], s2 = rs[tid+o];
            float mm = fmaxf(m1, m2);
            rm[tid] = mm;
            rs[tid] = s1 * __expf(m1 - mm) + s2 * __expf(m2 - mm);
        }
        __syncthreads();
    }
    if (tid == 0)
        rowloss[row] = -(logits[(size_t)row * V_ + targets[row]] - rm[0] - logf(rs[0]));
}

__global__ void loss_reduce_kernel(const float* __restrict__ rowloss,
                                   float* __restrict__ out)
{
    __shared__ float red[256];
    int tid = threadIdx.x;
    float s = 0.f;
    for (int i = tid; i < T_; i += 256) s += rowloss[i];
    red[tid] = s; __syncthreads();
    for (int o = 128; o; o >>= 1) { if (tid < o) red[tid] += red[tid+o]; __syncthreads(); }
    if (tid == 0) out[0] = red[0] / (float)T_;
}

// ---------------- launcher ---------------------------------------------------
extern "C" void kernel_launch(void* const* d_in, const int* in_sizes, int n_in,
                              void* d_out, int out_size)
{
    const int*   inputs  = (const int*)  d_in[0];
    const int*   targets = (const int*)  d_in[1];
    const float* wte     = (const float*)d_in[2];
    const float* wq      = (const float*)d_in[3];
    const float* bq      = (const float*)d_in[4];
    const float* wk      = (const float*)d_in[5];
    const float* bk      = (const float*)d_in[6];
    const float* wv      = (const float*)d_in[7];
    const float* bv      = (const float*)d_in[8];
    const float* wo      = (const float*)d_in[9];
    const float* bo      = (const float*)d_in[10];
    const float* w1      = (const float*)d_in[11];
    const float* b1      = (const float*)d_in[12];
    const float* w2      = (const float*)d_in[13];
    const float* b2      = (const float*)d_in[14];
    const float* ln_g    = (const float*)d_in[15];
    const float* ln_b    = (const float*)d_in[16];
    const float* w_out   = (const float*)d_in[17];
    const float* b_out   = (const float*)d_in[18];
    float* out = (float*)d_out;

    __half *x,*q,*k,*v,*ctx,*ao,*h1,*hn,*w;
    float *h2,*rowloss,*pmax,*psum,*bqkv;
    cudaGetSymbolAddress((void**)&x,   g_x);
    cudaGetSymbolAddress((void**)&q,   g_q);
    cudaGetSymbolAddress((void**)&k,   g_k);
    cudaGetSymbolAddress((void**)&v,   g_v);
    cudaGetSymbolAddress((void**)&ctx, g_ctx);
    cudaGetSymbolAddress((void**)&ao,  g_ao);
    cudaGetSymbolAddress((void**)&h1,  g_h1);
    cudaGetSymbolAddress((void**)&h2,  g_h2);
    cudaGetSymbolAddress((void**)&hn,  g_hn);
    cudaGetSymbolAddress((void**)&rowloss, g_rowloss);
    cudaGetSymbolAddress((void**)&pmax, g_pmax);
    cudaGetSymbolAddress((void**)&psum, g_psum);
    cudaGetSymbolAddress((void**)&bqkv, g_bqkv);
    cudaGetSymbolAddress((void**)&w,   g_w);

    const int SMEM_GEMM = 3 * STGB;
    cudaFuncSetAttribute(hgemm_kernel, cudaFuncAttributeMaxDynamicSharedMemorySize, SMEM_GEMM);

    // 0. fused weight conversion (single launch)
    convert_all_kernel<<<(int)((CN5 + 255) / 256), 256>>>(
        wq, wk, wv, wo, w1, w2, w_out, bq, bk, bv, w, bqkv);

    // 1. embedding + positional encoding (fp16)
    embed_kernel<<<(T_*D_)/256, 256>>>(inputs, wte, x);

    // 2. fused Q,K,V projection (one GEMM, split epilogue)
    hgemm_kernel<<<dim3(T_/128, 3*D_/128), 256, SMEM_GEMM>>>(
        x, w+OFF_WQKV, bqkv, 0, q, k, v, 0, 0, 0, T_, 3*D_, D_, 3*D_, 0, 2);

    // 3. causal multi-head attention (fp16 tensor cores, fp32 softmax)
    attn_tc_kernel<<<dim3(S_/64, B_*NH_), 128>>>(q, k, v, ctx);

    // 4. output projection -> fp16 ao
    dim3 gDD(T_/128, D_/128);
    hgemm_kernel<<<gDD, 256, SMEM_GEMM>>>(
        ctx, w+OFF_WO, bo, ao, 0,0,0, 0,0,0, T_, D_, D_, D_, 0, 1);

    // 5. FFN (h1 fp16 + relu; h2 fp32 for LN)
    hgemm_kernel<<<dim3(T_/128, HID_/128), 256, SMEM_GEMM>>>(
        ao, w+OFF_W1, b1, h1, 0,0,0, 0,0,0, T_, HID_, D_, HID_, 1, 1);
    hgemm_kernel<<<gDD, 256, SMEM_GEMM>>>(
        h1, w+OFF_W2, b2, h2, 0,0,0, 0,0,0, T_, D_, HID_, D_, 0, 0);

    // 6. LayerNorm (fp32 in -> fp16 hn)
    ln_kernel<<<T_, 256>>>(h2, ln_g, ln_b, hn);

    // 7. vocab projection -> fp32 logits + fused per-block softmax partials
    hgemm_kernel<<<dim3(T_/128, NBLK_), 256, SMEM_GEMM>>>(
        hn, w+OFF_WOUT, b_out, out, 0,0,0, pmax, psum, NBLK_,
        T_, V_, D_, VP2_, 0, 3);

    // 8. cross-entropy loss from partials
    loss_partials_kernel<<<T_, 128>>>(out, targets, pmax, psum, rowloss);
    if (out_size > T_ * V_)
        loss_reduce_kernel<<<1, 256>>>(rowloss, out + (size_t)T_ * V_);
}